// round 7
// baseline (speedup 1.0000x reference)
#include <cuda_runtime.h>
#include <cuda_bf16.h>
#include <math.h>
#include <stdint.h>

// Problem constants
#define NTOK   4096      // B*S = 2*2048
#define DMODEL 1024
#define DFF    4096
#define NHEAD  16
#define HD     64
#define SEQ    2048
#define QLD    (3 * DMODEL)   // fused qkv row stride

// ---------------------------------------------------------------------------
// Scratch (static device globals; no runtime allocation allowed)
// ---------------------------------------------------------------------------
__device__ __align__(16) float g_qkv [NTOK * 3 * DMODEL];    // fused q|k|v (tf32-rounded)
__device__ __align__(16) float g_vt  [32 * HD * SEQ];        // V^T per (b,h): [64][2048]
__device__ __align__(16) float g_srcr[NTOK * DMODEL];        // rounded src (QKV A operand)
__device__ __align__(16) float g_xr  [NTOK * DMODEL];        // rounded LN1 out (FFN1 A)
__device__ __align__(16) float g_wqkvT[3 * DMODEL * DMODEL]; // [3072,1024] K-major, rounded
__device__ __align__(16) float g_woT [DMODEL * DMODEL];
__device__ __align__(16) float g_w1T [DFF * DMODEL];
__device__ __align__(16) float g_w2T [DMODEL * DFF];
__device__ __align__(16) float g_bqkv[3 * DMODEL];
__device__ __align__(16) float g_ctx [NTOK * DMODEL];        // rounded flash output
__device__ __align__(16) float g_tmp [NTOK * DMODEL];
__device__ __align__(16) float g_x   [NTOK * DMODEL];
__device__ __align__(16) float g_ff  [NTOK * DFF];           // rounded FFN1 output

// ---------------------------------------------------------------------------
// PTX helpers (baseline sm_80+ features only — harness targets plain sm_103)
// ---------------------------------------------------------------------------
__device__ __forceinline__ uint32_t smem_u32(const void* p) {
    uint32_t a;
    asm("{ .reg .u64 t; cvta.to.shared.u64 t, %1; cvt.u32.u64 %0, t; }" : "=r"(a) : "l"(p));
    return a;
}
#define CP_ASYNC16(dst, src) \
    asm volatile("cp.async.cg.shared.global [%0], [%1], 16;" :: "r"(dst), "l"(src))
#define CP_COMMIT() asm volatile("cp.async.commit_group;" ::: "memory")
#define CP_WAIT(n)  asm volatile("cp.async.wait_group %0;" :: "n"(n) : "memory")

#define LDMATRIX_X4(r0, r1, r2, r3, addr) \
    asm volatile("ldmatrix.sync.aligned.m8n8.x4.shared.b16 {%0,%1,%2,%3}, [%4];" \
                 : "=r"(r0), "=r"(r1), "=r"(r2), "=r"(r3) : "r"(addr))

__device__ __forceinline__ uint32_t to_tf32f(float f) {
    uint32_t o;
    asm("cvt.rna.tf32.f32 %0, %1;" : "=r"(o) : "f"(f));
    return o;
}
__device__ __forceinline__ float roundf_tf32(float f) {
    return __uint_as_float(to_tf32f(f));
}

#define MMA_TF32(c0, c1, c2, c3, a0, a1, a2, a3, b0, b1) \
    asm volatile("mma.sync.aligned.m16n8k8.row.col.f32.tf32.tf32.f32 " \
                 "{%0,%1,%2,%3}, {%4,%5,%6,%7}, {%8,%9}, {%0,%1,%2,%3};" \
                 : "+f"(c0), "+f"(c1), "+f"(c2), "+f"(c3) \
                 : "r"(a0), "r"(a1), "r"(a2), "r"(a3), "r"(b0), "r"(b1))

// ---------------------------------------------------------------------------
// tf32 tensor-core GEMM:  C[M,N] = A[M,K] @ BT[N,K]^T + bias[N].
// Inputs already tf32-rounded (raw bits into mma). 128x256 block tile,
// K-chunk 32, 256 threads (8 warps, 2x4 grid, warp tile 64x64), 3-stage
// cp.async pipeline, ONE barrier per main-loop iteration.
// Requires M%128==0, N%256==0, K%32==0.
// ---------------------------------------------------------------------------
#define STAGES 3
#define A_ST_BYTES (128 * 32 * 4)            // 16KB
#define B_ST_BYTES (256 * 32 * 4)            // 32KB
#define STAGE_BYTES (A_ST_BYTES + B_ST_BYTES)
#define SMEM_DYN (STAGES * STAGE_BYTES)      // 144KB

template <bool RELU, bool ROUND>
__global__ __launch_bounds__(256, 1)
void gemm_mma(const float* __restrict__ A, const float* __restrict__ BT,
              const float* __restrict__ bias, float* __restrict__ C,
              int M, int N, int K)
{
    extern __shared__ char smem[];
    const uint32_t sbase = smem_u32(smem);
    const int tid  = threadIdx.x;
    const int wid  = tid >> 5;
    const int lane = tid & 31;
    const int warp_m = wid & 1;        // 0..1 (64 rows each)
    const int warp_n = wid >> 1;       // 0..3 (64 cols each)
    const int gid = lane >> 2;
    const int tg  = lane & 3;

    const int bm = blockIdx.y * 128;
    const int bn = blockIdx.x * 256;
    const int KT = K >> 5;

    // --- cp.async mappings ---
    // A: 128 rows x 8 units; thread -> row tid>>1, 4 consecutive units
    const int lrowA = tid >> 1;
    const int luA   = (tid & 1) * 4;
    const float* Ag = A + (size_t)(bm + lrowA) * K + luA * 4;
    uint32_t aswz[4];
    #pragma unroll
    for (int i = 0; i < 4; i++) {
        uint32_t off = lrowA * 128 + (luA + i) * 16;
        aswz[i] = off ^ ((off >> 3) & 0x70);
    }
    // B: 256 rows x 8 units; thread -> row tid, all 8 units
    const float* Bg = BT + (size_t)(bn + tid) * K;
    uint32_t bswz[8];
    #pragma unroll
    for (int i = 0; i < 8; i++) {
        uint32_t off = tid * 128 + i * 16;
        bswz[i] = off ^ ((off >> 3) & 0x70);
    }

    // --- ldmatrix fragment addressing ---
    uint32_t a_rel[4], a_xr[4];
    #pragma unroll
    for (int i = 0; i < 4; i++) {
        int r = warp_m * 64 + i * 16 + (lane & 7) + ((lane >> 3) & 1) * 8;
        a_rel[i] = r * 128;
        a_xr[i]  = (r & 7) << 4;
    }
    const uint32_t a_kb = ((lane >> 4) & 1) * 16;
    uint32_t b_rel[4], b_xr[4];
    #pragma unroll
    for (int j = 0; j < 4; j++) {
        int r = warp_n * 64 + j * 16 + (lane & 7) + ((lane >> 4) & 1) * 8;
        b_rel[j] = r * 128;
        b_xr[j]  = (r & 7) << 4;
    }
    const uint32_t b_kb = ((lane >> 3) & 1) * 16;

    float acc[4][8][4];
    #pragma unroll
    for (int i = 0; i < 4; i++)
        #pragma unroll
        for (int t = 0; t < 8; t++)
            #pragma unroll
            for (int r = 0; r < 4; r++) acc[i][t][r] = 0.f;

    auto load_tile = [&](int s, int kt) {
        const uint32_t sA = sbase + s * STAGE_BYTES;
        const uint32_t sB = sA + A_ST_BYTES;
        const float* ar = Ag + kt * 32;
        const float* br = Bg + kt * 32;
        #pragma unroll
        for (int i = 0; i < 4; i++) CP_ASYNC16(sA + aswz[i], ar + i * 4);
        #pragma unroll
        for (int i = 0; i < 8; i++) CP_ASYNC16(sB + bswz[i], br + i * 4);
    };

    #pragma unroll
    for (int s = 0; s < STAGES - 1; s++) { load_tile(s, s); CP_COMMIT(); }

    int cur = 0;
    for (int kt = 0; kt < KT; kt++) {
        CP_WAIT(STAGES - 2);
        __syncthreads();   // all warps finished reading the stage we now overwrite

        const int pf = kt + STAGES - 1;
        if (pf < KT) {
            int ps = pf - STAGES * (pf / STAGES);   // pf % STAGES
            load_tile(ps, pf);
        }
        CP_COMMIT();

        const uint32_t sA = sbase + cur * STAGE_BYTES;
        const uint32_t sB = sA + A_ST_BYTES;

        #pragma unroll
        for (int ks = 0; ks < 4; ks++) {
            const uint32_t kso = ks * 32;
            uint32_t af[4][4];
            #pragma unroll
            for (int i = 0; i < 4; i++) {
                uint32_t addr = sA + ((a_rel[i] + a_kb + kso) ^ a_xr[i]);
                LDMATRIX_X4(af[i][0], af[i][1], af[i][2], af[i][3], addr);
            }
            uint32_t bf[8][2];
            #pragma unroll
            for (int j = 0; j < 4; j++) {
                uint32_t r0, r1, r2, r3;
                uint32_t addr = sB + ((b_rel[j] + b_kb + kso) ^ b_xr[j]);
                LDMATRIX_X4(r0, r1, r2, r3, addr);
                bf[2*j+0][0] = r0; bf[2*j+0][1] = r1;
                bf[2*j+1][0] = r2; bf[2*j+1][1] = r3;
            }
            #pragma unroll
            for (int i = 0; i < 4; i++)
                #pragma unroll
                for (int t = 0; t < 8; t++)
                    MMA_TF32(acc[i][t][0], acc[i][t][1], acc[i][t][2], acc[i][t][3],
                             af[i][0], af[i][1], af[i][2], af[i][3],
                             bf[t][0], bf[t][1]);
        }
        cur++; if (cur == STAGES) cur = 0;
    }

    #pragma unroll
    for (int i = 0; i < 4; i++) {
        const int row0 = bm + warp_m * 64 + i * 16 + gid;
        #pragma unroll
        for (int t = 0; t < 8; t++) {
            const int col = bn + warp_n * 64 + t * 8 + 2 * tg;
            const float2 bv = *(const float2*)(bias + col);
            float2 v0, v1;
            v0.x = acc[i][t][0] + bv.x; v0.y = acc[i][t][1] + bv.y;
            v1.x = acc[i][t][2] + bv.x; v1.y = acc[i][t][3] + bv.y;
            if (RELU) {
                v0.x = fmaxf(v0.x, 0.f); v0.y = fmaxf(v0.y, 0.f);
                v1.x = fmaxf(v1.x, 0.f); v1.y = fmaxf(v1.y, 0.f);
            }
            if (ROUND) {
                v0.x = roundf_tf32(v0.x); v0.y = roundf_tf32(v0.y);
                v1.x = roundf_tf32(v1.x); v1.y = roundf_tf32(v1.y);
            }
            *(float2*)(C + (size_t)row0 * N + col)       = v0;
            *(float2*)(C + (size_t)(row0 + 8) * N + col) = v1;
        }
    }
}

// ---------------------------------------------------------------------------
// Tensor-core flash attention (tf32 mma). 64 queries x 1 head per block.
// Q/K/V already tf32-rounded; raw bits feed mma. Output rounded (feeds O-proj).
// ---------------------------------------------------------------------------
#define ATT_SMEM 65536

__global__ __launch_bounds__(128, 2)
void flash_mma(const float* __restrict__ QKV, const float* __restrict__ VT,
               float* __restrict__ O)
{
    extern __shared__ char smem[];
    const uint32_t sbase = smem_u32(smem);
    const int tid  = threadIdx.x;
    const int wid  = tid >> 5;
    const int lane = tid & 31;
    const int gid  = lane >> 2;
    const int tg   = lane & 3;

    const int bh = blockIdx.y;
    const int b  = bh >> 4;
    const int h  = bh & 15;
    const int q0 = blockIdx.x * 64;

    const float* Qg  = QKV + (size_t)b * SEQ * QLD + h * HD;
    const float* Kg  = Qg + DMODEL;
    const float* VTg = VT + (size_t)bh * HD * SEQ;

    const uint32_t qreg = sbase + 32768;

    const int lrow = tid >> 1;
    const int lu0  = (tid & 1) * 8;
    uint32_t lsw[8];
    #pragma unroll
    for (int i = 0; i < 8; i++) {
        int u = lu0 + i;
        uint32_t off = lrow * 128 + (u & 7) * 16;
        lsw[i] = (u >> 3) * 8192 + (off ^ ((off >> 3) & 0x70));
    }

    uint32_t aq_rel, aq_xr;
    {
        int r = wid * 16 + (lane & 7) + ((lane >> 3) & 1) * 8;
        aq_rel = r * 128;
        aq_xr  = (r & 7) << 4;
    }
    const uint32_t a_kb = ((lane >> 4) & 1) * 16;
    uint32_t b_rel[4], b_xr[4];
    #pragma unroll
    for (int j = 0; j < 4; j++) {
        int r = j * 16 + (lane & 7) + ((lane >> 4) & 1) * 8;
        b_rel[j] = r * 128;
        b_xr[j]  = (r & 7) << 4;
    }
    const uint32_t b_kb = ((lane >> 3) & 1) * 16;

    auto load_KV = [&](int stage, int kt) {
        const uint32_t sK = sbase + stage * 32768;
        const uint32_t sV = sK + 16384;
        const float* kr = Kg  + (size_t)(kt * 64 + lrow) * QLD + lu0 * 4;
        const float* vr = VTg + (size_t)lrow * SEQ + kt * 64 + lu0 * 4;
        #pragma unroll
        for (int i = 0; i < 8; i++) CP_ASYNC16(sK + lsw[i], kr + i * 4);
        #pragma unroll
        for (int i = 0; i < 8; i++) CP_ASYNC16(sV + lsw[i], vr + i * 4);
    };

    {
        const float* qr = Qg + (size_t)(q0 + lrow) * QLD + lu0 * 4;
        #pragma unroll
        for (int i = 0; i < 8; i++) CP_ASYNC16(qreg + lsw[i], qr + i * 4);
        load_KV(0, 0);
        CP_COMMIT();
        CP_WAIT(0);
        __syncthreads();
    }

    uint32_t qf[8][4];
    #pragma unroll
    for (int c = 0; c < 2; c++)
        #pragma unroll
        for (int ks = 0; ks < 4; ks++) {
            uint32_t addr = qreg + c * 8192 + ((aq_rel + a_kb + ks * 32) ^ aq_xr);
            LDMATRIX_X4(qf[c*4+ks][0], qf[c*4+ks][1], qf[c*4+ks][2], qf[c*4+ks][3], addr);
        }
    __syncthreads();

    const int NT = SEQ / 64;
    load_KV(1, 1);
    CP_COMMIT();

    float o[8][4];
    #pragma unroll
    for (int t = 0; t < 8; t++)
        #pragma unroll
        for (int r = 0; r < 4; r++) o[t][r] = 0.f;
    float m0 = -1e30f, m1 = -1e30f, l0 = 0.f, l1 = 0.f;

    for (int kt = 0; kt < NT; kt++) {
        if (kt < NT - 1) { CP_WAIT(1); } else { CP_WAIT(0); }
        __syncthreads();
        const uint32_t sK = sbase + (kt & 1) * 32768;
        const uint32_t sV = sK + 16384;

        // ---- S = Q @ K^T ----
        float s[8][4];
        #pragma unroll
        for (int t = 0; t < 8; t++)
            #pragma unroll
            for (int r = 0; r < 4; r++) s[t][r] = 0.f;

        #pragma unroll
        for (int c = 0; c < 2; c++)
            #pragma unroll
            for (int ks = 0; ks < 4; ks++) {
                uint32_t bf[8][2];
                #pragma unroll
                for (int j = 0; j < 4; j++) {
                    uint32_t r0, r1, r2, r3;
                    uint32_t addr = sK + c * 8192 + ((b_rel[j] + b_kb + ks * 32) ^ b_xr[j]);
                    LDMATRIX_X4(r0, r1, r2, r3, addr);
                    bf[2*j+0][0] = r0; bf[2*j+0][1] = r1;
                    bf[2*j+1][0] = r2; bf[2*j+1][1] = r3;
                }
                const uint32_t* aq = qf[c*4+ks];
                #pragma unroll
                for (int t = 0; t < 8; t++)
                    MMA_TF32(s[t][0], s[t][1], s[t][2], s[t][3],
                             aq[0], aq[1], aq[2], aq[3], bf[t][0], bf[t][1]);
            }

        // ---- online softmax ----
        float tmax0 = -1e30f, tmax1 = -1e30f;
        #pragma unroll
        for (int t = 0; t < 8; t++) {
            s[t][0] *= 0.125f; s[t][1] *= 0.125f; s[t][2] *= 0.125f; s[t][3] *= 0.125f;
            tmax0 = fmaxf(tmax0, fmaxf(s[t][0], s[t][1]));
            tmax1 = fmaxf(tmax1, fmaxf(s[t][2], s[t][3]));
        }
        tmax0 = fmaxf(tmax0, __shfl_xor_sync(0xffffffffu, tmax0, 1));
        tmax0 = fmaxf(tmax0, __shfl_xor_sync(0xffffffffu, tmax0, 2));
        tmax1 = fmaxf(tmax1, __shfl_xor_sync(0xffffffffu, tmax1, 1));
        tmax1 = fmaxf(tmax1, __shfl_xor_sync(0xffffffffu, tmax1, 2));

        const float mnew0 = fmaxf(m0, tmax0);
        const float mnew1 = fmaxf(m1, tmax1);
        const float corr0 = __expf(m0 - mnew0);
        const float corr1 = __expf(m1 - mnew1);

        float rs0 = 0.f, rs1 = 0.f;
        #pragma unroll
        for (int t = 0; t < 8; t++) {
            s[t][0] = __expf(s[t][0] - mnew0);
            s[t][1] = __expf(s[t][1] - mnew0);
            s[t][2] = __expf(s[t][2] - mnew1);
            s[t][3] = __expf(s[t][3] - mnew1);
            rs0 += s[t][0] + s[t][1];
            rs1 += s[t][2] + s[t][3];
        }
        rs0 += __shfl_xor_sync(0xffffffffu, rs0, 1);
        rs0 += __shfl_xor_sync(0xffffffffu, rs0, 2);
        rs1 += __shfl_xor_sync(0xffffffffu, rs1, 1);
        rs1 += __shfl_xor_sync(0xffffffffu, rs1, 2);

        l0 = l0 * corr0 + rs0;
        l1 = l1 * corr1 + rs1;
        #pragma unroll
        for (int t = 0; t < 8; t++) {
            o[t][0] *= corr0; o[t][1] *= corr0;
            o[t][2] *= corr1; o[t][3] *= corr1;
        }
        m0 = mnew0; m1 = mnew1;

        // ---- ctx += P @ V ----
        #pragma unroll
        for (int ks = 0; ks < 8; ks++) {
            const int src0 = tg >> 1, src1 = src0 + 2;
            float v00 = __shfl_sync(0xffffffffu, s[ks][0], src0, 4);
            float v01 = __shfl_sync(0xffffffffu, s[ks][1], src0, 4);
            float v20 = __shfl_sync(0xffffffffu, s[ks][0], src1, 4);
            float v21 = __shfl_sync(0xffffffffu, s[ks][1], src1, 4);
            float v10 = __shfl_sync(0xffffffffu, s[ks][2], src0, 4);
            float v11 = __shfl_sync(0xffffffffu, s[ks][3], src0, 4);
            float v30 = __shfl_sync(0xffffffffu, s[ks][2], src1, 4);
            float v31 = __shfl_sync(0xffffffffu, s[ks][3], src1, 4);
            const bool oddc = (tg & 1);
            uint32_t a0 = to_tf32f(oddc ? v01 : v00);
            uint32_t a1 = to_tf32f(oddc ? v11 : v10);
            uint32_t a2 = to_tf32f(oddc ? v21 : v20);
            uint32_t a3 = to_tf32f(oddc ? v31 : v30);

            uint32_t bf[8][2];
            const uint32_t vbase = sV + (ks >> 2) * 8192;
            const uint32_t kso = (ks & 3) * 32;
            #pragma unroll
            for (int j = 0; j < 4; j++) {
                uint32_t r0, r1, r2, r3;
                uint32_t addr = vbase + ((b_rel[j] + b_kb + kso) ^ b_xr[j]);
                LDMATRIX_X4(r0, r1, r2, r3, addr);
                bf[2*j+0][0] = r0; bf[2*j+0][1] = r1;
                bf[2*j+1][0] = r2; bf[2*j+1][1] = r3;
            }
            #pragma unroll
            for (int t = 0; t < 8; t++)
                MMA_TF32(o[t][0], o[t][1], o[t][2], o[t][3],
                         a0, a1, a2, a3, bf[t][0], bf[t][1]);
        }

        __syncthreads();
        const int pf = kt + 2;
        if (pf < NT) { load_KV(pf & 1, pf); CP_COMMIT(); }
    }

    // ---- write ctx (tf32-rounded: feeds O-projection A operand) ----
    const float inv0 = 1.0f / l0;
    const float inv1 = 1.0f / l1;
    const int qa = q0 + wid * 16 + gid;
    float* orow0 = O + (size_t)(b * SEQ + qa)     * DMODEL + h * HD;
    float* orow1 = O + (size_t)(b * SEQ + qa + 8) * DMODEL + h * HD;
    #pragma unroll
    for (int t = 0; t < 8; t++) {
        const int col = t * 8 + 2 * tg;
        float2 w0, w1;
        w0.x = roundf_tf32(o[t][0] * inv0); w0.y = roundf_tf32(o[t][1] * inv0);
        w1.x = roundf_tf32(o[t][2] * inv1); w1.y = roundf_tf32(o[t][3] * inv1);
        *(float2*)(orow0 + col) = w0;
        *(float2*)(orow1 + col) = w1;
    }
}

// ---------------------------------------------------------------------------
// Transpose helpers (weight transposes round to tf32 — they feed mma B)
// ---------------------------------------------------------------------------
__global__ __launch_bounds__(256)
void transpose_k(const float* __restrict__ in, float* __restrict__ out, int K, int N)
{
    __shared__ float tile[32][33];
    const int k0 = blockIdx.y * 32, n0 = blockIdx.x * 32;
    const int tx = threadIdx.x, ty = threadIdx.y;
    #pragma unroll
    for (int i = ty; i < 32; i += 8)
        tile[i][tx] = in[(size_t)(k0 + i) * N + n0 + tx];
    __syncthreads();
    #pragma unroll
    for (int i = ty; i < 32; i += 8)
        out[(size_t)(n0 + i) * K + k0 + tx] = roundf_tf32(tile[tx][i]);
}

// V slice of fused qkv -> g_vt[bh][64][2048] (input already rounded)
__global__ __launch_bounds__(256)
void transpose_vt(const float* __restrict__ qkv, float* __restrict__ vt)
{
    __shared__ float tile[32][33];
    const int s0 = blockIdx.x * 32;
    const int d0 = blockIdx.y * 32;
    const int bh = blockIdx.z;
    const int b = bh >> 4, h = bh & 15;
    const int tx = threadIdx.x, ty = threadIdx.y;
    const float* in = qkv + (size_t)b * SEQ * QLD + 2 * DMODEL + h * HD;
    float* out = vt + (size_t)bh * HD * SEQ;
    #pragma unroll
    for (int i = ty; i < 32; i += 8)
        tile[i][tx] = in[(size_t)(s0 + i) * QLD + d0 + tx];
    __syncthreads();
    #pragma unroll
    for (int i = ty; i < 32; i += 8)
        out[(size_t)(d0 + i) * SEQ + s0 + tx] = tile[tx][i];
}

__global__ void concat_bias(const float* a, const float* b, const float* c, float* out)
{
    int i = blockIdx.x * 256 + threadIdx.x;
    if (i < DMODEL)            out[i] = a[i];
    else if (i < 2 * DMODEL)   out[i] = b[i - DMODEL];
    else if (i < 3 * DMODEL)   out[i] = c[i - 2 * DMODEL];
}

// Rounded copy: out[i] = tf32(in[i]). Vectorized float4.
__global__ __launch_bounds__(256)
void round_copy(const float* __restrict__ in, float* __restrict__ out, int n4)
{
    int i = blockIdx.x * 256 + threadIdx.x;
    if (i < n4) {
        float4 v = ((const float4*)in)[i];
        v.x = roundf_tf32(v.x); v.y = roundf_tf32(v.y);
        v.z = roundf_tf32(v.z); v.w = roundf_tf32(v.w);
        ((float4*)out)[i] = v;
    }
}

// ---------------------------------------------------------------------------
// Fused residual add + LayerNorm over D=1024. One block (256 threads) per row.
// Optionally writes a tf32-rounded second copy (for downstream GEMM A operand).
// ---------------------------------------------------------------------------
__global__ __launch_bounds__(256)
void add_ln(const float* __restrict__ A, const float* __restrict__ Bv,
            const float* __restrict__ g, const float* __restrict__ be,
            float* __restrict__ out, float* __restrict__ out_r)
{
    const int row = blockIdx.x;
    const int tid = threadIdx.x;

    const float4 a4 = ((const float4*)(A  + (size_t)row * DMODEL))[tid];
    const float4 b4 = ((const float4*)(Bv + (size_t)row * DMODEL))[tid];
    float4 v;
    v.x = a4.x + b4.x; v.y = a4.y + b4.y; v.z = a4.z + b4.z; v.w = a4.w + b4.w;

    float s  = v.x + v.y + v.z + v.w;
    float ss = v.x*v.x + v.y*v.y + v.z*v.z + v.w*v.w;

    #pragma unroll
    for (int ofs = 16; ofs > 0; ofs >>= 1) {
        s  += __shfl_xor_sync(0xFFFFFFFFu, s,  ofs);
        ss += __shfl_xor_sync(0xFFFFFFFFu, ss, ofs);
    }

    __shared__ float shs[8], shss[8];
    const int w = tid >> 5;
    if ((tid & 31) == 0) { shs[w] = s; shss[w] = ss; }
    __syncthreads();
    if (tid < 32) {
        float s2  = (tid < 8) ? shs[tid]  : 0.f;
        float ss2 = (tid < 8) ? shss[tid] : 0.f;
        #pragma unroll
        for (int ofs = 4; ofs > 0; ofs >>= 1) {
            s2  += __shfl_xor_sync(0xFFFFFFFFu, s2,  ofs);
            ss2 += __shfl_xor_sync(0xFFFFFFFFu, ss2, ofs);
        }
        if (tid == 0) { shs[0] = s2; shss[0] = ss2; }
    }
    __syncthreads();

    const float mu  = shs[0]  * (1.f / DMODEL);
    const float var = shss[0] * (1.f / DMODEL) - mu * mu;
    const float inv = rsqrtf(var + 1e-5f);

    const float4 gv = ((const float4*)g)[tid];
    const float4 bb = ((const float4*)be)[tid];
    float4 o;
    o.x = (v.x - mu) * inv * gv.x + bb.x;
    o.y = (v.y - mu) * inv * gv.y + bb.y;
    o.z = (v.z - mu) * inv * gv.z + bb.z;
    o.w = (v.w - mu) * inv * gv.w + bb.w;
    ((float4*)(out + (size_t)row * DMODEL))[tid] = o;
    if (out_r) {
        float4 r;
        r.x = roundf_tf32(o.x); r.y = roundf_tf32(o.y);
        r.z = roundf_tf32(o.z); r.w = roundf_tf32(o.w);
        ((float4*)(out_r + (size_t)row * DMODEL))[tid] = r;
    }
}

// ---------------------------------------------------------------------------
// Launch
// ---------------------------------------------------------------------------
extern "C" void kernel_launch(void* const* d_in, const int* in_sizes, int n_in,
                              void* d_out, int out_size)
{
    const float* src  = (const float*)d_in[0];
    const float* Wq   = (const float*)d_in[1];
    const float* bq   = (const float*)d_in[2];
    const float* Wk   = (const float*)d_in[3];
    const float* bk   = (const float*)d_in[4];
    const float* Wv   = (const float*)d_in[5];
    const float* bv   = (const float*)d_in[6];
    const float* Wo   = (const float*)d_in[7];
    const float* bo   = (const float*)d_in[8];
    const float* W1   = (const float*)d_in[9];
    const float* b1   = (const float*)d_in[10];
    const float* W2   = (const float*)d_in[11];
    const float* b2   = (const float*)d_in[12];
    const float* ln1g = (const float*)d_in[13];
    const float* ln1b = (const float*)d_in[14];
    const float* ln2g = (const float*)d_in[15];
    const float* ln2b = (const float*)d_in[16];
    float* out = (float*)d_out;

    float *pqkv, *pvt, *psrcr, *pxr, *pwqkvT, *pwoT, *pw1T, *pw2T, *pbqkv,
          *pctx, *ptmp, *px, *pff;
    cudaGetSymbolAddress((void**)&pqkv,   g_qkv);
    cudaGetSymbolAddress((void**)&pvt,    g_vt);
    cudaGetSymbolAddress((void**)&psrcr,  g_srcr);
    cudaGetSymbolAddress((void**)&pxr,    g_xr);
    cudaGetSymbolAddress((void**)&pwqkvT, g_wqkvT);
    cudaGetSymbolAddress((void**)&pwoT,   g_woT);
    cudaGetSymbolAddress((void**)&pw1T,   g_w1T);
    cudaGetSymbolAddress((void**)&pw2T,   g_w2T);
    cudaGetSymbolAddress((void**)&pbqkv,  g_bqkv);
    cudaGetSymbolAddress((void**)&pctx,   g_ctx);
    cudaGetSymbolAddress((void**)&ptmp,   g_tmp);
    cudaGetSymbolAddress((void**)&px,     g_x);
    cudaGetSymbolAddress((void**)&pff,    g_ff);

    cudaFuncSetAttribute((const void*)gemm_mma<false,false>, cudaFuncAttributeMaxDynamicSharedMemorySize, SMEM_DYN);
    cudaFuncSetAttribute((const void*)gemm_mma<false,true>,  cudaFuncAttributeMaxDynamicSharedMemorySize, SMEM_DYN);
    cudaFuncSetAttribute((const void*)gemm_mma<true,true>,   cudaFuncAttributeMaxDynamicSharedMemorySize, SMEM_DYN);
    cudaFuncSetAttribute((const void*)flash_mma, cudaFuncAttributeMaxDynamicSharedMemorySize, ATT_SMEM);

    // Pre-rounded inputs + weight transposes (to K-major [N,K], tf32-rounded)
    {
        dim3 blk(32, 8);
        round_copy<<<(NTOK * DMODEL / 4 + 255) / 256, 256>>>(src, psrcr, NTOK * DMODEL / 4);
        transpose_k<<<dim3(32, 32),  blk>>>(Wq, pwqkvT,                       DMODEL, DMODEL);
        transpose_k<<<dim3(32, 32),  blk>>>(Wk, pwqkvT + DMODEL * DMODEL,     DMODEL, DMODEL);
        transpose_k<<<dim3(32, 32),  blk>>>(Wv, pwqkvT + 2 * DMODEL * DMODEL, DMODEL, DMODEL);
        transpose_k<<<dim3(32, 32),  blk>>>(Wo, pwoT,  DMODEL, DMODEL);
        transpose_k<<<dim3(128, 32), blk>>>(W1, pw1T,  DMODEL, DFF);
        transpose_k<<<dim3(32, 128), blk>>>(W2, pw2T,  DFF,    DMODEL);
        concat_bias<<<12, 256>>>(bq, bk, bv, pbqkv);
    }

    // Fused QKV projection (output rounded: feeds attention)
    gemm_mma<false, true><<<dim3(3 * DMODEL / 256, NTOK / 128), 256, SMEM_DYN>>>(
        psrcr, pwqkvT, pbqkv, pqkv, NTOK, 3 * DMODEL, DMODEL);

    // V^T for attention PV operand
    transpose_vt<<<dim3(SEQ / 32, HD / 32, 32), dim3(32, 8)>>>(pqkv, pvt);

    // Tensor-core flash attention (output rounded: feeds O-proj)
    flash_mma<<<dim3(SEQ / 64, 2 * NHEAD), 128, ATT_SMEM>>>(pqkv, pvt, pctx);

    // Output projection (full-precision out: feeds residual) + LN1
    gemm_mma<false, false><<<dim3(DMODEL / 256, NTOK / 128), 256, SMEM_DYN>>>(
        pctx, pwoT, bo, ptmp, NTOK, DMODEL, DMODEL);
    add_ln<<<NTOK, 256>>>(src, ptmp, ln1g, ln1b, px, pxr);

    // FFN
    gemm_mma<true, true><<<dim3(DFF / 256, NTOK / 128), 256, SMEM_DYN>>>(
        pxr, pw1T, b1, pff, NTOK, DFF, DMODEL);
    gemm_mma<false, false><<<dim3(DMODEL / 256, NTOK / 128), 256, SMEM_DYN>>>(
        pff, pw2T, b2, ptmp, NTOK, DMODEL, DFF);
    add_ln<<<NTOK, 256>>>(px, ptmp, ln2g, ln2b, out, (float*)nullptr);
}

// round 8
// speedup vs baseline: 1.0930x; 1.0930x over previous
#include <cuda_runtime.h>
#include <cuda_bf16.h>
#include <math.h>
#include <stdint.h>

// Problem constants
#define NTOK   4096      // B*S = 2*2048
#define DMODEL 1024
#define DFF    4096
#define NHEAD  16
#define HD     64
#define SEQ    2048
#define QLD    (3 * DMODEL)   // fused qkv row stride

// ---------------------------------------------------------------------------
// Scratch (static device globals; no runtime allocation allowed)
// ---------------------------------------------------------------------------
__device__ __align__(16) float g_qkv [NTOK * 3 * DMODEL];    // fused q|k|v (tf32-rounded)
__device__ __align__(16) float g_vt  [32 * HD * SEQ];        // V^T per (b,h): [64][2048]
__device__ __align__(16) float g_srcr[NTOK * DMODEL];        // rounded src (QKV A operand)
__device__ __align__(16) float g_xr  [NTOK * DMODEL];        // rounded LN1 out (FFN1 A)
__device__ __align__(16) float g_wqkvT[3 * DMODEL * DMODEL]; // [3072,1024] K-major, rounded
__device__ __align__(16) float g_woT [DMODEL * DMODEL];
__device__ __align__(16) float g_w1T [DFF * DMODEL];
__device__ __align__(16) float g_w2T [DMODEL * DFF];
__device__ __align__(16) float g_bqkv[3 * DMODEL];
__device__ __align__(16) float g_ctx [NTOK * DMODEL];        // rounded flash output
__device__ __align__(16) float g_tmp [NTOK * DMODEL];
__device__ __align__(16) float g_x   [NTOK * DMODEL];
__device__ __align__(16) float g_ff  [NTOK * DFF];           // rounded FFN1 output

// ---------------------------------------------------------------------------
// PTX helpers (baseline sm_80+ features only — harness targets plain sm_103)
// ---------------------------------------------------------------------------
__device__ __forceinline__ uint32_t smem_u32(const void* p) {
    uint32_t a;
    asm("{ .reg .u64 t; cvta.to.shared.u64 t, %1; cvt.u32.u64 %0, t; }" : "=r"(a) : "l"(p));
    return a;
}
#define CP_ASYNC16(dst, src) \
    asm volatile("cp.async.cg.shared.global [%0], [%1], 16;" :: "r"(dst), "l"(src))
#define CP_COMMIT() asm volatile("cp.async.commit_group;" ::: "memory")
#define CP_WAIT(n)  asm volatile("cp.async.wait_group %0;" :: "n"(n) : "memory")

#define LDMATRIX_X4(r0, r1, r2, r3, addr) \
    asm volatile("ldmatrix.sync.aligned.m8n8.x4.shared.b16 {%0,%1,%2,%3}, [%4];" \
                 : "=r"(r0), "=r"(r1), "=r"(r2), "=r"(r3) : "r"(addr))

__device__ __forceinline__ uint32_t to_tf32f(float f) {
    uint32_t o;
    asm("cvt.rna.tf32.f32 %0, %1;" : "=r"(o) : "f"(f));
    return o;
}
__device__ __forceinline__ float roundf_tf32(float f) {
    return __uint_as_float(to_tf32f(f));
}

#define MMA_TF32(c0, c1, c2, c3, a0, a1, a2, a3, b0, b1) \
    asm volatile("mma.sync.aligned.m16n8k8.row.col.f32.tf32.tf32.f32 " \
                 "{%0,%1,%2,%3}, {%4,%5,%6,%7}, {%8,%9}, {%0,%1,%2,%3};" \
                 : "+f"(c0), "+f"(c1), "+f"(c2), "+f"(c3) \
                 : "r"(a0), "r"(a1), "r"(a2), "r"(a3), "r"(b0), "r"(b1))

// ---------------------------------------------------------------------------
// tf32 tensor-core GEMM (R6-proven config):  C = A @ BT^T + bias.
// 128x128 block tile, K-chunk 32, 256 threads (8 warps, warp tile 64x32),
// 4-stage cp.async pipeline. Inputs already tf32-rounded.
// ---------------------------------------------------------------------------
#define STAGES 4
#define STAGE_BYTES (2 * 128 * 32 * 4)
#define SMEM_DYN (STAGES * STAGE_BYTES)

template <bool RELU, bool ROUND>
__global__ __launch_bounds__(256, 1)
void gemm_mma(const float* __restrict__ A, const float* __restrict__ BT,
              const float* __restrict__ bias, float* __restrict__ C,
              int M, int N, int K)
{
    extern __shared__ char smem[];
    const uint32_t sbase = smem_u32(smem);
    const int tid  = threadIdx.x;
    const int wid  = tid >> 5;
    const int lane = tid & 31;
    const int warp_m = wid & 1;
    const int warp_n = wid >> 1;
    const int gid = lane >> 2;
    const int tg  = lane & 3;

    const int bm = blockIdx.y * 128;
    const int bn = blockIdx.x * 128;
    const int KT = K >> 5;

    const int lrow  = tid >> 1;
    const int lunit = (tid & 1) * 4;
    const float* Ag = A  + (size_t)(bm + lrow) * K + lunit * 4;
    const float* Bg = BT + (size_t)(bn + lrow) * K + lunit * 4;
    uint32_t lsw[4];
    #pragma unroll
    for (int i = 0; i < 4; i++) {
        uint32_t off = lrow * 128 + (lunit + i) * 16;
        lsw[i] = off ^ ((off >> 3) & 0x70);
    }

    uint32_t a_rel[4], a_xr[4];
    #pragma unroll
    for (int i = 0; i < 4; i++) {
        int r = warp_m * 64 + i * 16 + (lane & 7) + ((lane >> 3) & 1) * 8;
        a_rel[i] = r * 128;
        a_xr[i]  = (r & 7) << 4;
    }
    const uint32_t a_kb = ((lane >> 4) & 1) * 16;
    uint32_t b_rel[2], b_xr[2];
    #pragma unroll
    for (int j = 0; j < 2; j++) {
        int r = warp_n * 32 + j * 16 + (lane & 7) + ((lane >> 4) & 1) * 8;
        b_rel[j] = r * 128;
        b_xr[j]  = (r & 7) << 4;
    }
    const uint32_t b_kb = ((lane >> 3) & 1) * 16;

    float acc[4][4][4];
    #pragma unroll
    for (int i = 0; i < 4; i++)
        #pragma unroll
        for (int t = 0; t < 4; t++)
            #pragma unroll
            for (int r = 0; r < 4; r++) acc[i][t][r] = 0.f;

    auto load_tile = [&](int s, int kt) {
        const uint32_t sA = sbase + s * STAGE_BYTES;
        const uint32_t sB = sA + 16384;
        const float* ar = Ag + kt * 32;
        const float* br = Bg + kt * 32;
        #pragma unroll
        for (int i = 0; i < 4; i++) CP_ASYNC16(sA + lsw[i], ar + i * 4);
        #pragma unroll
        for (int i = 0; i < 4; i++) CP_ASYNC16(sB + lsw[i], br + i * 4);
    };

    #pragma unroll
    for (int s = 0; s < STAGES - 1; s++) { load_tile(s, s); CP_COMMIT(); }

    for (int kt = 0; kt < KT; kt++) {
        const int cur = kt & (STAGES - 1);
        CP_WAIT(STAGES - 2);
        __syncthreads();

        const int pf = kt + STAGES - 1;
        if (pf < KT) load_tile(pf & (STAGES - 1), pf);
        CP_COMMIT();

        const uint32_t sA = sbase + cur * STAGE_BYTES;
        const uint32_t sB = sA + 16384;

        #pragma unroll
        for (int ks = 0; ks < 4; ks++) {
            const uint32_t kso = ks * 32;
            uint32_t af[4][4];
            #pragma unroll
            for (int i = 0; i < 4; i++) {
                uint32_t addr = sA + ((a_rel[i] + a_kb + kso) ^ a_xr[i]);
                LDMATRIX_X4(af[i][0], af[i][1], af[i][2], af[i][3], addr);
            }
            uint32_t bf[4][2];
            #pragma unroll
            for (int j = 0; j < 2; j++) {
                uint32_t r0, r1, r2, r3;
                uint32_t addr = sB + ((b_rel[j] + b_kb + kso) ^ b_xr[j]);
                LDMATRIX_X4(r0, r1, r2, r3, addr);
                bf[2*j+0][0] = r0; bf[2*j+0][1] = r1;
                bf[2*j+1][0] = r2; bf[2*j+1][1] = r3;
            }
            #pragma unroll
            for (int i = 0; i < 4; i++)
                #pragma unroll
                for (int t = 0; t < 4; t++)
                    MMA_TF32(acc[i][t][0], acc[i][t][1], acc[i][t][2], acc[i][t][3],
                             af[i][0], af[i][1], af[i][2], af[i][3],
                             bf[t][0], bf[t][1]);
        }
        __syncthreads();
    }

    #pragma unroll
    for (int i = 0; i < 4; i++) {
        const int row0 = bm + warp_m * 64 + i * 16 + gid;
        #pragma unroll
        for (int t = 0; t < 4; t++) {
            const int col = bn + warp_n * 32 + t * 8 + 2 * tg;
            const float2 bv = *(const float2*)(bias + col);
            float2 v0, v1;
            v0.x = acc[i][t][0] + bv.x; v0.y = acc[i][t][1] + bv.y;
            v1.x = acc[i][t][2] + bv.x; v1.y = acc[i][t][3] + bv.y;
            if (RELU) {
                v0.x = fmaxf(v0.x, 0.f); v0.y = fmaxf(v0.y, 0.f);
                v1.x = fmaxf(v1.x, 0.f); v1.y = fmaxf(v1.y, 0.f);
            }
            if (ROUND) {
                v0.x = roundf_tf32(v0.x); v0.y = roundf_tf32(v0.y);
                v1.x = roundf_tf32(v1.x); v1.y = roundf_tf32(v1.y);
            }
            *(float2*)(C + (size_t)row0 * N + col)       = v0;
            *(float2*)(C + (size_t)(row0 + 8) * N + col) = v1;
        }
    }
}

// ---------------------------------------------------------------------------
// Tensor-core flash attention (tf32 mma). 64 queries x 1 head per block.
// 2 blocks/SM for latency hiding.
// ---------------------------------------------------------------------------
#define ATT_SMEM 65536

__global__ __launch_bounds__(128, 2)
void flash_mma(const float* __restrict__ QKV, const float* __restrict__ VT,
               float* __restrict__ O)
{
    extern __shared__ char smem[];
    const uint32_t sbase = smem_u32(smem);
    const int tid  = threadIdx.x;
    const int wid  = tid >> 5;
    const int lane = tid & 31;
    const int gid  = lane >> 2;
    const int tg   = lane & 3;

    const int bh = blockIdx.y;
    const int b  = bh >> 4;
    const int h  = bh & 15;
    const int q0 = blockIdx.x * 64;

    const float* Qg  = QKV + (size_t)b * SEQ * QLD + h * HD;
    const float* Kg  = Qg + DMODEL;
    const float* VTg = VT + (size_t)bh * HD * SEQ;

    const uint32_t qreg = sbase + 32768;

    const int lrow = tid >> 1;
    const int lu0  = (tid & 1) * 8;
    uint32_t lsw[8];
    #pragma unroll
    for (int i = 0; i < 8; i++) {
        int u = lu0 + i;
        uint32_t off = lrow * 128 + (u & 7) * 16;
        lsw[i] = (u >> 3) * 8192 + (off ^ ((off >> 3) & 0x70));
    }

    uint32_t aq_rel, aq_xr;
    {
        int r = wid * 16 + (lane & 7) + ((lane >> 3) & 1) * 8;
        aq_rel = r * 128;
        aq_xr  = (r & 7) << 4;
    }
    const uint32_t a_kb = ((lane >> 4) & 1) * 16;
    uint32_t b_rel[4], b_xr[4];
    #pragma unroll
    for (int j = 0; j < 4; j++) {
        int r = j * 16 + (lane & 7) + ((lane >> 4) & 1) * 8;
        b_rel[j] = r * 128;
        b_xr[j]  = (r & 7) << 4;
    }
    const uint32_t b_kb = ((lane >> 3) & 1) * 16;

    auto load_KV = [&](int stage, int kt) {
        const uint32_t sK = sbase + stage * 32768;
        const uint32_t sV = sK + 16384;
        const float* kr = Kg  + (size_t)(kt * 64 + lrow) * QLD + lu0 * 4;
        const float* vr = VTg + (size_t)lrow * SEQ + kt * 64 + lu0 * 4;
        #pragma unroll
        for (int i = 0; i < 8; i++) CP_ASYNC16(sK + lsw[i], kr + i * 4);
        #pragma unroll
        for (int i = 0; i < 8; i++) CP_ASYNC16(sV + lsw[i], vr + i * 4);
    };

    {
        const float* qr = Qg + (size_t)(q0 + lrow) * QLD + lu0 * 4;
        #pragma unroll
        for (int i = 0; i < 8; i++) CP_ASYNC16(qreg + lsw[i], qr + i * 4);
        load_KV(0, 0);
        CP_COMMIT();
        CP_WAIT(0);
        __syncthreads();
    }

    uint32_t qf[8][4];
    #pragma unroll
    for (int c = 0; c < 2; c++)
        #pragma unroll
        for (int ks = 0; ks < 4; ks++) {
            uint32_t addr = qreg + c * 8192 + ((aq_rel + a_kb + ks * 32) ^ aq_xr);
            LDMATRIX_X4(qf[c*4+ks][0], qf[c*4+ks][1], qf[c*4+ks][2], qf[c*4+ks][3], addr);
        }
    __syncthreads();

    const int NT = SEQ / 64;
    load_KV(1, 1);
    CP_COMMIT();

    float o[8][4];
    #pragma unroll
    for (int t = 0; t < 8; t++)
        #pragma unroll
        for (int r = 0; r < 4; r++) o[t][r] = 0.f;
    float m0 = -1e30f, m1 = -1e30f, l0 = 0.f, l1 = 0.f;

    for (int kt = 0; kt < NT; kt++) {
        if (kt < NT - 1) { CP_WAIT(1); } else { CP_WAIT(0); }
        __syncthreads();
        const uint32_t sK = sbase + (kt & 1) * 32768;
        const uint32_t sV = sK + 16384;

        // ---- S = Q @ K^T ----
        float s[8][4];
        #pragma unroll
        for (int t = 0; t < 8; t++)
            #pragma unroll
            for (int r = 0; r < 4; r++) s[t][r] = 0.f;

        #pragma unroll
        for (int c = 0; c < 2; c++)
            #pragma unroll
            for (int ks = 0; ks < 4; ks++) {
                uint32_t bf[8][2];
                #pragma unroll
                for (int j = 0; j < 4; j++) {
                    uint32_t r0, r1, r2, r3;
                    uint32_t addr = sK + c * 8192 + ((b_rel[j] + b_kb + ks * 32) ^ b_xr[j]);
                    LDMATRIX_X4(r0, r1, r2, r3, addr);
                    bf[2*j+0][0] = r0; bf[2*j+0][1] = r1;
                    bf[2*j+1][0] = r2; bf[2*j+1][1] = r3;
                }
                const uint32_t* aq = qf[c*4+ks];
                #pragma unroll
                for (int t = 0; t < 8; t++)
                    MMA_TF32(s[t][0], s[t][1], s[t][2], s[t][3],
                             aq[0], aq[1], aq[2], aq[3], bf[t][0], bf[t][1]);
            }

        // ---- online softmax ----
        float tmax0 = -1e30f, tmax1 = -1e30f;
        #pragma unroll
        for (int t = 0; t < 8; t++) {
            s[t][0] *= 0.125f; s[t][1] *= 0.125f; s[t][2] *= 0.125f; s[t][3] *= 0.125f;
            tmax0 = fmaxf(tmax0, fmaxf(s[t][0], s[t][1]));
            tmax1 = fmaxf(tmax1, fmaxf(s[t][2], s[t][3]));
        }
        tmax0 = fmaxf(tmax0, __shfl_xor_sync(0xffffffffu, tmax0, 1));
        tmax0 = fmaxf(tmax0, __shfl_xor_sync(0xffffffffu, tmax0, 2));
        tmax1 = fmaxf(tmax1, __shfl_xor_sync(0xffffffffu, tmax1, 1));
        tmax1 = fmaxf(tmax1, __shfl_xor_sync(0xffffffffu, tmax1, 2));

        const float mnew0 = fmaxf(m0, tmax0);
        const float mnew1 = fmaxf(m1, tmax1);
        const float corr0 = __expf(m0 - mnew0);
        const float corr1 = __expf(m1 - mnew1);

        float rs0 = 0.f, rs1 = 0.f;
        #pragma unroll
        for (int t = 0; t < 8; t++) {
            s[t][0] = __expf(s[t][0] - mnew0);
            s[t][1] = __expf(s[t][1] - mnew0);
            s[t][2] = __expf(s[t][2] - mnew1);
            s[t][3] = __expf(s[t][3] - mnew1);
            rs0 += s[t][0] + s[t][1];
            rs1 += s[t][2] + s[t][3];
        }
        rs0 += __shfl_xor_sync(0xffffffffu, rs0, 1);
        rs0 += __shfl_xor_sync(0xffffffffu, rs0, 2);
        rs1 += __shfl_xor_sync(0xffffffffu, rs1, 1);
        rs1 += __shfl_xor_sync(0xffffffffu, rs1, 2);

        l0 = l0 * corr0 + rs0;
        l1 = l1 * corr1 + rs1;
        #pragma unroll
        for (int t = 0; t < 8; t++) {
            o[t][0] *= corr0; o[t][1] *= corr0;
            o[t][2] *= corr1; o[t][3] *= corr1;
        }
        m0 = mnew0; m1 = mnew1;

        // ---- ctx += P @ V ----
        #pragma unroll
        for (int ks = 0; ks < 8; ks++) {
            const int src0 = tg >> 1, src1 = src0 + 2;
            float v00 = __shfl_sync(0xffffffffu, s[ks][0], src0, 4);
            float v01 = __shfl_sync(0xffffffffu, s[ks][1], src0, 4);
            float v20 = __shfl_sync(0xffffffffu, s[ks][0], src1, 4);
            float v21 = __shfl_sync(0xffffffffu, s[ks][1], src1, 4);
            float v10 = __shfl_sync(0xffffffffu, s[ks][2], src0, 4);
            float v11 = __shfl_sync(0xffffffffu, s[ks][3], src0, 4);
            float v30 = __shfl_sync(0xffffffffu, s[ks][2], src1, 4);
            float v31 = __shfl_sync(0xffffffffu, s[ks][3], src1, 4);
            const bool oddc = (tg & 1);
            uint32_t a0 = to_tf32f(oddc ? v01 : v00);
            uint32_t a1 = to_tf32f(oddc ? v11 : v10);
            uint32_t a2 = to_tf32f(oddc ? v21 : v20);
            uint32_t a3 = to_tf32f(oddc ? v31 : v30);

            uint32_t bf[8][2];
            const uint32_t vbase = sV + (ks >> 2) * 8192;
            const uint32_t kso = (ks & 3) * 32;
            #pragma unroll
            for (int j = 0; j < 4; j++) {
                uint32_t r0, r1, r2, r3;
                uint32_t addr = vbase + ((b_rel[j] + b_kb + kso) ^ b_xr[j]);
                LDMATRIX_X4(r0, r1, r2, r3, addr);
                bf[2*j+0][0] = r0; bf[2*j+0][1] = r1;
                bf[2*j+1][0] = r2; bf[2*j+1][1] = r3;
            }
            #pragma unroll
            for (int t = 0; t < 8; t++)
                MMA_TF32(o[t][0], o[t][1], o[t][2], o[t][3],
                         a0, a1, a2, a3, bf[t][0], bf[t][1]);
        }

        __syncthreads();
        const int pf = kt + 2;
        if (pf < NT) { load_KV(pf & 1, pf); CP_COMMIT(); }
    }

    // ---- write ctx (tf32-rounded: feeds O-projection A operand) ----
    const float inv0 = 1.0f / l0;
    const float inv1 = 1.0f / l1;
    const int qa = q0 + wid * 16 + gid;
    float* orow0 = O + (size_t)(b * SEQ + qa)     * DMODEL + h * HD;
    float* orow1 = O + (size_t)(b * SEQ + qa + 8) * DMODEL + h * HD;
    #pragma unroll
    for (int t = 0; t < 8; t++) {
        const int col = t * 8 + 2 * tg;
        float2 w0, w1;
        w0.x = roundf_tf32(o[t][0] * inv0); w0.y = roundf_tf32(o[t][1] * inv0);
        w1.x = roundf_tf32(o[t][2] * inv1); w1.y = roundf_tf32(o[t][3] * inv1);
        *(float2*)(orow0 + col) = w0;
        *(float2*)(orow1 + col) = w1;
    }
}

// ---------------------------------------------------------------------------
// Transpose helpers (weight transposes round to tf32 — they feed mma B)
// ---------------------------------------------------------------------------
__global__ __launch_bounds__(256)
void transpose_k(const float* __restrict__ in, float* __restrict__ out, int K, int N)
{
    __shared__ float tile[32][33];
    const int k0 = blockIdx.y * 32, n0 = blockIdx.x * 32;
    const int tx = threadIdx.x, ty = threadIdx.y;
    #pragma unroll
    for (int i = ty; i < 32; i += 8)
        tile[i][tx] = in[(size_t)(k0 + i) * N + n0 + tx];
    __syncthreads();
    #pragma unroll
    for (int i = ty; i < 32; i += 8)
        out[(size_t)(n0 + i) * K + k0 + tx] = roundf_tf32(tile[tx][i]);
}

// V slice of fused qkv -> g_vt[bh][64][2048] (input already rounded)
__global__ __launch_bounds__(256)
void transpose_vt(const float* __restrict__ qkv, float* __restrict__ vt)
{
    __shared__ float tile[32][33];
    const int s0 = blockIdx.x * 32;
    const int d0 = blockIdx.y * 32;
    const int bh = blockIdx.z;
    const int b = bh >> 4, h = bh & 15;
    const int tx = threadIdx.x, ty = threadIdx.y;
    const float* in = qkv + (size_t)b * SEQ * QLD + 2 * DMODEL + h * HD;
    float* out = vt + (size_t)bh * HD * SEQ;
    #pragma unroll
    for (int i = ty; i < 32; i += 8)
        tile[i][tx] = in[(size_t)(s0 + i) * QLD + d0 + tx];
    __syncthreads();
    #pragma unroll
    for (int i = ty; i < 32; i += 8)
        out[(size_t)(d0 + i) * SEQ + s0 + tx] = tile[tx][i];
}

__global__ void concat_bias(const float* a, const float* b, const float* c, float* out)
{
    int i = blockIdx.x * 256 + threadIdx.x;
    if (i < DMODEL)            out[i] = a[i];
    else if (i < 2 * DMODEL)   out[i] = b[i - DMODEL];
    else if (i < 3 * DMODEL)   out[i] = c[i - 2 * DMODEL];
}

// Rounded copy: out[i] = tf32(in[i]). Vectorized float4.
__global__ __launch_bounds__(256)
void round_copy(const float* __restrict__ in, float* __restrict__ out, int n4)
{
    int i = blockIdx.x * 256 + threadIdx.x;
    if (i < n4) {
        float4 v = ((const float4*)in)[i];
        v.x = roundf_tf32(v.x); v.y = roundf_tf32(v.y);
        v.z = roundf_tf32(v.z); v.w = roundf_tf32(v.w);
        ((float4*)out)[i] = v;
    }
}

// ---------------------------------------------------------------------------
// Fused residual add + LayerNorm over D=1024. One block (256 threads) per row.
// Optionally writes a tf32-rounded second copy (for downstream GEMM A operand).
// ---------------------------------------------------------------------------
__global__ __launch_bounds__(256)
void add_ln(const float* __restrict__ A, const float* __restrict__ Bv,
            const float* __restrict__ g, const float* __restrict__ be,
            float* __restrict__ out, float* __restrict__ out_r)
{
    const int row = blockIdx.x;
    const int tid = threadIdx.x;

    const float4 a4 = ((const float4*)(A  + (size_t)row * DMODEL))[tid];
    const float4 b4 = ((const float4*)(Bv + (size_t)row * DMODEL))[tid];
    float4 v;
    v.x = a4.x + b4.x; v.y = a4.y + b4.y; v.z = a4.z + b4.z; v.w = a4.w + b4.w;

    float s  = v.x + v.y + v.z + v.w;
    float ss = v.x*v.x + v.y*v.y + v.z*v.z + v.w*v.w;

    #pragma unroll
    for (int ofs = 16; ofs > 0; ofs >>= 1) {
        s  += __shfl_xor_sync(0xFFFFFFFFu, s,  ofs);
        ss += __shfl_xor_sync(0xFFFFFFFFu, ss, ofs);
    }

    __shared__ float shs[8], shss[8];
    const int w = tid >> 5;
    if ((tid & 31) == 0) { shs[w] = s; shss[w] = ss; }
    __syncthreads();
    if (tid < 32) {
        float s2  = (tid < 8) ? shs[tid]  : 0.f;
        float ss2 = (tid < 8) ? shss[tid] : 0.f;
        #pragma unroll
        for (int ofs = 4; ofs > 0; ofs >>= 1) {
            s2  += __shfl_xor_sync(0xFFFFFFFFu, s2,  ofs);
            ss2 += __shfl_xor_sync(0xFFFFFFFFu, ss2, ofs);
        }
        if (tid == 0) { shs[0] = s2; shss[0] = ss2; }
    }
    __syncthreads();

    const float mu  = shs[0]  * (1.f / DMODEL);
    const float var = shss[0] * (1.f / DMODEL) - mu * mu;
    const float inv = rsqrtf(var + 1e-5f);

    const float4 gv = ((const float4*)g)[tid];
    const float4 bb = ((const float4*)be)[tid];
    float4 o;
    o.x = (v.x - mu) * inv * gv.x + bb.x;
    o.y = (v.y - mu) * inv * gv.y + bb.y;
    o.z = (v.z - mu) * inv * gv.z + bb.z;
    o.w = (v.w - mu) * inv * gv.w + bb.w;
    ((float4*)(out + (size_t)row * DMODEL))[tid] = o;
    if (out_r) {
        float4 r;
        r.x = roundf_tf32(o.x); r.y = roundf_tf32(o.y);
        r.z = roundf_tf32(o.z); r.w = roundf_tf32(o.w);
        ((float4*)(out_r + (size_t)row * DMODEL))[tid] = r;
    }
}

// ---------------------------------------------------------------------------
// Launch
// ---------------------------------------------------------------------------
extern "C" void kernel_launch(void* const* d_in, const int* in_sizes, int n_in,
                              void* d_out, int out_size)
{
    const float* src  = (const float*)d_in[0];
    const float* Wq   = (const float*)d_in[1];
    const float* bq   = (const float*)d_in[2];
    const float* Wk   = (const float*)d_in[3];
    const float* bk   = (const float*)d_in[4];
    const float* Wv   = (const float*)d_in[5];
    const float* bv   = (const float*)d_in[6];
    const float* Wo   = (const float*)d_in[7];
    const float* bo   = (const float*)d_in[8];
    const float* W1   = (const float*)d_in[9];
    const float* b1   = (const float*)d_in[10];
    const float* W2   = (const float*)d_in[11];
    const float* b2   = (const float*)d_in[12];
    const float* ln1g = (const float*)d_in[13];
    const float* ln1b = (const float*)d_in[14];
    const float* ln2g = (const float*)d_in[15];
    const float* ln2b = (const float*)d_in[16];
    float* out = (float*)d_out;

    float *pqkv, *pvt, *psrcr, *pxr, *pwqkvT, *pwoT, *pw1T, *pw2T, *pbqkv,
          *pctx, *ptmp, *px, *pff;
    cudaGetSymbolAddress((void**)&pqkv,   g_qkv);
    cudaGetSymbolAddress((void**)&pvt,    g_vt);
    cudaGetSymbolAddress((void**)&psrcr,  g_srcr);
    cudaGetSymbolAddress((void**)&pxr,    g_xr);
    cudaGetSymbolAddress((void**)&pwqkvT, g_wqkvT);
    cudaGetSymbolAddress((void**)&pwoT,   g_woT);
    cudaGetSymbolAddress((void**)&pw1T,   g_w1T);
    cudaGetSymbolAddress((void**)&pw2T,   g_w2T);
    cudaGetSymbolAddress((void**)&pbqkv,  g_bqkv);
    cudaGetSymbolAddress((void**)&pctx,   g_ctx);
    cudaGetSymbolAddress((void**)&ptmp,   g_tmp);
    cudaGetSymbolAddress((void**)&px,     g_x);
    cudaGetSymbolAddress((void**)&pff,    g_ff);

    cudaFuncSetAttribute((const void*)gemm_mma<false,false>, cudaFuncAttributeMaxDynamicSharedMemorySize, SMEM_DYN);
    cudaFuncSetAttribute((const void*)gemm_mma<false,true>,  cudaFuncAttributeMaxDynamicSharedMemorySize, SMEM_DYN);
    cudaFuncSetAttribute((const void*)gemm_mma<true,true>,   cudaFuncAttributeMaxDynamicSharedMemorySize, SMEM_DYN);
    cudaFuncSetAttribute((const void*)flash_mma, cudaFuncAttributeMaxDynamicSharedMemorySize, ATT_SMEM);

    // Pre-rounded inputs + weight transposes (to K-major [N,K], tf32-rounded)
    {
        dim3 blk(32, 8);
        round_copy<<<(NTOK * DMODEL / 4 + 255) / 256, 256>>>(src, psrcr, NTOK * DMODEL / 4);
        transpose_k<<<dim3(32, 32),  blk>>>(Wq, pwqkvT,                       DMODEL, DMODEL);
        transpose_k<<<dim3(32, 32),  blk>>>(Wk, pwqkvT + DMODEL * DMODEL,     DMODEL, DMODEL);
        transpose_k<<<dim3(32, 32),  blk>>>(Wv, pwqkvT + 2 * DMODEL * DMODEL, DMODEL, DMODEL);
        transpose_k<<<dim3(32, 32),  blk>>>(Wo, pwoT,  DMODEL, DMODEL);
        transpose_k<<<dim3(128, 32), blk>>>(W1, pw1T,  DMODEL, DFF);
        transpose_k<<<dim3(32, 128), blk>>>(W2, pw2T,  DFF,    DMODEL);
        concat_bias<<<12, 256>>>(bq, bk, bv, pbqkv);
    }

    // Fused QKV projection (output rounded: feeds attention)
    gemm_mma<false, true><<<dim3(3 * DMODEL / 128, NTOK / 128), 256, SMEM_DYN>>>(
        psrcr, pwqkvT, pbqkv, pqkv, NTOK, 3 * DMODEL, DMODEL);

    // V^T for attention PV operand
    transpose_vt<<<dim3(SEQ / 32, HD / 32, 32), dim3(32, 8)>>>(pqkv, pvt);

    // Tensor-core flash attention (output rounded: feeds O-proj)
    flash_mma<<<dim3(SEQ / 64, 2 * NHEAD), 128, ATT_SMEM>>>(pqkv, pvt, pctx);

    // Output projection (full-precision out: feeds residual) + LN1
    gemm_mma<false, false><<<dim3(DMODEL / 128, NTOK / 128), 256, SMEM_DYN>>>(
        pctx, pwoT, bo, ptmp, NTOK, DMODEL, DMODEL);
    add_ln<<<NTOK, 256>>>(src, ptmp, ln1g, ln1b, px, pxr);

    // FFN
    gemm_mma<true, true><<<dim3(DFF / 128, NTOK / 128), 256, SMEM_DYN>>>(
        pxr, pw1T, b1, pff, NTOK, DFF, DMODEL);
    gemm_mma<false, false><<<dim3(DMODEL / 128, NTOK / 128), 256, SMEM_DYN>>>(
        pff, pw2T, b2, ptmp, NTOK, DMODEL, DFF);
    add_ln<<<NTOK, 256>>>(px, ptmp, ln2g, ln2b, out, (float*)nullptr);
}

// round 9
// speedup vs baseline: 1.1866x; 1.0856x over previous
#include <cuda_runtime.h>
#include <cuda_bf16.h>
#include <math.h>
#include <stdint.h>

// Problem constants
#define NTOK   4096      // B*S = 2*2048
#define DMODEL 1024
#define DFF    4096
#define NHEAD  16
#define HD     64
#define SEQ    2048
#define QLD    (3 * DMODEL)   // fused qkv row stride

// ---------------------------------------------------------------------------
// Scratch (static device globals; no runtime allocation allowed)
// ---------------------------------------------------------------------------
__device__ __align__(16) float g_qkv [NTOK * 3 * DMODEL];    // fused q|k|v (tf32-rounded)
__device__ __align__(16) float g_vt  [32 * HD * SEQ];        // V^T per (b,h): [64][2048]
__device__ __align__(16) float g_srcr[NTOK * DMODEL];        // rounded src (QKV A operand)
__device__ __align__(16) float g_xr  [NTOK * DMODEL];        // rounded LN1 out (FFN1 A)
__device__ __align__(16) float g_wqkvT[3 * DMODEL * DMODEL]; // [3072,1024] K-major, rounded
__device__ __align__(16) float g_woT [DMODEL * DMODEL];
__device__ __align__(16) float g_w1T [DFF * DMODEL];
__device__ __align__(16) float g_w2T [DMODEL * DFF];
__device__ __align__(16) float g_bqkv[3 * DMODEL];
__device__ __align__(16) float g_ctx [NTOK * DMODEL];        // rounded flash output
__device__ __align__(16) float g_tmp [NTOK * DMODEL];
__device__ __align__(16) float g_x   [NTOK * DMODEL];
__device__ __align__(16) float g_ff  [NTOK * DFF];           // rounded FFN1 output

// ---------------------------------------------------------------------------
// PTX helpers (baseline sm_80+ features only — harness targets plain sm_103)
// ---------------------------------------------------------------------------
__device__ __forceinline__ uint32_t smem_u32(const void* p) {
    uint32_t a;
    asm("{ .reg .u64 t; cvta.to.shared.u64 t, %1; cvt.u32.u64 %0, t; }" : "=r"(a) : "l"(p));
    return a;
}
#define CP_ASYNC16(dst, src) \
    asm volatile("cp.async.cg.shared.global [%0], [%1], 16;" :: "r"(dst), "l"(src))
#define CP_COMMIT() asm volatile("cp.async.commit_group;" ::: "memory")
#define CP_WAIT(n)  asm volatile("cp.async.wait_group %0;" :: "n"(n) : "memory")

#define LDMATRIX_X4(r0, r1, r2, r3, addr) \
    asm volatile("ldmatrix.sync.aligned.m8n8.x4.shared.b16 {%0,%1,%2,%3}, [%4];" \
                 : "=r"(r0), "=r"(r1), "=r"(r2), "=r"(r3) : "r"(addr))

__device__ __forceinline__ uint32_t to_tf32f(float f) {
    uint32_t o;
    asm("cvt.rna.tf32.f32 %0, %1;" : "=r"(o) : "f"(f));
    return o;
}
__device__ __forceinline__ float roundf_tf32(float f) {
    return __uint_as_float(to_tf32f(f));
}

#define MMA_TF32(c0, c1, c2, c3, a0, a1, a2, a3, b0, b1) \
    asm volatile("mma.sync.aligned.m16n8k8.row.col.f32.tf32.tf32.f32 " \
                 "{%0,%1,%2,%3}, {%4,%5,%6,%7}, {%8,%9}, {%0,%1,%2,%3};" \
                 : "+f"(c0), "+f"(c1), "+f"(c2), "+f"(c3) \
                 : "r"(a0), "r"(a1), "r"(a2), "r"(a3), "r"(b0), "r"(b1))

// ---------------------------------------------------------------------------
// tf32 tensor-core GEMM:  C = A @ BT^T + bias.
// 128x128 block tile, K-chunk 32, 256 threads (8 warps, warp tile 64x32),
// 3-stage cp.async pipeline, 2 blocks/SM, one barrier per iteration.
// Inputs already tf32-rounded.
// ---------------------------------------------------------------------------
#define STAGES 3
#define STAGE_BYTES (2 * 128 * 32 * 4)
#define SMEM_DYN (STAGES * STAGE_BYTES)     // 96KB -> 2 blocks/SM

template <bool RELU, bool ROUND>
__global__ __launch_bounds__(256, 2)
void gemm_mma(const float* __restrict__ A, const float* __restrict__ BT,
              const float* __restrict__ bias, float* __restrict__ C,
              int M, int N, int K)
{
    extern __shared__ char smem[];
    const uint32_t sbase = smem_u32(smem);
    const int tid  = threadIdx.x;
    const int wid  = tid >> 5;
    const int lane = tid & 31;
    const int warp_m = wid & 1;
    const int warp_n = wid >> 1;
    const int gid = lane >> 2;
    const int tg  = lane & 3;

    const int bm = blockIdx.y * 128;
    const int bn = blockIdx.x * 128;
    const int KT = K >> 5;

    const int lrow  = tid >> 1;
    const int lunit = (tid & 1) * 4;
    const float* Ag = A  + (size_t)(bm + lrow) * K + lunit * 4;
    const float* Bg = BT + (size_t)(bn + lrow) * K + lunit * 4;
    uint32_t lsw[4];
    #pragma unroll
    for (int i = 0; i < 4; i++) {
        uint32_t off = lrow * 128 + (lunit + i) * 16;
        lsw[i] = off ^ ((off >> 3) & 0x70);
    }

    uint32_t a_rel[4], a_xr[4];
    #pragma unroll
    for (int i = 0; i < 4; i++) {
        int r = warp_m * 64 + i * 16 + (lane & 7) + ((lane >> 3) & 1) * 8;
        a_rel[i] = r * 128;
        a_xr[i]  = (r & 7) << 4;
    }
    const uint32_t a_kb = ((lane >> 4) & 1) * 16;
    uint32_t b_rel[2], b_xr[2];
    #pragma unroll
    for (int j = 0; j < 2; j++) {
        int r = warp_n * 32 + j * 16 + (lane & 7) + ((lane >> 4) & 1) * 8;
        b_rel[j] = r * 128;
        b_xr[j]  = (r & 7) << 4;
    }
    const uint32_t b_kb = ((lane >> 3) & 1) * 16;

    float acc[4][4][4];
    #pragma unroll
    for (int i = 0; i < 4; i++)
        #pragma unroll
        for (int t = 0; t < 4; t++)
            #pragma unroll
            for (int r = 0; r < 4; r++) acc[i][t][r] = 0.f;

    auto load_tile = [&](int s, int kt) {
        const uint32_t sA = sbase + s * STAGE_BYTES;
        const uint32_t sB = sA + 16384;
        const float* ar = Ag + kt * 32;
        const float* br = Bg + kt * 32;
        #pragma unroll
        for (int i = 0; i < 4; i++) CP_ASYNC16(sA + lsw[i], ar + i * 4);
        #pragma unroll
        for (int i = 0; i < 4; i++) CP_ASYNC16(sB + lsw[i], br + i * 4);
    };

    #pragma unroll
    for (int s = 0; s < STAGES - 1; s++) { load_tile(s, s); CP_COMMIT(); }

    int cur = 0, pfs = STAGES - 1;
    for (int kt = 0; kt < KT; kt++) {
        CP_WAIT(STAGES - 2);
        __syncthreads();   // all warps finished reading the stage prefetch overwrites

        const int pf = kt + STAGES - 1;
        if (pf < KT) load_tile(pfs, pf);
        CP_COMMIT();

        const uint32_t sA = sbase + cur * STAGE_BYTES;
        const uint32_t sB = sA + 16384;

        #pragma unroll
        for (int ks = 0; ks < 4; ks++) {
            const uint32_t kso = ks * 32;
            uint32_t af[4][4];
            #pragma unroll
            for (int i = 0; i < 4; i++) {
                uint32_t addr = sA + ((a_rel[i] + a_kb + kso) ^ a_xr[i]);
                LDMATRIX_X4(af[i][0], af[i][1], af[i][2], af[i][3], addr);
            }
            uint32_t bf[4][2];
            #pragma unroll
            for (int j = 0; j < 2; j++) {
                uint32_t r0, r1, r2, r3;
                uint32_t addr = sB + ((b_rel[j] + b_kb + kso) ^ b_xr[j]);
                LDMATRIX_X4(r0, r1, r2, r3, addr);
                bf[2*j+0][0] = r0; bf[2*j+0][1] = r1;
                bf[2*j+1][0] = r2; bf[2*j+1][1] = r3;
            }
            #pragma unroll
            for (int i = 0; i < 4; i++)
                #pragma unroll
                for (int t = 0; t < 4; t++)
                    MMA_TF32(acc[i][t][0], acc[i][t][1], acc[i][t][2], acc[i][t][3],
                             af[i][0], af[i][1], af[i][2], af[i][3],
                             bf[t][0], bf[t][1]);
        }
        cur++; if (cur == STAGES) cur = 0;
        pfs++; if (pfs == STAGES) pfs = 0;
    }

    #pragma unroll
    for (int i = 0; i < 4; i++) {
        const int row0 = bm + warp_m * 64 + i * 16 + gid;
        #pragma unroll
        for (int t = 0; t < 4; t++) {
            const int col = bn + warp_n * 32 + t * 8 + 2 * tg;
            const float2 bv = *(const float2*)(bias + col);
            float2 v0, v1;
            v0.x = acc[i][t][0] + bv.x; v0.y = acc[i][t][1] + bv.y;
            v1.x = acc[i][t][2] + bv.x; v1.y = acc[i][t][3] + bv.y;
            if (RELU) {
                v0.x = fmaxf(v0.x, 0.f); v0.y = fmaxf(v0.y, 0.f);
                v1.x = fmaxf(v1.x, 0.f); v1.y = fmaxf(v1.y, 0.f);
            }
            if (ROUND) {
                v0.x = roundf_tf32(v0.x); v0.y = roundf_tf32(v0.y);
                v1.x = roundf_tf32(v1.x); v1.y = roundf_tf32(v1.y);
            }
            *(float2*)(C + (size_t)row0 * N + col)       = v0;
            *(float2*)(C + (size_t)(row0 + 8) * N + col) = v1;
        }
    }
}

// ---------------------------------------------------------------------------
// Tensor-core flash attention (tf32 mma). 64 queries x 1 head per block.
// 2 blocks/SM for latency hiding.
// ---------------------------------------------------------------------------
#define ATT_SMEM 65536

__global__ __launch_bounds__(128, 2)
void flash_mma(const float* __restrict__ QKV, const float* __restrict__ VT,
               float* __restrict__ O)
{
    extern __shared__ char smem[];
    const uint32_t sbase = smem_u32(smem);
    const int tid  = threadIdx.x;
    const int wid  = tid >> 5;
    const int lane = tid & 31;
    const int gid  = lane >> 2;
    const int tg   = lane & 3;

    const int bh = blockIdx.y;
    const int b  = bh >> 4;
    const int h  = bh & 15;
    const int q0 = blockIdx.x * 64;

    const float* Qg  = QKV + (size_t)b * SEQ * QLD + h * HD;
    const float* Kg  = Qg + DMODEL;
    const float* VTg = VT + (size_t)bh * HD * SEQ;

    const uint32_t qreg = sbase + 32768;

    const int lrow = tid >> 1;
    const int lu0  = (tid & 1) * 8;
    uint32_t lsw[8];
    #pragma unroll
    for (int i = 0; i < 8; i++) {
        int u = lu0 + i;
        uint32_t off = lrow * 128 + (u & 7) * 16;
        lsw[i] = (u >> 3) * 8192 + (off ^ ((off >> 3) & 0x70));
    }

    uint32_t aq_rel, aq_xr;
    {
        int r = wid * 16 + (lane & 7) + ((lane >> 3) & 1) * 8;
        aq_rel = r * 128;
        aq_xr  = (r & 7) << 4;
    }
    const uint32_t a_kb = ((lane >> 4) & 1) * 16;
    uint32_t b_rel[4], b_xr[4];
    #pragma unroll
    for (int j = 0; j < 4; j++) {
        int r = j * 16 + (lane & 7) + ((lane >> 4) & 1) * 8;
        b_rel[j] = r * 128;
        b_xr[j]  = (r & 7) << 4;
    }
    const uint32_t b_kb = ((lane >> 3) & 1) * 16;

    auto load_KV = [&](int stage, int kt) {
        const uint32_t sK = sbase + stage * 32768;
        const uint32_t sV = sK + 16384;
        const float* kr = Kg  + (size_t)(kt * 64 + lrow) * QLD + lu0 * 4;
        const float* vr = VTg + (size_t)lrow * SEQ + kt * 64 + lu0 * 4;
        #pragma unroll
        for (int i = 0; i < 8; i++) CP_ASYNC16(sK + lsw[i], kr + i * 4);
        #pragma unroll
        for (int i = 0; i < 8; i++) CP_ASYNC16(sV + lsw[i], vr + i * 4);
    };

    {
        const float* qr = Qg + (size_t)(q0 + lrow) * QLD + lu0 * 4;
        #pragma unroll
        for (int i = 0; i < 8; i++) CP_ASYNC16(qreg + lsw[i], qr + i * 4);
        load_KV(0, 0);
        CP_COMMIT();
        CP_WAIT(0);
        __syncthreads();
    }

    uint32_t qf[8][4];
    #pragma unroll
    for (int c = 0; c < 2; c++)
        #pragma unroll
        for (int ks = 0; ks < 4; ks++) {
            uint32_t addr = qreg + c * 8192 + ((aq_rel + a_kb + ks * 32) ^ aq_xr);
            LDMATRIX_X4(qf[c*4+ks][0], qf[c*4+ks][1], qf[c*4+ks][2], qf[c*4+ks][3], addr);
        }
    __syncthreads();

    const int NT = SEQ / 64;
    load_KV(1, 1);
    CP_COMMIT();

    float o[8][4];
    #pragma unroll
    for (int t = 0; t < 8; t++)
        #pragma unroll
        for (int r = 0; r < 4; r++) o[t][r] = 0.f;
    float m0 = -1e30f, m1 = -1e30f, l0 = 0.f, l1 = 0.f;

    for (int kt = 0; kt < NT; kt++) {
        if (kt < NT - 1) { CP_WAIT(1); } else { CP_WAIT(0); }
        __syncthreads();
        const uint32_t sK = sbase + (kt & 1) * 32768;
        const uint32_t sV = sK + 16384;

        // ---- S = Q @ K^T ----
        float s[8][4];
        #pragma unroll
        for (int t = 0; t < 8; t++)
            #pragma unroll
            for (int r = 0; r < 4; r++) s[t][r] = 0.f;

        #pragma unroll
        for (int c = 0; c < 2; c++)
            #pragma unroll
            for (int ks = 0; ks < 4; ks++) {
                uint32_t bf[8][2];
                #pragma unroll
                for (int j = 0; j < 4; j++) {
                    uint32_t r0, r1, r2, r3;
                    uint32_t addr = sK + c * 8192 + ((b_rel[j] + b_kb + ks * 32) ^ b_xr[j]);
                    LDMATRIX_X4(r0, r1, r2, r3, addr);
                    bf[2*j+0][0] = r0; bf[2*j+0][1] = r1;
                    bf[2*j+1][0] = r2; bf[2*j+1][1] = r3;
                }
                const uint32_t* aq = qf[c*4+ks];
                #pragma unroll
                for (int t = 0; t < 8; t++)
                    MMA_TF32(s[t][0], s[t][1], s[t][2], s[t][3],
                             aq[0], aq[1], aq[2], aq[3], bf[t][0], bf[t][1]);
            }

        // ---- online softmax ----
        float tmax0 = -1e30f, tmax1 = -1e30f;
        #pragma unroll
        for (int t = 0; t < 8; t++) {
            s[t][0] *= 0.125f; s[t][1] *= 0.125f; s[t][2] *= 0.125f; s[t][3] *= 0.125f;
            tmax0 = fmaxf(tmax0, fmaxf(s[t][0], s[t][1]));
            tmax1 = fmaxf(tmax1, fmaxf(s[t][2], s[t][3]));
        }
        tmax0 = fmaxf(tmax0, __shfl_xor_sync(0xffffffffu, tmax0, 1));
        tmax0 = fmaxf(tmax0, __shfl_xor_sync(0xffffffffu, tmax0, 2));
        tmax1 = fmaxf(tmax1, __shfl_xor_sync(0xffffffffu, tmax1, 1));
        tmax1 = fmaxf(tmax1, __shfl_xor_sync(0xffffffffu, tmax1, 2));

        const float mnew0 = fmaxf(m0, tmax0);
        const float mnew1 = fmaxf(m1, tmax1);
        const float corr0 = __expf(m0 - mnew0);
        const float corr1 = __expf(m1 - mnew1);

        float rs0 = 0.f, rs1 = 0.f;
        #pragma unroll
        for (int t = 0; t < 8; t++) {
            s[t][0] = __expf(s[t][0] - mnew0);
            s[t][1] = __expf(s[t][1] - mnew0);
            s[t][2] = __expf(s[t][2] - mnew1);
            s[t][3] = __expf(s[t][3] - mnew1);
            rs0 += s[t][0] + s[t][1];
            rs1 += s[t][2] + s[t][3];
        }
        rs0 += __shfl_xor_sync(0xffffffffu, rs0, 1);
        rs0 += __shfl_xor_sync(0xffffffffu, rs0, 2);
        rs1 += __shfl_xor_sync(0xffffffffu, rs1, 1);
        rs1 += __shfl_xor_sync(0xffffffffu, rs1, 2);

        l0 = l0 * corr0 + rs0;
        l1 = l1 * corr1 + rs1;
        #pragma unroll
        for (int t = 0; t < 8; t++) {
            o[t][0] *= corr0; o[t][1] *= corr0;
            o[t][2] *= corr1; o[t][3] *= corr1;
        }
        m0 = mnew0; m1 = mnew1;

        // ---- ctx += P @ V ----
        #pragma unroll
        for (int ks = 0; ks < 8; ks++) {
            const int src0 = tg >> 1, src1 = src0 + 2;
            float v00 = __shfl_sync(0xffffffffu, s[ks][0], src0, 4);
            float v01 = __shfl_sync(0xffffffffu, s[ks][1], src0, 4);
            float v20 = __shfl_sync(0xffffffffu, s[ks][0], src1, 4);
            float v21 = __shfl_sync(0xffffffffu, s[ks][1], src1, 4);
            float v10 = __shfl_sync(0xffffffffu, s[ks][2], src0, 4);
            float v11 = __shfl_sync(0xffffffffu, s[ks][3], src0, 4);
            float v30 = __shfl_sync(0xffffffffu, s[ks][2], src1, 4);
            float v31 = __shfl_sync(0xffffffffu, s[ks][3], src1, 4);
            const bool oddc = (tg & 1);
            uint32_t a0 = to_tf32f(oddc ? v01 : v00);
            uint32_t a1 = to_tf32f(oddc ? v11 : v10);
            uint32_t a2 = to_tf32f(oddc ? v21 : v20);
            uint32_t a3 = to_tf32f(oddc ? v31 : v30);

            uint32_t bf[8][2];
            const uint32_t vbase = sV + (ks >> 2) * 8192;
            const uint32_t kso = (ks & 3) * 32;
            #pragma unroll
            for (int j = 0; j < 4; j++) {
                uint32_t r0, r1, r2, r3;
                uint32_t addr = vbase + ((b_rel[j] + b_kb + kso) ^ b_xr[j]);
                LDMATRIX_X4(r0, r1, r2, r3, addr);
                bf[2*j+0][0] = r0; bf[2*j+0][1] = r1;
                bf[2*j+1][0] = r2; bf[2*j+1][1] = r3;
            }
            #pragma unroll
            for (int t = 0; t < 8; t++)
                MMA_TF32(o[t][0], o[t][1], o[t][2], o[t][3],
                         a0, a1, a2, a3, bf[t][0], bf[t][1]);
        }

        __syncthreads();
        const int pf = kt + 2;
        if (pf < NT) { load_KV(pf & 1, pf); CP_COMMIT(); }
    }

    // ---- write ctx (tf32-rounded: feeds O-projection A operand) ----
    const float inv0 = 1.0f / l0;
    const float inv1 = 1.0f / l1;
    const int qa = q0 + wid * 16 + gid;
    float* orow0 = O + (size_t)(b * SEQ + qa)     * DMODEL + h * HD;
    float* orow1 = O + (size_t)(b * SEQ + qa + 8) * DMODEL + h * HD;
    #pragma unroll
    for (int t = 0; t < 8; t++) {
        const int col = t * 8 + 2 * tg;
        float2 w0, w1;
        w0.x = roundf_tf32(o[t][0] * inv0); w0.y = roundf_tf32(o[t][1] * inv0);
        w1.x = roundf_tf32(o[t][2] * inv1); w1.y = roundf_tf32(o[t][3] * inv1);
        *(float2*)(orow0 + col) = w0;
        *(float2*)(orow1 + col) = w1;
    }
}

// ---------------------------------------------------------------------------
// Transpose helpers (weight transposes round to tf32 — they feed mma B)
// ---------------------------------------------------------------------------
__global__ __launch_bounds__(256)
void transpose_k(const float* __restrict__ in, float* __restrict__ out, int K, int N)
{
    __shared__ float tile[32][33];
    const int k0 = blockIdx.y * 32, n0 = blockIdx.x * 32;
    const int tx = threadIdx.x, ty = threadIdx.y;
    #pragma unroll
    for (int i = ty; i < 32; i += 8)
        tile[i][tx] = in[(size_t)(k0 + i) * N + n0 + tx];
    __syncthreads();
    #pragma unroll
    for (int i = ty; i < 32; i += 8)
        out[(size_t)(n0 + i) * K + k0 + tx] = roundf_tf32(tile[tx][i]);
}

// V slice of fused qkv -> g_vt[bh][64][2048] (input already rounded)
__global__ __launch_bounds__(256)
void transpose_vt(const float* __restrict__ qkv, float* __restrict__ vt)
{
    __shared__ float tile[32][33];
    const int s0 = blockIdx.x * 32;
    const int d0 = blockIdx.y * 32;
    const int bh = blockIdx.z;
    const int b = bh >> 4, h = bh & 15;
    const int tx = threadIdx.x, ty = threadIdx.y;
    const float* in = qkv + (size_t)b * SEQ * QLD + 2 * DMODEL + h * HD;
    float* out = vt + (size_t)bh * HD * SEQ;
    #pragma unroll
    for (int i = ty; i < 32; i += 8)
        tile[i][tx] = in[(size_t)(s0 + i) * QLD + d0 + tx];
    __syncthreads();
    #pragma unroll
    for (int i = ty; i < 32; i += 8)
        out[(size_t)(d0 + i) * SEQ + s0 + tx] = tile[tx][i];
}

__global__ void concat_bias(const float* a, const float* b, const float* c, float* out)
{
    int i = blockIdx.x * 256 + threadIdx.x;
    if (i < DMODEL)            out[i] = a[i];
    else if (i < 2 * DMODEL)   out[i] = b[i - DMODEL];
    else if (i < 3 * DMODEL)   out[i] = c[i - 2 * DMODEL];
}

// Rounded copy: out[i] = tf32(in[i]). Vectorized float4.
__global__ __launch_bounds__(256)
void round_copy(const float* __restrict__ in, float* __restrict__ out, int n4)
{
    int i = blockIdx.x * 256 + threadIdx.x;
    if (i < n4) {
        float4 v = ((const float4*)in)[i];
        v.x = roundf_tf32(v.x); v.y = roundf_tf32(v.y);
        v.z = roundf_tf32(v.z); v.w = roundf_tf32(v.w);
        ((float4*)out)[i] = v;
    }
}

// ---------------------------------------------------------------------------
// Fused residual add + LayerNorm over D=1024. One block (256 threads) per row.
// Optionally writes a tf32-rounded second copy (for downstream GEMM A operand).
// ---------------------------------------------------------------------------
__global__ __launch_bounds__(256)
void add_ln(const float* __restrict__ A, const float* __restrict__ Bv,
            const float* __restrict__ g, const float* __restrict__ be,
            float* __restrict__ out, float* __restrict__ out_r)
{
    const int row = blockIdx.x;
    const int tid = threadIdx.x;

    const float4 a4 = ((const float4*)(A  + (size_t)row * DMODEL))[tid];
    const float4 b4 = ((const float4*)(Bv + (size_t)row * DMODEL))[tid];
    float4 v;
    v.x = a4.x + b4.x; v.y = a4.y + b4.y; v.z = a4.z + b4.z; v.w = a4.w + b4.w;

    float s  = v.x + v.y + v.z + v.w;
    float ss = v.x*v.x + v.y*v.y + v.z*v.z + v.w*v.w;

    #pragma unroll
    for (int ofs = 16; ofs > 0; ofs >>= 1) {
        s  += __shfl_xor_sync(0xFFFFFFFFu, s,  ofs);
        ss += __shfl_xor_sync(0xFFFFFFFFu, ss, ofs);
    }

    __shared__ float shs[8], shss[8];
    const int w = tid >> 5;
    if ((tid & 31) == 0) { shs[w] = s; shss[w] = ss; }
    __syncthreads();
    if (tid < 32) {
        float s2  = (tid < 8) ? shs[tid]  : 0.f;
        float ss2 = (tid < 8) ? shss[tid] : 0.f;
        #pragma unroll
        for (int ofs = 4; ofs > 0; ofs >>= 1) {
            s2  += __shfl_xor_sync(0xFFFFFFFFu, s2,  ofs);
            ss2 += __shfl_xor_sync(0xFFFFFFFFu, ss2, ofs);
        }
        if (tid == 0) { shs[0] = s2; shss[0] = ss2; }
    }
    __syncthreads();

    const float mu  = shs[0]  * (1.f / DMODEL);
    const float var = shss[0] * (1.f / DMODEL) - mu * mu;
    const float inv = rsqrtf(var + 1e-5f);

    const float4 gv = ((const float4*)g)[tid];
    const float4 bb = ((const float4*)be)[tid];
    float4 o;
    o.x = (v.x - mu) * inv * gv.x + bb.x;
    o.y = (v.y - mu) * inv * gv.y + bb.y;
    o.z = (v.z - mu) * inv * gv.z + bb.z;
    o.w = (v.w - mu) * inv * gv.w + bb.w;
    ((float4*)(out + (size_t)row * DMODEL))[tid] = o;
    if (out_r) {
        float4 r;
        r.x = roundf_tf32(o.x); r.y = roundf_tf32(o.y);
        r.z = roundf_tf32(o.z); r.w = roundf_tf32(o.w);
        ((float4*)(out_r + (size_t)row * DMODEL))[tid] = r;
    }
}

// ---------------------------------------------------------------------------
// Launch
// ---------------------------------------------------------------------------
extern "C" void kernel_launch(void* const* d_in, const int* in_sizes, int n_in,
                              void* d_out, int out_size)
{
    const float* src  = (const float*)d_in[0];
    const float* Wq   = (const float*)d_in[1];
    const float* bq   = (const float*)d_in[2];
    const float* Wk   = (const float*)d_in[3];
    const float* bk   = (const float*)d_in[4];
    const float* Wv   = (const float*)d_in[5];
    const float* bv   = (const float*)d_in[6];
    const float* Wo   = (const float*)d_in[7];
    const float* bo   = (const float*)d_in[8];
    const float* W1   = (const float*)d_in[9];
    const float* b1   = (const float*)d_in[10];
    const float* W2   = (const float*)d_in[11];
    const float* b2   = (const float*)d_in[12];
    const float* ln1g = (const float*)d_in[13];
    const float* ln1b = (const float*)d_in[14];
    const float* ln2g = (const float*)d_in[15];
    const float* ln2b = (const float*)d_in[16];
    float* out = (float*)d_out;

    float *pqkv, *pvt, *psrcr, *pxr, *pwqkvT, *pwoT, *pw1T, *pw2T, *pbqkv,
          *pctx, *ptmp, *px, *pff;
    cudaGetSymbolAddress((void**)&pqkv,   g_qkv);
    cudaGetSymbolAddress((void**)&pvt,    g_vt);
    cudaGetSymbolAddress((void**)&psrcr,  g_srcr);
    cudaGetSymbolAddress((void**)&pxr,    g_xr);
    cudaGetSymbolAddress((void**)&pwqkvT, g_wqkvT);
    cudaGetSymbolAddress((void**)&pwoT,   g_woT);
    cudaGetSymbolAddress((void**)&pw1T,   g_w1T);
    cudaGetSymbolAddress((void**)&pw2T,   g_w2T);
    cudaGetSymbolAddress((void**)&pbqkv,  g_bqkv);
    cudaGetSymbolAddress((void**)&pctx,   g_ctx);
    cudaGetSymbolAddress((void**)&ptmp,   g_tmp);
    cudaGetSymbolAddress((void**)&px,     g_x);
    cudaGetSymbolAddress((void**)&pff,    g_ff);

    cudaFuncSetAttribute((const void*)gemm_mma<false,false>, cudaFuncAttributeMaxDynamicSharedMemorySize, SMEM_DYN);
    cudaFuncSetAttribute((const void*)gemm_mma<false,true>,  cudaFuncAttributeMaxDynamicSharedMemorySize, SMEM_DYN);
    cudaFuncSetAttribute((const void*)gemm_mma<true,true>,   cudaFuncAttributeMaxDynamicSharedMemorySize, SMEM_DYN);
    cudaFuncSetAttribute((const void*)flash_mma, cudaFuncAttributeMaxDynamicSharedMemorySize, ATT_SMEM);

    // Pre-rounded inputs + weight transposes (to K-major [N,K], tf32-rounded)
    {
        dim3 blk(32, 8);
        round_copy<<<(NTOK * DMODEL / 4 + 255) / 256, 256>>>(src, psrcr, NTOK * DMODEL / 4);
        transpose_k<<<dim3(32, 32),  blk>>>(Wq, pwqkvT,                       DMODEL, DMODEL);
        transpose_k<<<dim3(32, 32),  blk>>>(Wk, pwqkvT + DMODEL * DMODEL,     DMODEL, DMODEL);
        transpose_k<<<dim3(32, 32),  blk>>>(Wv, pwqkvT + 2 * DMODEL * DMODEL, DMODEL, DMODEL);
        transpose_k<<<dim3(32, 32),  blk>>>(Wo, pwoT,  DMODEL, DMODEL);
        transpose_k<<<dim3(128, 32), blk>>>(W1, pw1T,  DMODEL, DFF);
        transpose_k<<<dim3(32, 128), blk>>>(W2, pw2T,  DFF,    DMODEL);
        concat_bias<<<12, 256>>>(bq, bk, bv, pbqkv);
    }

    // Fused QKV projection (output rounded: feeds attention)
    gemm_mma<false, true><<<dim3(3 * DMODEL / 128, NTOK / 128), 256, SMEM_DYN>>>(
        psrcr, pwqkvT, pbqkv, pqkv, NTOK, 3 * DMODEL, DMODEL);

    // V^T for attention PV operand
    transpose_vt<<<dim3(SEQ / 32, HD / 32, 32), dim3(32, 8)>>>(pqkv, pvt);

    // Tensor-core flash attention (output rounded: feeds O-proj)
    flash_mma<<<dim3(SEQ / 64, 2 * NHEAD), 128, ATT_SMEM>>>(pqkv, pvt, pctx);

    // Output projection (full-precision out: feeds residual) + LN1
    gemm_mma<false, false><<<dim3(DMODEL / 128, NTOK / 128), 256, SMEM_DYN>>>(
        pctx, pwoT, bo, ptmp, NTOK, DMODEL, DMODEL);
    add_ln<<<NTOK, 256>>>(src, ptmp, ln1g, ln1b, px, pxr);

    // FFN
    gemm_mma<true, true><<<dim3(DFF / 128, NTOK / 128), 256, SMEM_DYN>>>(
        pxr, pw1T, b1, pff, NTOK, DFF, DMODEL);
    gemm_mma<false, false><<<dim3(DMODEL / 128, NTOK / 128), 256, SMEM_DYN>>>(
        pff, pw2T, b2, ptmp, NTOK, DMODEL, DFF);
    add_ln<<<NTOK, 256>>>(px, ptmp, ln2g, ln2b, out, (float*)nullptr);
}

// round 10
// speedup vs baseline: 1.3021x; 1.0973x over previous
#include <cuda_runtime.h>
#include <cuda_bf16.h>
#include <math.h>
#include <stdint.h>

// Problem constants
#define NTOK   4096      // B*S = 2*2048
#define DMODEL 1024
#define DFF    4096
#define NHEAD  16
#define HD     64
#define SEQ    2048
#define QLD    (3 * DMODEL)   // fused qkv row stride

// ---------------------------------------------------------------------------
// Scratch (static device globals; no runtime allocation allowed)
// ---------------------------------------------------------------------------
__device__ __align__(16) float g_qkv [NTOK * 3 * DMODEL];    // fused q|k|v (tf32-rounded)
__device__ __align__(16) float g_vt  [32 * HD * SEQ];        // V^T per (b,h): [64][2048]
__device__ __align__(16) float g_srcr[NTOK * DMODEL];        // rounded src (QKV A operand)
__device__ __align__(16) float g_xr  [NTOK * DMODEL];        // rounded LN1 out (FFN1 A)
__device__ __align__(16) float g_wqkvT[3 * DMODEL * DMODEL]; // [3072,1024] K-major, rounded
__device__ __align__(16) float g_woT [DMODEL * DMODEL];
__device__ __align__(16) float g_w1T [DFF * DMODEL];
__device__ __align__(16) float g_w2T [DMODEL * DFF];
__device__ __align__(16) float g_bqkv[3 * DMODEL];
__device__ __align__(16) float g_ctx [NTOK * DMODEL];        // rounded flash output
__device__ __align__(16) float g_tmp [NTOK * DMODEL];
__device__ __align__(16) float g_x   [NTOK * DMODEL];
__device__ __align__(16) float g_ff  [NTOK * DFF];           // rounded FFN1 output

// ---------------------------------------------------------------------------
// PTX helpers (baseline sm_80+ features only — harness targets plain sm_103)
// ---------------------------------------------------------------------------
__device__ __forceinline__ uint32_t smem_u32(const void* p) {
    uint32_t a;
    asm("{ .reg .u64 t; cvta.to.shared.u64 t, %1; cvt.u32.u64 %0, t; }" : "=r"(a) : "l"(p));
    return a;
}
#define CP_ASYNC16(dst, src) \
    asm volatile("cp.async.cg.shared.global [%0], [%1], 16;" :: "r"(dst), "l"(src))
#define CP_COMMIT() asm volatile("cp.async.commit_group;" ::: "memory")
#define CP_WAIT(n)  asm volatile("cp.async.wait_group %0;" :: "n"(n) : "memory")

#define LDMATRIX_X4(r0, r1, r2, r3, addr) \
    asm volatile("ldmatrix.sync.aligned.m8n8.x4.shared.b16 {%0,%1,%2,%3}, [%4];" \
                 : "=r"(r0), "=r"(r1), "=r"(r2), "=r"(r3) : "r"(addr))

__device__ __forceinline__ uint32_t to_tf32f(float f) {
    uint32_t o;
    asm("cvt.rna.tf32.f32 %0, %1;" : "=r"(o) : "f"(f));
    return o;
}
__device__ __forceinline__ float roundf_tf32(float f) {
    return __uint_as_float(to_tf32f(f));
}

#define MMA_TF32(c0, c1, c2, c3, a0, a1, a2, a3, b0, b1) \
    asm volatile("mma.sync.aligned.m16n8k8.row.col.f32.tf32.tf32.f32 " \
                 "{%0,%1,%2,%3}, {%4,%5,%6,%7}, {%8,%9}, {%0,%1,%2,%3};" \
                 : "+f"(c0), "+f"(c1), "+f"(c2), "+f"(c3) \
                 : "r"(a0), "r"(a1), "r"(a2), "r"(a3), "r"(b0), "r"(b1))

// ---------------------------------------------------------------------------
// tf32 tensor-core GEMM (R9-proven):  C = A @ BT^T + bias.
// 128x128 tile, K-chunk 32, 256 threads, 3-stage cp.async, 2 blocks/SM,
// one barrier per iteration. Inputs already tf32-rounded.
// ---------------------------------------------------------------------------
#define STAGES 3
#define STAGE_BYTES (2 * 128 * 32 * 4)
#define SMEM_DYN (STAGES * STAGE_BYTES)     // 96KB -> 2 blocks/SM

template <bool RELU, bool ROUND>
__global__ __launch_bounds__(256, 2)
void gemm_mma(const float* __restrict__ A, const float* __restrict__ BT,
              const float* __restrict__ bias, float* __restrict__ C,
              int M, int N, int K)
{
    extern __shared__ char smem[];
    const uint32_t sbase = smem_u32(smem);
    const int tid  = threadIdx.x;
    const int wid  = tid >> 5;
    const int lane = tid & 31;
    const int warp_m = wid & 1;
    const int warp_n = wid >> 1;
    const int gid = lane >> 2;
    const int tg  = lane & 3;

    const int bm = blockIdx.y * 128;
    const int bn = blockIdx.x * 128;
    const int KT = K >> 5;

    const int lrow  = tid >> 1;
    const int lunit = (tid & 1) * 4;
    const float* Ag = A  + (size_t)(bm + lrow) * K + lunit * 4;
    const float* Bg = BT + (size_t)(bn + lrow) * K + lunit * 4;
    uint32_t lsw[4];
    #pragma unroll
    for (int i = 0; i < 4; i++) {
        uint32_t off = lrow * 128 + (lunit + i) * 16;
        lsw[i] = off ^ ((off >> 3) & 0x70);
    }

    uint32_t a_rel[4], a_xr[4];
    #pragma unroll
    for (int i = 0; i < 4; i++) {
        int r = warp_m * 64 + i * 16 + (lane & 7) + ((lane >> 3) & 1) * 8;
        a_rel[i] = r * 128;
        a_xr[i]  = (r & 7) << 4;
    }
    const uint32_t a_kb = ((lane >> 4) & 1) * 16;
    uint32_t b_rel[2], b_xr[2];
    #pragma unroll
    for (int j = 0; j < 2; j++) {
        int r = warp_n * 32 + j * 16 + (lane & 7) + ((lane >> 4) & 1) * 8;
        b_rel[j] = r * 128;
        b_xr[j]  = (r & 7) << 4;
    }
    const uint32_t b_kb = ((lane >> 3) & 1) * 16;

    float acc[4][4][4];
    #pragma unroll
    for (int i = 0; i < 4; i++)
        #pragma unroll
        for (int t = 0; t < 4; t++)
            #pragma unroll
            for (int r = 0; r < 4; r++) acc[i][t][r] = 0.f;

    auto load_tile = [&](int s, int kt) {
        const uint32_t sA = sbase + s * STAGE_BYTES;
        const uint32_t sB = sA + 16384;
        const float* ar = Ag + kt * 32;
        const float* br = Bg + kt * 32;
        #pragma unroll
        for (int i = 0; i < 4; i++) CP_ASYNC16(sA + lsw[i], ar + i * 4);
        #pragma unroll
        for (int i = 0; i < 4; i++) CP_ASYNC16(sB + lsw[i], br + i * 4);
    };

    #pragma unroll
    for (int s = 0; s < STAGES - 1; s++) { load_tile(s, s); CP_COMMIT(); }

    int cur = 0, pfs = STAGES - 1;
    for (int kt = 0; kt < KT; kt++) {
        CP_WAIT(STAGES - 2);
        __syncthreads();

        const int pf = kt + STAGES - 1;
        if (pf < KT) load_tile(pfs, pf);
        CP_COMMIT();

        const uint32_t sA = sbase + cur * STAGE_BYTES;
        const uint32_t sB = sA + 16384;

        #pragma unroll
        for (int ks = 0; ks < 4; ks++) {
            const uint32_t kso = ks * 32;
            uint32_t af[4][4];
            #pragma unroll
            for (int i = 0; i < 4; i++) {
                uint32_t addr = sA + ((a_rel[i] + a_kb + kso) ^ a_xr[i]);
                LDMATRIX_X4(af[i][0], af[i][1], af[i][2], af[i][3], addr);
            }
            uint32_t bf[4][2];
            #pragma unroll
            for (int j = 0; j < 2; j++) {
                uint32_t r0, r1, r2, r3;
                uint32_t addr = sB + ((b_rel[j] + b_kb + kso) ^ b_xr[j]);
                LDMATRIX_X4(r0, r1, r2, r3, addr);
                bf[2*j+0][0] = r0; bf[2*j+0][1] = r1;
                bf[2*j+1][0] = r2; bf[2*j+1][1] = r3;
            }
            #pragma unroll
            for (int i = 0; i < 4; i++)
                #pragma unroll
                for (int t = 0; t < 4; t++)
                    MMA_TF32(acc[i][t][0], acc[i][t][1], acc[i][t][2], acc[i][t][3],
                             af[i][0], af[i][1], af[i][2], af[i][3],
                             bf[t][0], bf[t][1]);
        }
        cur++; if (cur == STAGES) cur = 0;
        pfs++; if (pfs == STAGES) pfs = 0;
    }

    #pragma unroll
    for (int i = 0; i < 4; i++) {
        const int row0 = bm + warp_m * 64 + i * 16 + gid;
        #pragma unroll
        for (int t = 0; t < 4; t++) {
            const int col = bn + warp_n * 32 + t * 8 + 2 * tg;
            const float2 bv = *(const float2*)(bias + col);
            float2 v0, v1;
            v0.x = acc[i][t][0] + bv.x; v0.y = acc[i][t][1] + bv.y;
            v1.x = acc[i][t][2] + bv.x; v1.y = acc[i][t][3] + bv.y;
            if (RELU) {
                v0.x = fmaxf(v0.x, 0.f); v0.y = fmaxf(v0.y, 0.f);
                v1.x = fmaxf(v1.x, 0.f); v1.y = fmaxf(v1.y, 0.f);
            }
            if (ROUND) {
                v0.x = roundf_tf32(v0.x); v0.y = roundf_tf32(v0.y);
                v1.x = roundf_tf32(v1.x); v1.y = roundf_tf32(v1.y);
            }
            *(float2*)(C + (size_t)row0 * N + col)       = v0;
            *(float2*)(C + (size_t)(row0 + 8) * N + col) = v1;
        }
    }
}

// ---------------------------------------------------------------------------
// Tensor-core flash attention (tf32 mma). 128 queries x 1 head per block,
// 8 warps (16 q-rows each). K-tile = 64 keys, double-buffered cp.async.
// Halves K/V L2 traffic vs 64-query blocks.
// ---------------------------------------------------------------------------
#define ATT_SMEM 65536   // 2 stages x (16KB K + 16KB VT); Q staged in stage 1

__global__ __launch_bounds__(256, 1)
void flash_mma(const float* __restrict__ QKV, const float* __restrict__ VT,
               float* __restrict__ O)
{
    extern __shared__ char smem[];
    const uint32_t sbase = smem_u32(smem);
    const int tid  = threadIdx.x;
    const int wid  = tid >> 5;          // 0..7, one m16 q-tile each
    const int lane = tid & 31;
    const int gid  = lane >> 2;
    const int tg   = lane & 3;

    const int bh = blockIdx.y;
    const int b  = bh >> 4;
    const int h  = bh & 15;
    const int q0 = blockIdx.x * 128;

    const float* Qg  = QKV + (size_t)b * SEQ * QLD + h * HD;
    const float* Kg  = Qg + DMODEL;
    const float* VTg = VT + (size_t)bh * HD * SEQ;

    const uint32_t qreg = sbase + 32768;   // stage-1 (K+V) region: 32KB for 128-row Q

    // ---- Q staging map: 128 rows x 16 units; thread -> row tid>>1, 8 units ----
    const int qrow = tid >> 1;
    const int qu0  = (tid & 1) * 8;
    uint32_t qsw[8];
    #pragma unroll
    for (int i = 0; i < 8; i++) {
        int u = qu0 + i;                                  // 0..15
        uint32_t off = qrow * 128 + (u & 7) * 16;
        qsw[i] = (u >> 3) * 16384 + (off ^ ((off >> 3) & 0x70));
    }

    // ---- K/V tile map: 64 rows x 16 units each; thread -> row tid>>2, 4 units ----
    const int krow = tid >> 2;
    const int ku0  = (tid & 3) * 4;
    uint32_t kvsw[4];
    #pragma unroll
    for (int i = 0; i < 4; i++) {
        int u = ku0 + i;                                  // 0..15
        uint32_t off = krow * 128 + (u & 7) * 16;
        kvsw[i] = (u >> 3) * 8192 + (off ^ ((off >> 3) & 0x70));
    }

    // ---- fragment addressing ----
    uint32_t aq_rel, aq_xr;
    {
        int r = wid * 16 + (lane & 7) + ((lane >> 3) & 1) * 8;   // 0..127
        aq_rel = r * 128;
        aq_xr  = (r & 7) << 4;
    }
    const uint32_t a_kb = ((lane >> 4) & 1) * 16;
    uint32_t b_rel[4], b_xr[4];
    #pragma unroll
    for (int j = 0; j < 4; j++) {
        int r = j * 16 + (lane & 7) + ((lane >> 4) & 1) * 8;
        b_rel[j] = r * 128;
        b_xr[j]  = (r & 7) << 4;
    }
    const uint32_t b_kb = ((lane >> 3) & 1) * 16;

    auto load_KV = [&](int stage, int kt) {
        const uint32_t sK = sbase + stage * 32768;
        const uint32_t sV = sK + 16384;
        const float* kr = Kg  + (size_t)(kt * 64 + krow) * QLD + ku0 * 4;
        const float* vr = VTg + (size_t)krow * SEQ + kt * 64 + ku0 * 4;
        #pragma unroll
        for (int i = 0; i < 4; i++) CP_ASYNC16(sK + kvsw[i], kr + i * 4);
        #pragma unroll
        for (int i = 0; i < 4; i++) CP_ASYNC16(sV + kvsw[i], vr + i * 4);
    };

    // ---- prologue: stage Q (into stage-1 region) + KV tile 0 ----
    {
        const float* qr = Qg + (size_t)(q0 + qrow) * QLD + qu0 * 4;
        #pragma unroll
        for (int i = 0; i < 8; i++) CP_ASYNC16(qreg + qsw[i], qr + i * 4);
        load_KV(0, 0);
        CP_COMMIT();
        CP_WAIT(0);
        __syncthreads();
    }

    // extract Q fragments (8 ksteps over 64 dims)
    uint32_t qf[8][4];
    #pragma unroll
    for (int c = 0; c < 2; c++)
        #pragma unroll
        for (int ks = 0; ks < 4; ks++) {
            uint32_t addr = qreg + c * 16384 + ((aq_rel + a_kb + ks * 32) ^ aq_xr);
            LDMATRIX_X4(qf[c*4+ks][0], qf[c*4+ks][1], qf[c*4+ks][2], qf[c*4+ks][3], addr);
        }
    __syncthreads();

    const int NT = SEQ / 64;
    load_KV(1, 1);
    CP_COMMIT();

    float o[8][4];
    #pragma unroll
    for (int t = 0; t < 8; t++)
        #pragma unroll
        for (int r = 0; r < 4; r++) o[t][r] = 0.f;
    float m0 = -1e30f, m1 = -1e30f, l0 = 0.f, l1 = 0.f;

    for (int kt = 0; kt < NT; kt++) {
        if (kt < NT - 1) { CP_WAIT(1); } else { CP_WAIT(0); }
        __syncthreads();
        const uint32_t sK = sbase + (kt & 1) * 32768;
        const uint32_t sV = sK + 16384;

        // ---- S = Q @ K^T ----
        float s[8][4];
        #pragma unroll
        for (int t = 0; t < 8; t++)
            #pragma unroll
            for (int r = 0; r < 4; r++) s[t][r] = 0.f;

        #pragma unroll
        for (int c = 0; c < 2; c++)
            #pragma unroll
            for (int ks = 0; ks < 4; ks++) {
                uint32_t bf[8][2];
                #pragma unroll
                for (int j = 0; j < 4; j++) {
                    uint32_t r0, r1, r2, r3;
                    uint32_t addr = sK + c * 8192 + ((b_rel[j] + b_kb + ks * 32) ^ b_xr[j]);
                    LDMATRIX_X4(r0, r1, r2, r3, addr);
                    bf[2*j+0][0] = r0; bf[2*j+0][1] = r1;
                    bf[2*j+1][0] = r2; bf[2*j+1][1] = r3;
                }
                const uint32_t* aq = qf[c*4+ks];
                #pragma unroll
                for (int t = 0; t < 8; t++)
                    MMA_TF32(s[t][0], s[t][1], s[t][2], s[t][3],
                             aq[0], aq[1], aq[2], aq[3], bf[t][0], bf[t][1]);
            }

        // ---- online softmax ----
        float tmax0 = -1e30f, tmax1 = -1e30f;
        #pragma unroll
        for (int t = 0; t < 8; t++) {
            s[t][0] *= 0.125f; s[t][1] *= 0.125f; s[t][2] *= 0.125f; s[t][3] *= 0.125f;
            tmax0 = fmaxf(tmax0, fmaxf(s[t][0], s[t][1]));
            tmax1 = fmaxf(tmax1, fmaxf(s[t][2], s[t][3]));
        }
        tmax0 = fmaxf(tmax0, __shfl_xor_sync(0xffffffffu, tmax0, 1));
        tmax0 = fmaxf(tmax0, __shfl_xor_sync(0xffffffffu, tmax0, 2));
        tmax1 = fmaxf(tmax1, __shfl_xor_sync(0xffffffffu, tmax1, 1));
        tmax1 = fmaxf(tmax1, __shfl_xor_sync(0xffffffffu, tmax1, 2));

        const float mnew0 = fmaxf(m0, tmax0);
        const float mnew1 = fmaxf(m1, tmax1);
        const float corr0 = __expf(m0 - mnew0);
        const float corr1 = __expf(m1 - mnew1);

        float rs0 = 0.f, rs1 = 0.f;
        #pragma unroll
        for (int t = 0; t < 8; t++) {
            s[t][0] = __expf(s[t][0] - mnew0);
            s[t][1] = __expf(s[t][1] - mnew0);
            s[t][2] = __expf(s[t][2] - mnew1);
            s[t][3] = __expf(s[t][3] - mnew1);
            rs0 += s[t][0] + s[t][1];
            rs1 += s[t][2] + s[t][3];
        }
        rs0 += __shfl_xor_sync(0xffffffffu, rs0, 1);
        rs0 += __shfl_xor_sync(0xffffffffu, rs0, 2);
        rs1 += __shfl_xor_sync(0xffffffffu, rs1, 1);
        rs1 += __shfl_xor_sync(0xffffffffu, rs1, 2);

        l0 = l0 * corr0 + rs0;
        l1 = l1 * corr1 + rs1;
        #pragma unroll
        for (int t = 0; t < 8; t++) {
            o[t][0] *= corr0; o[t][1] *= corr0;
            o[t][2] *= corr1; o[t][3] *= corr1;
        }
        m0 = mnew0; m1 = mnew1;

        // ---- ctx += P @ V ----
        #pragma unroll
        for (int ks = 0; ks < 8; ks++) {
            const int src0 = tg >> 1, src1 = src0 + 2;
            float v00 = __shfl_sync(0xffffffffu, s[ks][0], src0, 4);
            float v01 = __shfl_sync(0xffffffffu, s[ks][1], src0, 4);
            float v20 = __shfl_sync(0xffffffffu, s[ks][0], src1, 4);
            float v21 = __shfl_sync(0xffffffffu, s[ks][1], src1, 4);
            float v10 = __shfl_sync(0xffffffffu, s[ks][2], src0, 4);
            float v11 = __shfl_sync(0xffffffffu, s[ks][3], src0, 4);
            float v30 = __shfl_sync(0xffffffffu, s[ks][2], src1, 4);
            float v31 = __shfl_sync(0xffffffffu, s[ks][3], src1, 4);
            const bool oddc = (tg & 1);
            uint32_t a0 = to_tf32f(oddc ? v01 : v00);
            uint32_t a1 = to_tf32f(oddc ? v11 : v10);
            uint32_t a2 = to_tf32f(oddc ? v21 : v20);
            uint32_t a3 = to_tf32f(oddc ? v31 : v30);

            uint32_t bf[8][2];
            const uint32_t vbase = sV + (ks >> 2) * 8192;
            const uint32_t kso = (ks & 3) * 32;
            #pragma unroll
            for (int j = 0; j < 4; j++) {
                uint32_t r0, r1, r2, r3;
                uint32_t addr = vbase + ((b_rel[j] + b_kb + kso) ^ b_xr[j]);
                LDMATRIX_X4(r0, r1, r2, r3, addr);
                bf[2*j+0][0] = r0; bf[2*j+0][1] = r1;
                bf[2*j+1][0] = r2; bf[2*j+1][1] = r3;
            }
            #pragma unroll
            for (int t = 0; t < 8; t++)
                MMA_TF32(o[t][0], o[t][1], o[t][2], o[t][3],
                         a0, a1, a2, a3, bf[t][0], bf[t][1]);
        }

        __syncthreads();
        const int pf = kt + 2;
        if (pf < NT) { load_KV(pf & 1, pf); CP_COMMIT(); }
    }

    // ---- write ctx (tf32-rounded: feeds O-projection A operand) ----
    const float inv0 = 1.0f / l0;
    const float inv1 = 1.0f / l1;
    const int qa = q0 + wid * 16 + gid;
    float* orow0 = O + (size_t)(b * SEQ + qa)     * DMODEL + h * HD;
    float* orow1 = O + (size_t)(b * SEQ + qa + 8) * DMODEL + h * HD;
    #pragma unroll
    for (int t = 0; t < 8; t++) {
        const int col = t * 8 + 2 * tg;
        float2 w0, w1;
        w0.x = roundf_tf32(o[t][0] * inv0); w0.y = roundf_tf32(o[t][1] * inv0);
        w1.x = roundf_tf32(o[t][2] * inv1); w1.y = roundf_tf32(o[t][3] * inv1);
        *(float2*)(orow0 + col) = w0;
        *(float2*)(orow1 + col) = w1;
    }
}

// ---------------------------------------------------------------------------
// Transpose helpers (weight transposes round to tf32 — they feed mma B)
// ---------------------------------------------------------------------------
__global__ __launch_bounds__(256)
void transpose_k(const float* __restrict__ in, float* __restrict__ out, int K, int N)
{
    __shared__ float tile[32][33];
    const int k0 = blockIdx.y * 32, n0 = blockIdx.x * 32;
    const int tx = threadIdx.x, ty = threadIdx.y;
    #pragma unroll
    for (int i = ty; i < 32; i += 8)
        tile[i][tx] = in[(size_t)(k0 + i) * N + n0 + tx];
    __syncthreads();
    #pragma unroll
    for (int i = ty; i < 32; i += 8)
        out[(size_t)(n0 + i) * K + k0 + tx] = roundf_tf32(tile[tx][i]);
}

// V slice of fused qkv -> g_vt[bh][64][2048] (input already rounded)
__global__ __launch_bounds__(256)
void transpose_vt(const float* __restrict__ qkv, float* __restrict__ vt)
{
    __shared__ float tile[32][33];
    const int s0 = blockIdx.x * 32;
    const int d0 = blockIdx.y * 32;
    const int bh = blockIdx.z;
    const int b = bh >> 4, h = bh & 15;
    const int tx = threadIdx.x, ty = threadIdx.y;
    const float* in = qkv + (size_t)b * SEQ * QLD + 2 * DMODEL + h * HD;
    float* out = vt + (size_t)bh * HD * SEQ;
    #pragma unroll
    for (int i = ty; i < 32; i += 8)
        tile[i][tx] = in[(size_t)(s0 + i) * QLD + d0 + tx];
    __syncthreads();
    #pragma unroll
    for (int i = ty; i < 32; i += 8)
        out[(size_t)(d0 + i) * SEQ + s0 + tx] = tile[tx][i];
}

__global__ void concat_bias(const float* a, const float* b, const float* c, float* out)
{
    int i = blockIdx.x * 256 + threadIdx.x;
    if (i < DMODEL)            out[i] = a[i];
    else if (i < 2 * DMODEL)   out[i] = b[i - DMODEL];
    else if (i < 3 * DMODEL)   out[i] = c[i - 2 * DMODEL];
}

// Rounded copy: out[i] = tf32(in[i]). Vectorized float4.
__global__ __launch_bounds__(256)
void round_copy(const float* __restrict__ in, float* __restrict__ out, int n4)
{
    int i = blockIdx.x * 256 + threadIdx.x;
    if (i < n4) {
        float4 v = ((const float4*)in)[i];
        v.x = roundf_tf32(v.x); v.y = roundf_tf32(v.y);
        v.z = roundf_tf32(v.z); v.w = roundf_tf32(v.w);
        ((float4*)out)[i] = v;
    }
}

// ---------------------------------------------------------------------------
// Fused residual add + LayerNorm over D=1024. One block (256 threads) per row.
// Optionally writes a tf32-rounded second copy (for downstream GEMM A operand).
// ---------------------------------------------------------------------------
__global__ __launch_bounds__(256)
void add_ln(const float* __restrict__ A, const float* __restrict__ Bv,
            const float* __restrict__ g, const float* __restrict__ be,
            float* __restrict__ out, float* __restrict__ out_r)
{
    const int row = blockIdx.x;
    const int tid = threadIdx.x;

    const float4 a4 = ((const float4*)(A  + (size_t)row * DMODEL))[tid];
    const float4 b4 = ((const float4*)(Bv + (size_t)row * DMODEL))[tid];
    float4 v;
    v.x = a4.x + b4.x; v.y = a4.y + b4.y; v.z = a4.z + b4.z; v.w = a4.w + b4.w;

    float s  = v.x + v.y + v.z + v.w;
    float ss = v.x*v.x + v.y*v.y + v.z*v.z + v.w*v.w;

    #pragma unroll
    for (int ofs = 16; ofs > 0; ofs >>= 1) {
        s  += __shfl_xor_sync(0xFFFFFFFFu, s,  ofs);
        ss += __shfl_xor_sync(0xFFFFFFFFu, ss, ofs);
    }

    __shared__ float shs[8], shss[8];
    const int w = tid >> 5;
    if ((tid & 31) == 0) { shs[w] = s; shss[w] = ss; }
    __syncthreads();
    if (tid < 32) {
        float s2  = (tid < 8) ? shs[tid]  : 0.f;
        float ss2 = (tid < 8) ? shss[tid] : 0.f;
        #pragma unroll
        for (int ofs = 4; ofs > 0; ofs >>= 1) {
            s2  += __shfl_xor_sync(0xFFFFFFFFu, s2,  ofs);
            ss2 += __shfl_xor_sync(0xFFFFFFFFu, ss2, ofs);
        }
        if (tid == 0) { shs[0] = s2; shss[0] = ss2; }
    }
    __syncthreads();

    const float mu  = shs[0]  * (1.f / DMODEL);
    const float var = shss[0] * (1.f / DMODEL) - mu * mu;
    const float inv = rsqrtf(var + 1e-5f);

    const float4 gv = ((const float4*)g)[tid];
    const float4 bb = ((const float4*)be)[tid];
    float4 o;
    o.x = (v.x - mu) * inv * gv.x + bb.x;
    o.y = (v.y - mu) * inv * gv.y + bb.y;
    o.z = (v.z - mu) * inv * gv.z + bb.z;
    o.w = (v.w - mu) * inv * gv.w + bb.w;
    ((float4*)(out + (size_t)row * DMODEL))[tid] = o;
    if (out_r) {
        float4 r;
        r.x = roundf_tf32(o.x); r.y = roundf_tf32(o.y);
        r.z = roundf_tf32(o.z); r.w = roundf_tf32(o.w);
        ((float4*)(out_r + (size_t)row * DMODEL))[tid] = r;
    }
}

// ---------------------------------------------------------------------------
// Launch
// ---------------------------------------------------------------------------
extern "C" void kernel_launch(void* const* d_in, const int* in_sizes, int n_in,
                              void* d_out, int out_size)
{
    const float* src  = (const float*)d_in[0];
    const float* Wq   = (const float*)d_in[1];
    const float* bq   = (const float*)d_in[2];
    const float* Wk   = (const float*)d_in[3];
    const float* bk   = (const float*)d_in[4];
    const float* Wv   = (const float*)d_in[5];
    const float* bv   = (const float*)d_in[6];
    const float* Wo   = (const float*)d_in[7];
    const float* bo   = (const float*)d_in[8];
    const float* W1   = (const float*)d_in[9];
    const float* b1   = (const float*)d_in[10];
    const float* W2   = (const float*)d_in[11];
    const float* b2   = (const float*)d_in[12];
    const float* ln1g = (const float*)d_in[13];
    const float* ln1b = (const float*)d_in[14];
    const float* ln2g = (const float*)d_in[15];
    const float* ln2b = (const float*)d_in[16];
    float* out = (float*)d_out;

    float *pqkv, *pvt, *psrcr, *pxr, *pwqkvT, *pwoT, *pw1T, *pw2T, *pbqkv,
          *pctx, *ptmp, *px, *pff;
    cudaGetSymbolAddress((void**)&pqkv,   g_qkv);
    cudaGetSymbolAddress((void**)&pvt,    g_vt);
    cudaGetSymbolAddress((void**)&psrcr,  g_srcr);
    cudaGetSymbolAddress((void**)&pxr,    g_xr);
    cudaGetSymbolAddress((void**)&pwqkvT, g_wqkvT);
    cudaGetSymbolAddress((void**)&pwoT,   g_woT);
    cudaGetSymbolAddress((void**)&pw1T,   g_w1T);
    cudaGetSymbolAddress((void**)&pw2T,   g_w2T);
    cudaGetSymbolAddress((void**)&pbqkv,  g_bqkv);
    cudaGetSymbolAddress((void**)&pctx,   g_ctx);
    cudaGetSymbolAddress((void**)&ptmp,   g_tmp);
    cudaGetSymbolAddress((void**)&px,     g_x);
    cudaGetSymbolAddress((void**)&pff,    g_ff);

    cudaFuncSetAttribute((const void*)gemm_mma<false,false>, cudaFuncAttributeMaxDynamicSharedMemorySize, SMEM_DYN);
    cudaFuncSetAttribute((const void*)gemm_mma<false,true>,  cudaFuncAttributeMaxDynamicSharedMemorySize, SMEM_DYN);
    cudaFuncSetAttribute((const void*)gemm_mma<true,true>,   cudaFuncAttributeMaxDynamicSharedMemorySize, SMEM_DYN);
    cudaFuncSetAttribute((const void*)flash_mma, cudaFuncAttributeMaxDynamicSharedMemorySize, ATT_SMEM);

    // Pre-rounded inputs + weight transposes (to K-major [N,K], tf32-rounded)
    {
        dim3 blk(32, 8);
        round_copy<<<(NTOK * DMODEL / 4 + 255) / 256, 256>>>(src, psrcr, NTOK * DMODEL / 4);
        transpose_k<<<dim3(32, 32),  blk>>>(Wq, pwqkvT,                       DMODEL, DMODEL);
        transpose_k<<<dim3(32, 32),  blk>>>(Wk, pwqkvT + DMODEL * DMODEL,     DMODEL, DMODEL);
        transpose_k<<<dim3(32, 32),  blk>>>(Wv, pwqkvT + 2 * DMODEL * DMODEL, DMODEL, DMODEL);
        transpose_k<<<dim3(32, 32),  blk>>>(Wo, pwoT,  DMODEL, DMODEL);
        transpose_k<<<dim3(128, 32), blk>>>(W1, pw1T,  DMODEL, DFF);
        transpose_k<<<dim3(32, 128), blk>>>(W2, pw2T,  DFF,    DMODEL);
        concat_bias<<<12, 256>>>(bq, bk, bv, pbqkv);
    }

    // Fused QKV projection (output rounded: feeds attention)
    gemm_mma<false, true><<<dim3(3 * DMODEL / 128, NTOK / 128), 256, SMEM_DYN>>>(
        psrcr, pwqkvT, pbqkv, pqkv, NTOK, 3 * DMODEL, DMODEL);

    // V^T for attention PV operand
    transpose_vt<<<dim3(SEQ / 32, HD / 32, 32), dim3(32, 8)>>>(pqkv, pvt);

    // Tensor-core flash attention (128 queries/block)
    flash_mma<<<dim3(SEQ / 128, 2 * NHEAD), 256, ATT_SMEM>>>(pqkv, pvt, pctx);

    // Output projection (full-precision out: feeds residual) + LN1
    gemm_mma<false, false><<<dim3(DMODEL / 128, NTOK / 128), 256, SMEM_DYN>>>(
        pctx, pwoT, bo, ptmp, NTOK, DMODEL, DMODEL);
    add_ln<<<NTOK, 256>>>(src, ptmp, ln1g, ln1b, px, pxr);

    // FFN
    gemm_mma<true, true><<<dim3(DFF / 128, NTOK / 128), 256, SMEM_DYN>>>(
        pxr, pw1T, b1, pff, NTOK, DFF, DMODEL);
    gemm_mma<false, false><<<dim3(DMODEL / 128, NTOK / 128), 256, SMEM_DYN>>>(
        pff, pw2T, b2, ptmp, NTOK, DMODEL, DFF);
    add_ln<<<NTOK, 256>>>(px, ptmp, ln2g, ln2b, out, (float*)nullptr);
}

// round 11
// speedup vs baseline: 1.9079x; 1.4653x over previous
#include <cuda_runtime.h>
#include <cuda_fp16.h>
#include <math.h>
#include <stdint.h>

// Problem constants
#define NTOK   4096      // B*S = 2*2048
#define DMODEL 1024
#define DFF    4096
#define NHEAD  16
#define HD     64
#define SEQ    2048
#define QLD    (3 * DMODEL)   // fused qkv row stride

// ---------------------------------------------------------------------------
// Scratch (static device globals; no runtime allocation allowed)
// ---------------------------------------------------------------------------
__device__ __align__(16) float  g_qkv [NTOK * 3 * DMODEL];    // fp32, tf32-rounded (flash in)
__device__ __align__(16) float  g_vt  [32 * HD * SEQ];        // V^T per (b,h) fp32
__device__ __align__(16) __half g_srcr[NTOK * DMODEL];        // half src (QKV A)
__device__ __align__(16) __half g_xr  [NTOK * DMODEL];        // half LN1 out (FFN1 A)
__device__ __align__(16) __half g_wqkvT[3 * DMODEL * DMODEL]; // [3072,1024] K-major half
__device__ __align__(16) __half g_woT [DMODEL * DMODEL];
__device__ __align__(16) __half g_w1T [DFF * DMODEL];
__device__ __align__(16) __half g_w2T [DMODEL * DFF];
__device__ __align__(16) float  g_bqkv[3 * DMODEL];
__device__ __align__(16) __half g_ctx [NTOK * DMODEL];        // half flash output (O-proj A)
__device__ __align__(16) float  g_tmp [NTOK * DMODEL];
__device__ __align__(16) float  g_x   [NTOK * DMODEL];
__device__ __align__(16) __half g_ff  [NTOK * DFF];           // half FFN1 output (FFN2 A)

// ---------------------------------------------------------------------------
// PTX helpers
// ---------------------------------------------------------------------------
__device__ __forceinline__ uint32_t smem_u32(const void* p) {
    uint32_t a;
    asm("{ .reg .u64 t; cvta.to.shared.u64 t, %1; cvt.u32.u64 %0, t; }" : "=r"(a) : "l"(p));
    return a;
}
#define CP_ASYNC16(dst, src) \
    asm volatile("cp.async.cg.shared.global [%0], [%1], 16;" :: "r"(dst), "l"(src))
#define CP_COMMIT() asm volatile("cp.async.commit_group;" ::: "memory")
#define CP_WAIT(n)  asm volatile("cp.async.wait_group %0;" :: "n"(n) : "memory")

#define LDMATRIX_X4(r0, r1, r2, r3, addr) \
    asm volatile("ldmatrix.sync.aligned.m8n8.x4.shared.b16 {%0,%1,%2,%3}, [%4];" \
                 : "=r"(r0), "=r"(r1), "=r"(r2), "=r"(r3) : "r"(addr))

__device__ __forceinline__ uint32_t to_tf32f(float f) {
    uint32_t o;
    asm("cvt.rna.tf32.f32 %0, %1;" : "=r"(o) : "f"(f));
    return o;
}
__device__ __forceinline__ float roundf_tf32(float f) {
    return __uint_as_float(to_tf32f(f));
}

#define MMA_TF32(c0, c1, c2, c3, a0, a1, a2, a3, b0, b1) \
    asm volatile("mma.sync.aligned.m16n8k8.row.col.f32.tf32.tf32.f32 " \
                 "{%0,%1,%2,%3}, {%4,%5,%6,%7}, {%8,%9}, {%0,%1,%2,%3};" \
                 : "+f"(c0), "+f"(c1), "+f"(c2), "+f"(c3) \
                 : "r"(a0), "r"(a1), "r"(a2), "r"(a3), "r"(b0), "r"(b1))

#define MMA_F16(c0, c1, c2, c3, a0, a1, a2, a3, b0, b1) \
    asm volatile("mma.sync.aligned.m16n8k16.row.col.f32.f16.f16.f32 " \
                 "{%0,%1,%2,%3}, {%4,%5,%6,%7}, {%8,%9}, {%0,%1,%2,%3};" \
                 : "+f"(c0), "+f"(c1), "+f"(c2), "+f"(c3) \
                 : "r"(a0), "r"(a1), "r"(a2), "r"(a3), "r"(b0), "r"(b1))

// ---------------------------------------------------------------------------
// fp16 tensor-core GEMM:  C = A @ BT^T + bias.  A,BT half (K-major).
// 128x128 tile, K-chunk 64 halves (=128B/row, same smem layout as tf32 ver),
// 256 threads, 3-stage cp.async, 2 blocks/SM, one barrier per iteration.
// OUTM: 0 = fp32, 1 = fp32 tf32-rounded, 2 = half.
// ---------------------------------------------------------------------------
#define STAGES 3
#define STAGE_BYTES (2 * 128 * 128)          // A 16KB + B 16KB
#define SMEM_DYN (STAGES * STAGE_BYTES)      // 96KB -> 2 blocks/SM

template <bool RELU, int OUTM>
__global__ __launch_bounds__(256, 2)
void gemm_mma(const __half* __restrict__ A, const __half* __restrict__ BT,
              const float* __restrict__ bias, void* __restrict__ Cv,
              int M, int N, int K)
{
    extern __shared__ char smem[];
    const uint32_t sbase = smem_u32(smem);
    const int tid  = threadIdx.x;
    const int wid  = tid >> 5;
    const int lane = tid & 31;
    const int warp_m = wid & 1;
    const int warp_n = wid >> 1;
    const int gid = lane >> 2;
    const int tg  = lane & 3;

    const int bm = blockIdx.y * 128;
    const int bn = blockIdx.x * 128;
    const int KT = K >> 6;                   // 64-half chunks

    // loads: 128 rows x 8 16B-units; thread -> row tid>>1, 4 units
    const int lrow  = tid >> 1;
    const int lunit = (tid & 1) * 4;
    const __half* Ag = A  + (size_t)(bm + lrow) * K + lunit * 8;
    const __half* Bg = BT + (size_t)(bn + lrow) * K + lunit * 8;
    uint32_t lsw[4];
    #pragma unroll
    for (int i = 0; i < 4; i++) {
        uint32_t off = lrow * 128 + (lunit + i) * 16;
        lsw[i] = off ^ ((off >> 3) & 0x70);
    }

    // fragment addressing (byte-identical to proven tf32 mapping)
    uint32_t a_rel[4], a_xr[4];
    #pragma unroll
    for (int i = 0; i < 4; i++) {
        int r = warp_m * 64 + i * 16 + (lane & 7) + ((lane >> 3) & 1) * 8;
        a_rel[i] = r * 128;
        a_xr[i]  = (r & 7) << 4;
    }
    const uint32_t a_kb = ((lane >> 4) & 1) * 16;
    uint32_t b_rel[2], b_xr[2];
    #pragma unroll
    for (int j = 0; j < 2; j++) {
        int r = warp_n * 32 + j * 16 + (lane & 7) + ((lane >> 4) & 1) * 8;
        b_rel[j] = r * 128;
        b_xr[j]  = (r & 7) << 4;
    }
    const uint32_t b_kb = ((lane >> 3) & 1) * 16;

    float acc[4][4][4];
    #pragma unroll
    for (int i = 0; i < 4; i++)
        #pragma unroll
        for (int t = 0; t < 4; t++)
            #pragma unroll
            for (int r = 0; r < 4; r++) acc[i][t][r] = 0.f;

    auto load_tile = [&](int s, int kt) {
        const uint32_t sA = sbase + s * STAGE_BYTES;
        const uint32_t sB = sA + 16384;
        const __half* ar = Ag + kt * 64;
        const __half* br = Bg + kt * 64;
        #pragma unroll
        for (int i = 0; i < 4; i++) CP_ASYNC16(sA + lsw[i], ar + i * 8);
        #pragma unroll
        for (int i = 0; i < 4; i++) CP_ASYNC16(sB + lsw[i], br + i * 8);
    };

    #pragma unroll
    for (int s = 0; s < STAGES - 1; s++) { load_tile(s, s); CP_COMMIT(); }

    int cur = 0, pfs = STAGES - 1;
    for (int kt = 0; kt < KT; kt++) {
        CP_WAIT(STAGES - 2);
        __syncthreads();

        const int pf = kt + STAGES - 1;
        if (pf < KT) load_tile(pfs, pf);
        CP_COMMIT();

        const uint32_t sA = sbase + cur * STAGE_BYTES;
        const uint32_t sB = sA + 16384;

        #pragma unroll
        for (int ks = 0; ks < 4; ks++) {          // 4 x k16 per 64-half chunk
            const uint32_t kso = ks * 32;
            uint32_t af[4][4];
            #pragma unroll
            for (int i = 0; i < 4; i++) {
                uint32_t addr = sA + ((a_rel[i] + a_kb + kso) ^ a_xr[i]);
                LDMATRIX_X4(af[i][0], af[i][1], af[i][2], af[i][3], addr);
            }
            uint32_t bf[4][2];
            #pragma unroll
            for (int j = 0; j < 2; j++) {
                uint32_t r0, r1, r2, r3;
                uint32_t addr = sB + ((b_rel[j] + b_kb + kso) ^ b_xr[j]);
                LDMATRIX_X4(r0, r1, r2, r3, addr);
                bf[2*j+0][0] = r0; bf[2*j+0][1] = r1;
                bf[2*j+1][0] = r2; bf[2*j+1][1] = r3;
            }
            #pragma unroll
            for (int i = 0; i < 4; i++)
                #pragma unroll
                for (int t = 0; t < 4; t++)
                    MMA_F16(acc[i][t][0], acc[i][t][1], acc[i][t][2], acc[i][t][3],
                            af[i][0], af[i][1], af[i][2], af[i][3],
                            bf[t][0], bf[t][1]);
        }
        cur++; if (cur == STAGES) cur = 0;
        pfs++; if (pfs == STAGES) pfs = 0;
    }

    #pragma unroll
    for (int i = 0; i < 4; i++) {
        const int row0 = bm + warp_m * 64 + i * 16 + gid;
        #pragma unroll
        for (int t = 0; t < 4; t++) {
            const int col = bn + warp_n * 32 + t * 8 + 2 * tg;
            const float2 bv = *(const float2*)(bias + col);
            float2 v0, v1;
            v0.x = acc[i][t][0] + bv.x; v0.y = acc[i][t][1] + bv.y;
            v1.x = acc[i][t][2] + bv.x; v1.y = acc[i][t][3] + bv.y;
            if (RELU) {
                v0.x = fmaxf(v0.x, 0.f); v0.y = fmaxf(v0.y, 0.f);
                v1.x = fmaxf(v1.x, 0.f); v1.y = fmaxf(v1.y, 0.f);
            }
            if (OUTM == 2) {
                __half* Ch = (__half*)Cv;
                *(__half2*)(Ch + (size_t)row0 * N + col)       = __floats2half2_rn(v0.x, v0.y);
                *(__half2*)(Ch + (size_t)(row0 + 8) * N + col) = __floats2half2_rn(v1.x, v1.y);
            } else {
                if (OUTM == 1) {
                    v0.x = roundf_tf32(v0.x); v0.y = roundf_tf32(v0.y);
                    v1.x = roundf_tf32(v1.x); v1.y = roundf_tf32(v1.y);
                }
                float* Cf = (float*)Cv;
                *(float2*)(Cf + (size_t)row0 * N + col)       = v0;
                *(float2*)(Cf + (size_t)(row0 + 8) * N + col) = v1;
            }
        }
    }
}

// ---------------------------------------------------------------------------
// Tensor-core flash attention (tf32 mma, fp32 Q/K/V). 128 queries x 1 head,
// 8 warps. K-tile 64 keys, double-buffered. Output written as HALF (O-proj A).
// ---------------------------------------------------------------------------
#define ATT_SMEM 65536

__global__ __launch_bounds__(256, 1)
void flash_mma(const float* __restrict__ QKV, const float* __restrict__ VT,
               __half* __restrict__ O)
{
    extern __shared__ char smem[];
    const uint32_t sbase = smem_u32(smem);
    const int tid  = threadIdx.x;
    const int wid  = tid >> 5;
    const int lane = tid & 31;
    const int gid  = lane >> 2;
    const int tg   = lane & 3;

    const int bh = blockIdx.y;
    const int b  = bh >> 4;
    const int h  = bh & 15;
    const int q0 = blockIdx.x * 128;

    const float* Qg  = QKV + (size_t)b * SEQ * QLD + h * HD;
    const float* Kg  = Qg + DMODEL;
    const float* VTg = VT + (size_t)bh * HD * SEQ;

    const uint32_t qreg = sbase + 32768;

    const int qrow = tid >> 1;
    const int qu0  = (tid & 1) * 8;
    uint32_t qsw[8];
    #pragma unroll
    for (int i = 0; i < 8; i++) {
        int u = qu0 + i;
        uint32_t off = qrow * 128 + (u & 7) * 16;
        qsw[i] = (u >> 3) * 16384 + (off ^ ((off >> 3) & 0x70));
    }

    const int krow = tid >> 2;
    const int ku0  = (tid & 3) * 4;
    uint32_t kvsw[4];
    #pragma unroll
    for (int i = 0; i < 4; i++) {
        int u = ku0 + i;
        uint32_t off = krow * 128 + (u & 7) * 16;
        kvsw[i] = (u >> 3) * 8192 + (off ^ ((off >> 3) & 0x70));
    }

    uint32_t aq_rel, aq_xr;
    {
        int r = wid * 16 + (lane & 7) + ((lane >> 3) & 1) * 8;
        aq_rel = r * 128;
        aq_xr  = (r & 7) << 4;
    }
    const uint32_t a_kb = ((lane >> 4) & 1) * 16;
    uint32_t b_rel[4], b_xr[4];
    #pragma unroll
    for (int j = 0; j < 4; j++) {
        int r = j * 16 + (lane & 7) + ((lane >> 4) & 1) * 8;
        b_rel[j] = r * 128;
        b_xr[j]  = (r & 7) << 4;
    }
    const uint32_t b_kb = ((lane >> 3) & 1) * 16;

    auto load_KV = [&](int stage, int kt) {
        const uint32_t sK = sbase + stage * 32768;
        const uint32_t sV = sK + 16384;
        const float* kr = Kg  + (size_t)(kt * 64 + krow) * QLD + ku0 * 4;
        const float* vr = VTg + (size_t)krow * SEQ + kt * 64 + ku0 * 4;
        #pragma unroll
        for (int i = 0; i < 4; i++) CP_ASYNC16(sK + kvsw[i], kr + i * 4);
        #pragma unroll
        for (int i = 0; i < 4; i++) CP_ASYNC16(sV + kvsw[i], vr + i * 4);
    };

    {
        const float* qr = Qg + (size_t)(q0 + qrow) * QLD + qu0 * 4;
        #pragma unroll
        for (int i = 0; i < 8; i++) CP_ASYNC16(qreg + qsw[i], qr + i * 4);
        load_KV(0, 0);
        CP_COMMIT();
        CP_WAIT(0);
        __syncthreads();
    }

    uint32_t qf[8][4];
    #pragma unroll
    for (int c = 0; c < 2; c++)
        #pragma unroll
        for (int ks = 0; ks < 4; ks++) {
            uint32_t addr = qreg + c * 16384 + ((aq_rel + a_kb + ks * 32) ^ aq_xr);
            LDMATRIX_X4(qf[c*4+ks][0], qf[c*4+ks][1], qf[c*4+ks][2], qf[c*4+ks][3], addr);
        }
    __syncthreads();

    const int NT = SEQ / 64;
    load_KV(1, 1);
    CP_COMMIT();

    float o[8][4];
    #pragma unroll
    for (int t = 0; t < 8; t++)
        #pragma unroll
        for (int r = 0; r < 4; r++) o[t][r] = 0.f;
    float m0 = -1e30f, m1 = -1e30f, l0 = 0.f, l1 = 0.f;

    for (int kt = 0; kt < NT; kt++) {
        if (kt < NT - 1) { CP_WAIT(1); } else { CP_WAIT(0); }
        __syncthreads();
        const uint32_t sK = sbase + (kt & 1) * 32768;
        const uint32_t sV = sK + 16384;

        float s[8][4];
        #pragma unroll
        for (int t = 0; t < 8; t++)
            #pragma unroll
            for (int r = 0; r < 4; r++) s[t][r] = 0.f;

        #pragma unroll
        for (int c = 0; c < 2; c++)
            #pragma unroll
            for (int ks = 0; ks < 4; ks++) {
                uint32_t bf[8][2];
                #pragma unroll
                for (int j = 0; j < 4; j++) {
                    uint32_t r0, r1, r2, r3;
                    uint32_t addr = sK + c * 8192 + ((b_rel[j] + b_kb + ks * 32) ^ b_xr[j]);
                    LDMATRIX_X4(r0, r1, r2, r3, addr);
                    bf[2*j+0][0] = r0; bf[2*j+0][1] = r1;
                    bf[2*j+1][0] = r2; bf[2*j+1][1] = r3;
                }
                const uint32_t* aq = qf[c*4+ks];
                #pragma unroll
                for (int t = 0; t < 8; t++)
                    MMA_TF32(s[t][0], s[t][1], s[t][2], s[t][3],
                             aq[0], aq[1], aq[2], aq[3], bf[t][0], bf[t][1]);
            }

        float tmax0 = -1e30f, tmax1 = -1e30f;
        #pragma unroll
        for (int t = 0; t < 8; t++) {
            s[t][0] *= 0.125f; s[t][1] *= 0.125f; s[t][2] *= 0.125f; s[t][3] *= 0.125f;
            tmax0 = fmaxf(tmax0, fmaxf(s[t][0], s[t][1]));
            tmax1 = fmaxf(tmax1, fmaxf(s[t][2], s[t][3]));
        }
        tmax0 = fmaxf(tmax0, __shfl_xor_sync(0xffffffffu, tmax0, 1));
        tmax0 = fmaxf(tmax0, __shfl_xor_sync(0xffffffffu, tmax0, 2));
        tmax1 = fmaxf(tmax1, __shfl_xor_sync(0xffffffffu, tmax1, 1));
        tmax1 = fmaxf(tmax1, __shfl_xor_sync(0xffffffffu, tmax1, 2));

        const float mnew0 = fmaxf(m0, tmax0);
        const float mnew1 = fmaxf(m1, tmax1);
        const float corr0 = __expf(m0 - mnew0);
        const float corr1 = __expf(m1 - mnew1);

        float rs0 = 0.f, rs1 = 0.f;
        #pragma unroll
        for (int t = 0; t < 8; t++) {
            s[t][0] = __expf(s[t][0] - mnew0);
            s[t][1] = __expf(s[t][1] - mnew0);
            s[t][2] = __expf(s[t][2] - mnew1);
            s[t][3] = __expf(s[t][3] - mnew1);
            rs0 += s[t][0] + s[t][1];
            rs1 += s[t][2] + s[t][3];
        }
        rs0 += __shfl_xor_sync(0xffffffffu, rs0, 1);
        rs0 += __shfl_xor_sync(0xffffffffu, rs0, 2);
        rs1 += __shfl_xor_sync(0xffffffffu, rs1, 1);
        rs1 += __shfl_xor_sync(0xffffffffu, rs1, 2);

        l0 = l0 * corr0 + rs0;
        l1 = l1 * corr1 + rs1;
        #pragma unroll
        for (int t = 0; t < 8; t++) {
            o[t][0] *= corr0; o[t][1] *= corr0;
            o[t][2] *= corr1; o[t][3] *= corr1;
        }
        m0 = mnew0; m1 = mnew1;

        #pragma unroll
        for (int ks = 0; ks < 8; ks++) {
            const int src0 = tg >> 1, src1 = src0 + 2;
            float v00 = __shfl_sync(0xffffffffu, s[ks][0], src0, 4);
            float v01 = __shfl_sync(0xffffffffu, s[ks][1], src0, 4);
            float v20 = __shfl_sync(0xffffffffu, s[ks][0], src1, 4);
            float v21 = __shfl_sync(0xffffffffu, s[ks][1], src1, 4);
            float v10 = __shfl_sync(0xffffffffu, s[ks][2], src0, 4);
            float v11 = __shfl_sync(0xffffffffu, s[ks][3], src0, 4);
            float v30 = __shfl_sync(0xffffffffu, s[ks][2], src1, 4);
            float v31 = __shfl_sync(0xffffffffu, s[ks][3], src1, 4);
            const bool oddc = (tg & 1);
            uint32_t a0 = to_tf32f(oddc ? v01 : v00);
            uint32_t a1 = to_tf32f(oddc ? v11 : v10);
            uint32_t a2 = to_tf32f(oddc ? v21 : v20);
            uint32_t a3 = to_tf32f(oddc ? v31 : v30);

            uint32_t bf[8][2];
            const uint32_t vbase = sV + (ks >> 2) * 8192;
            const uint32_t kso = (ks & 3) * 32;
            #pragma unroll
            for (int j = 0; j < 4; j++) {
                uint32_t r0, r1, r2, r3;
                uint32_t addr = vbase + ((b_rel[j] + b_kb + kso) ^ b_xr[j]);
                LDMATRIX_X4(r0, r1, r2, r3, addr);
                bf[2*j+0][0] = r0; bf[2*j+0][1] = r1;
                bf[2*j+1][0] = r2; bf[2*j+1][1] = r3;
            }
            #pragma unroll
            for (int t = 0; t < 8; t++)
                MMA_TF32(o[t][0], o[t][1], o[t][2], o[t][3],
                         a0, a1, a2, a3, bf[t][0], bf[t][1]);
        }

        __syncthreads();
        const int pf = kt + 2;
        if (pf < NT) { load_KV(pf & 1, pf); CP_COMMIT(); }
    }

    // ---- write ctx as HALF (feeds fp16 O-projection A operand) ----
    const float inv0 = 1.0f / l0;
    const float inv1 = 1.0f / l1;
    const int qa = q0 + wid * 16 + gid;
    __half* orow0 = O + (size_t)(b * SEQ + qa)     * DMODEL + h * HD;
    __half* orow1 = O + (size_t)(b * SEQ + qa + 8) * DMODEL + h * HD;
    #pragma unroll
    for (int t = 0; t < 8; t++) {
        const int col = t * 8 + 2 * tg;
        *(__half2*)(orow0 + col) = __floats2half2_rn(o[t][0] * inv0, o[t][1] * inv0);
        *(__half2*)(orow1 + col) = __floats2half2_rn(o[t][2] * inv1, o[t][3] * inv1);
    }
}

// ---------------------------------------------------------------------------
// Transpose helpers — weights to K-major half
// ---------------------------------------------------------------------------
__global__ __launch_bounds__(256)
void transpose_k(const float* __restrict__ in, __half* __restrict__ out, int K, int N)
{
    __shared__ float tile[32][33];
    const int k0 = blockIdx.y * 32, n0 = blockIdx.x * 32;
    const int tx = threadIdx.x, ty = threadIdx.y;
    #pragma unroll
    for (int i = ty; i < 32; i += 8)
        tile[i][tx] = in[(size_t)(k0 + i) * N + n0 + tx];
    __syncthreads();
    #pragma unroll
    for (int i = ty; i < 32; i += 8)
        out[(size_t)(n0 + i) * K + k0 + tx] = __float2half_rn(tile[tx][i]);
}

// V slice of fused qkv (fp32) -> g_vt[bh][64][2048] fp32
__global__ __launch_bounds__(256)
void transpose_vt(const float* __restrict__ qkv, float* __restrict__ vt)
{
    __shared__ float tile[32][33];
    const int s0 = blockIdx.x * 32;
    const int d0 = blockIdx.y * 32;
    const int bh = blockIdx.z;
    const int b = bh >> 4, h = bh & 15;
    const int tx = threadIdx.x, ty = threadIdx.y;
    const float* in = qkv + (size_t)b * SEQ * QLD + 2 * DMODEL + h * HD;
    float* out = vt + (size_t)bh * HD * SEQ;
    #pragma unroll
    for (int i = ty; i < 32; i += 8)
        tile[i][tx] = in[(size_t)(s0 + i) * QLD + d0 + tx];
    __syncthreads();
    #pragma unroll
    for (int i = ty; i < 32; i += 8)
        out[(size_t)(d0 + i) * SEQ + s0 + tx] = tile[tx][i];
}

__global__ void concat_bias(const float* a, const float* b, const float* c, float* out)
{
    int i = blockIdx.x * 256 + threadIdx.x;
    if (i < DMODEL)            out[i] = a[i];
    else if (i < 2 * DMODEL)   out[i] = b[i - DMODEL];
    else if (i < 3 * DMODEL)   out[i] = c[i - 2 * DMODEL];
}

// Half copy: out[i] = half(in[i]).
__global__ __launch_bounds__(256)
void half_copy(const float* __restrict__ in, __half* __restrict__ out, int n4)
{
    int i = blockIdx.x * 256 + threadIdx.x;
    if (i < n4) {
        float4 v = ((const float4*)in)[i];
        __half2* o = (__half2*)out + i * 2;
        o[0] = __floats2half2_rn(v.x, v.y);
        o[1] = __floats2half2_rn(v.z, v.w);
    }
}

// ---------------------------------------------------------------------------
// Fused residual add + LayerNorm. Optionally writes a half copy for fp16 GEMM A.
// ---------------------------------------------------------------------------
__global__ __launch_bounds__(256)
void add_ln(const float* __restrict__ A, const float* __restrict__ Bv,
            const float* __restrict__ g, const float* __restrict__ be,
            float* __restrict__ out, __half* __restrict__ out_h)
{
    const int row = blockIdx.x;
    const int tid = threadIdx.x;

    const float4 a4 = ((const float4*)(A  + (size_t)row * DMODEL))[tid];
    const float4 b4 = ((const float4*)(Bv + (size_t)row * DMODEL))[tid];
    float4 v;
    v.x = a4.x + b4.x; v.y = a4.y + b4.y; v.z = a4.z + b4.z; v.w = a4.w + b4.w;

    float s  = v.x + v.y + v.z + v.w;
    float ss = v.x*v.x + v.y*v.y + v.z*v.z + v.w*v.w;

    #pragma unroll
    for (int ofs = 16; ofs > 0; ofs >>= 1) {
        s  += __shfl_xor_sync(0xFFFFFFFFu, s,  ofs);
        ss += __shfl_xor_sync(0xFFFFFFFFu, ss, ofs);
    }

    __shared__ float shs[8], shss[8];
    const int w = tid >> 5;
    if ((tid & 31) == 0) { shs[w] = s; shss[w] = ss; }
    __syncthreads();
    if (tid < 32) {
        float s2  = (tid < 8) ? shs[tid]  : 0.f;
        float ss2 = (tid < 8) ? shss[tid] : 0.f;
        #pragma unroll
        for (int ofs = 4; ofs > 0; ofs >>= 1) {
            s2  += __shfl_xor_sync(0xFFFFFFFFu, s2,  ofs);
            ss2 += __shfl_xor_sync(0xFFFFFFFFu, ss2, ofs);
        }
        if (tid == 0) { shs[0] = s2; shss[0] = ss2; }
    }
    __syncthreads();

    const float mu  = shs[0]  * (1.f / DMODEL);
    const float var = shss[0] * (1.f / DMODEL) - mu * mu;
    const float inv = rsqrtf(var + 1e-5f);

    const float4 gv = ((const float4*)g)[tid];
    const float4 bb = ((const float4*)be)[tid];
    float4 o;
    o.x = (v.x - mu) * inv * gv.x + bb.x;
    o.y = (v.y - mu) * inv * gv.y + bb.y;
    o.z = (v.z - mu) * inv * gv.z + bb.z;
    o.w = (v.w - mu) * inv * gv.w + bb.w;
    ((float4*)(out + (size_t)row * DMODEL))[tid] = o;
    if (out_h) {
        __half2* oh = (__half2*)(out_h + (size_t)row * DMODEL) + tid * 2;
        oh[0] = __floats2half2_rn(o.x, o.y);
        oh[1] = __floats2half2_rn(o.z, o.w);
    }
}

// ---------------------------------------------------------------------------
// Launch
// ---------------------------------------------------------------------------
extern "C" void kernel_launch(void* const* d_in, const int* in_sizes, int n_in,
                              void* d_out, int out_size)
{
    const float* src  = (const float*)d_in[0];
    const float* Wq   = (const float*)d_in[1];
    const float* bq   = (const float*)d_in[2];
    const float* Wk   = (const float*)d_in[3];
    const float* bk   = (const float*)d_in[4];
    const float* Wv   = (const float*)d_in[5];
    const float* bv   = (const float*)d_in[6];
    const float* Wo   = (const float*)d_in[7];
    const float* bo   = (const float*)d_in[8];
    const float* W1   = (const float*)d_in[9];
    const float* b1   = (const float*)d_in[10];
    const float* W2   = (const float*)d_in[11];
    const float* b2   = (const float*)d_in[12];
    const float* ln1g = (const float*)d_in[13];
    const float* ln1b = (const float*)d_in[14];
    const float* ln2g = (const float*)d_in[15];
    const float* ln2b = (const float*)d_in[16];
    float* out = (float*)d_out;

    float  *pqkv, *pvt, *pbqkv, *ptmp, *px;
    __half *psrcr, *pxr, *pwqkvT, *pwoT, *pw1T, *pw2T, *pctx, *pff;
    cudaGetSymbolAddress((void**)&pqkv,   g_qkv);
    cudaGetSymbolAddress((void**)&pvt,    g_vt);
    cudaGetSymbolAddress((void**)&psrcr,  g_srcr);
    cudaGetSymbolAddress((void**)&pxr,    g_xr);
    cudaGetSymbolAddress((void**)&pwqkvT, g_wqkvT);
    cudaGetSymbolAddress((void**)&pwoT,   g_woT);
    cudaGetSymbolAddress((void**)&pw1T,   g_w1T);
    cudaGetSymbolAddress((void**)&pw2T,   g_w2T);
    cudaGetSymbolAddress((void**)&pbqkv,  g_bqkv);
    cudaGetSymbolAddress((void**)&pctx,   g_ctx);
    cudaGetSymbolAddress((void**)&ptmp,   g_tmp);
    cudaGetSymbolAddress((void**)&px,     g_x);
    cudaGetSymbolAddress((void**)&pff,    g_ff);

    cudaFuncSetAttribute((const void*)gemm_mma<false,0>, cudaFuncAttributeMaxDynamicSharedMemorySize, SMEM_DYN);
    cudaFuncSetAttribute((const void*)gemm_mma<false,1>, cudaFuncAttributeMaxDynamicSharedMemorySize, SMEM_DYN);
    cudaFuncSetAttribute((const void*)gemm_mma<true,2>,  cudaFuncAttributeMaxDynamicSharedMemorySize, SMEM_DYN);
    cudaFuncSetAttribute((const void*)flash_mma, cudaFuncAttributeMaxDynamicSharedMemorySize, ATT_SMEM);

    // Pre-converted inputs + weight transposes (to K-major [N,K], half)
    {
        dim3 blk(32, 8);
        half_copy<<<(NTOK * DMODEL / 4 + 255) / 256, 256>>>(src, psrcr, NTOK * DMODEL / 4);
        transpose_k<<<dim3(32, 32),  blk>>>(Wq, pwqkvT,                       DMODEL, DMODEL);
        transpose_k<<<dim3(32, 32),  blk>>>(Wk, pwqkvT + DMODEL * DMODEL,     DMODEL, DMODEL);
        transpose_k<<<dim3(32, 32),  blk>>>(Wv, pwqkvT + 2 * DMODEL * DMODEL, DMODEL, DMODEL);
        transpose_k<<<dim3(32, 32),  blk>>>(Wo, pwoT,  DMODEL, DMODEL);
        transpose_k<<<dim3(128, 32), blk>>>(W1, pw1T,  DMODEL, DFF);
        transpose_k<<<dim3(32, 128), blk>>>(W2, pw2T,  DFF,    DMODEL);
        concat_bias<<<12, 256>>>(bq, bk, bv, pbqkv);
    }

    // Fused QKV projection (fp16 in, fp32 tf32-rounded out: feeds tf32 flash)
    gemm_mma<false, 1><<<dim3(3 * DMODEL / 128, NTOK / 128), 256, SMEM_DYN>>>(
        psrcr, pwqkvT, pbqkv, pqkv, NTOK, 3 * DMODEL, DMODEL);

    // V^T for attention PV operand
    transpose_vt<<<dim3(SEQ / 32, HD / 32, 32), dim3(32, 8)>>>(pqkv, pvt);

    // Tensor-core flash attention (128 queries/block; half ctx out)
    flash_mma<<<dim3(SEQ / 128, 2 * NHEAD), 256, ATT_SMEM>>>(pqkv, pvt, pctx);

    // Output projection (half A, fp32 out) + LN1 (writes half copy for FFN1)
    gemm_mma<false, 0><<<dim3(DMODEL / 128, NTOK / 128), 256, SMEM_DYN>>>(
        pctx, pwoT, bo, ptmp, NTOK, DMODEL, DMODEL);
    add_ln<<<NTOK, 256>>>(src, ptmp, ln1g, ln1b, px, pxr);

    // FFN
    gemm_mma<true, 2><<<dim3(DFF / 128, NTOK / 128), 256, SMEM_DYN>>>(
        pxr, pw1T, b1, pff, NTOK, DFF, DMODEL);
    gemm_mma<false, 0><<<dim3(DMODEL / 128, NTOK / 128), 256, SMEM_DYN>>>(
        pff, pw2T, b2, ptmp, NTOK, DMODEL, DFF);
    add_ln<<<NTOK, 256>>>(px, ptmp, ln2g, ln2b, out, (__half*)nullptr);
}

// round 12
// speedup vs baseline: 2.4312x; 1.2742x over previous
#include <cuda_runtime.h>
#include <cuda_fp16.h>
#include <math.h>
#include <stdint.h>

// Problem constants
#define NTOK   4096      // B*S = 2*2048
#define DMODEL 1024
#define DFF    4096
#define NHEAD  16
#define HD     64
#define SEQ    2048
#define QLD    (3 * DMODEL)   // fused qkv row stride

// ---------------------------------------------------------------------------
// Scratch (static device globals; no runtime allocation allowed)
// ---------------------------------------------------------------------------
__device__ __align__(16) __half g_qkvh[NTOK * 3 * DMODEL];    // fused q|k|v half
__device__ __align__(16) __half g_vth [32 * HD * SEQ];        // V^T per (b,h) half
__device__ __align__(16) __half g_srcr[NTOK * DMODEL];        // half src (QKV A)
__device__ __align__(16) __half g_xr  [NTOK * DMODEL];        // half LN1 out (FFN1 A)
__device__ __align__(16) __half g_wqkvT[3 * DMODEL * DMODEL]; // [3072,1024] K-major half
__device__ __align__(16) __half g_woT [DMODEL * DMODEL];
__device__ __align__(16) __half g_w1T [DFF * DMODEL];
__device__ __align__(16) __half g_w2T [DMODEL * DFF];
__device__ __align__(16) float  g_bqkv[3 * DMODEL];
__device__ __align__(16) __half g_ctx [NTOK * DMODEL];        // half flash output (O-proj A)
__device__ __align__(16) float  g_tmp [NTOK * DMODEL];
__device__ __align__(16) float  g_x   [NTOK * DMODEL];
__device__ __align__(16) __half g_ff  [NTOK * DFF];           // half FFN1 output (FFN2 A)

// ---------------------------------------------------------------------------
// PTX helpers
// ---------------------------------------------------------------------------
__device__ __forceinline__ uint32_t smem_u32(const void* p) {
    uint32_t a;
    asm("{ .reg .u64 t; cvta.to.shared.u64 t, %1; cvt.u32.u64 %0, t; }" : "=r"(a) : "l"(p));
    return a;
}
#define CP_ASYNC16(dst, src) \
    asm volatile("cp.async.cg.shared.global [%0], [%1], 16;" :: "r"(dst), "l"(src))
#define CP_COMMIT() asm volatile("cp.async.commit_group;" ::: "memory")
#define CP_WAIT(n)  asm volatile("cp.async.wait_group %0;" :: "n"(n) : "memory")

#define LDMATRIX_X4(r0, r1, r2, r3, addr) \
    asm volatile("ldmatrix.sync.aligned.m8n8.x4.shared.b16 {%0,%1,%2,%3}, [%4];" \
                 : "=r"(r0), "=r"(r1), "=r"(r2), "=r"(r3) : "r"(addr))

#define MMA_F16(c0, c1, c2, c3, a0, a1, a2, a3, b0, b1) \
    asm volatile("mma.sync.aligned.m16n8k16.row.col.f32.f16.f16.f32 " \
                 "{%0,%1,%2,%3}, {%4,%5,%6,%7}, {%8,%9}, {%0,%1,%2,%3};" \
                 : "+f"(c0), "+f"(c1), "+f"(c2), "+f"(c3) \
                 : "r"(a0), "r"(a1), "r"(a2), "r"(a3), "r"(b0), "r"(b1))

__device__ __forceinline__ uint32_t packh2(float x, float y) {
    __half2 h = __floats2half2_rn(x, y);
    return *(uint32_t*)&h;
}

// ---------------------------------------------------------------------------
// fp16 tensor-core GEMM (R11-proven):  C = A @ BT^T + bias.  A,BT half.
// 128x128 tile, K-chunk 64 halves, 256 threads, 3-stage cp.async,
// 2 blocks/SM, one barrier per iteration.  OUTM: 0 = fp32 out, 2 = half out.
// ---------------------------------------------------------------------------
#define STAGES 3
#define STAGE_BYTES (2 * 128 * 128)          // A 16KB + B 16KB
#define SMEM_DYN (STAGES * STAGE_BYTES)      // 96KB -> 2 blocks/SM

template <bool RELU, int OUTM>
__global__ __launch_bounds__(256, 2)
void gemm_mma(const __half* __restrict__ A, const __half* __restrict__ BT,
              const float* __restrict__ bias, void* __restrict__ Cv,
              int M, int N, int K)
{
    extern __shared__ char smem[];
    const uint32_t sbase = smem_u32(smem);
    const int tid  = threadIdx.x;
    const int wid  = tid >> 5;
    const int lane = tid & 31;
    const int warp_m = wid & 1;
    const int warp_n = wid >> 1;
    const int gid = lane >> 2;
    const int tg  = lane & 3;

    const int bm = blockIdx.y * 128;
    const int bn = blockIdx.x * 128;
    const int KT = K >> 6;

    const int lrow  = tid >> 1;
    const int lunit = (tid & 1) * 4;
    const __half* Ag = A  + (size_t)(bm + lrow) * K + lunit * 8;
    const __half* Bg = BT + (size_t)(bn + lrow) * K + lunit * 8;
    uint32_t lsw[4];
    #pragma unroll
    for (int i = 0; i < 4; i++) {
        uint32_t off = lrow * 128 + (lunit + i) * 16;
        lsw[i] = off ^ ((off >> 3) & 0x70);
    }

    uint32_t a_rel[4], a_xr[4];
    #pragma unroll
    for (int i = 0; i < 4; i++) {
        int r = warp_m * 64 + i * 16 + (lane & 7) + ((lane >> 3) & 1) * 8;
        a_rel[i] = r * 128;
        a_xr[i]  = (r & 7) << 4;
    }
    const uint32_t a_kb = ((lane >> 4) & 1) * 16;
    uint32_t b_rel[2], b_xr[2];
    #pragma unroll
    for (int j = 0; j < 2; j++) {
        int r = warp_n * 32 + j * 16 + (lane & 7) + ((lane >> 4) & 1) * 8;
        b_rel[j] = r * 128;
        b_xr[j]  = (r & 7) << 4;
    }
    const uint32_t b_kb = ((lane >> 3) & 1) * 16;

    float acc[4][4][4];
    #pragma unroll
    for (int i = 0; i < 4; i++)
        #pragma unroll
        for (int t = 0; t < 4; t++)
            #pragma unroll
            for (int r = 0; r < 4; r++) acc[i][t][r] = 0.f;

    auto load_tile = [&](int s, int kt) {
        const uint32_t sA = sbase + s * STAGE_BYTES;
        const uint32_t sB = sA + 16384;
        const __half* ar = Ag + kt * 64;
        const __half* br = Bg + kt * 64;
        #pragma unroll
        for (int i = 0; i < 4; i++) CP_ASYNC16(sA + lsw[i], ar + i * 8);
        #pragma unroll
        for (int i = 0; i < 4; i++) CP_ASYNC16(sB + lsw[i], br + i * 8);
    };

    #pragma unroll
    for (int s = 0; s < STAGES - 1; s++) { load_tile(s, s); CP_COMMIT(); }

    int cur = 0, pfs = STAGES - 1;
    for (int kt = 0; kt < KT; kt++) {
        CP_WAIT(STAGES - 2);
        __syncthreads();

        const int pf = kt + STAGES - 1;
        if (pf < KT) load_tile(pfs, pf);
        CP_COMMIT();

        const uint32_t sA = sbase + cur * STAGE_BYTES;
        const uint32_t sB = sA + 16384;

        #pragma unroll
        for (int ks = 0; ks < 4; ks++) {
            const uint32_t kso = ks * 32;
            uint32_t af[4][4];
            #pragma unroll
            for (int i = 0; i < 4; i++) {
                uint32_t addr = sA + ((a_rel[i] + a_kb + kso) ^ a_xr[i]);
                LDMATRIX_X4(af[i][0], af[i][1], af[i][2], af[i][3], addr);
            }
            uint32_t bf[4][2];
            #pragma unroll
            for (int j = 0; j < 2; j++) {
                uint32_t r0, r1, r2, r3;
                uint32_t addr = sB + ((b_rel[j] + b_kb + kso) ^ b_xr[j]);
                LDMATRIX_X4(r0, r1, r2, r3, addr);
                bf[2*j+0][0] = r0; bf[2*j+0][1] = r1;
                bf[2*j+1][0] = r2; bf[2*j+1][1] = r3;
            }
            #pragma unroll
            for (int i = 0; i < 4; i++)
                #pragma unroll
                for (int t = 0; t < 4; t++)
                    MMA_F16(acc[i][t][0], acc[i][t][1], acc[i][t][2], acc[i][t][3],
                            af[i][0], af[i][1], af[i][2], af[i][3],
                            bf[t][0], bf[t][1]);
        }
        cur++; if (cur == STAGES) cur = 0;
        pfs++; if (pfs == STAGES) pfs = 0;
    }

    #pragma unroll
    for (int i = 0; i < 4; i++) {
        const int row0 = bm + warp_m * 64 + i * 16 + gid;
        #pragma unroll
        for (int t = 0; t < 4; t++) {
            const int col = bn + warp_n * 32 + t * 8 + 2 * tg;
            const float2 bv = *(const float2*)(bias + col);
            float2 v0, v1;
            v0.x = acc[i][t][0] + bv.x; v0.y = acc[i][t][1] + bv.y;
            v1.x = acc[i][t][2] + bv.x; v1.y = acc[i][t][3] + bv.y;
            if (RELU) {
                v0.x = fmaxf(v0.x, 0.f); v0.y = fmaxf(v0.y, 0.f);
                v1.x = fmaxf(v1.x, 0.f); v1.y = fmaxf(v1.y, 0.f);
            }
            if (OUTM == 2) {
                __half* Ch = (__half*)Cv;
                *(__half2*)(Ch + (size_t)row0 * N + col)       = __floats2half2_rn(v0.x, v0.y);
                *(__half2*)(Ch + (size_t)(row0 + 8) * N + col) = __floats2half2_rn(v1.x, v1.y);
            } else {
                float* Cf = (float*)Cv;
                *(float2*)(Cf + (size_t)row0 * N + col)       = v0;
                *(float2*)(Cf + (size_t)(row0 + 8) * N + col) = v1;
            }
        }
    }
}

// ---------------------------------------------------------------------------
// fp16 tensor-core flash attention. 128 queries x 1 head per block, 8 warps.
// K-tile 64 keys, double-buffered. Half Q/K/V; fp32 softmax/accum; half out.
// Tile rows = 64 halves = 128B -> single SW128 chunk.
// P A-operand built directly from S accumulators (no shuffles).
// ---------------------------------------------------------------------------
#define ATT_SMEM 49152   // 2 stages x (8KB K + 8KB VT) + 16KB Q

__global__ __launch_bounds__(256, 2)
void flash_mma(const __half* __restrict__ QKV, const __half* __restrict__ VT,
               __half* __restrict__ O)
{
    extern __shared__ char smem[];
    const uint32_t sbase = smem_u32(smem);
    const int tid  = threadIdx.x;
    const int wid  = tid >> 5;
    const int lane = tid & 31;
    const int gid  = lane >> 2;
    const int tg   = lane & 3;

    const int bh = blockIdx.y;
    const int b  = bh >> 4;
    const int h  = bh & 15;
    const int q0 = blockIdx.x * 128;

    const __half* Qg  = QKV + (size_t)b * SEQ * QLD + h * HD;
    const __half* Kg  = Qg + DMODEL;
    const __half* VTg = VT + (size_t)bh * HD * SEQ;

    const uint32_t qreg = sbase + 32768;    // 16KB Q region after 2x16KB stages

    // Q staging: 128 rows x 128B; thread -> row tid>>1, 4 of 8 16B units
    const int qrow = tid >> 1;
    const int qu0  = (tid & 1) * 4;
    uint32_t qsw[4];
    #pragma unroll
    for (int i = 0; i < 4; i++) {
        uint32_t off = qrow * 128 + (qu0 + i) * 16;
        qsw[i] = off ^ ((off >> 3) & 0x70);
    }
    // K/V tiles: 64 rows x 128B; thread -> row tid>>2, 2 of 8 units
    const int krow = tid >> 2;
    const int ku0  = (tid & 3) * 2;
    uint32_t kvsw[2];
    #pragma unroll
    for (int i = 0; i < 2; i++) {
        uint32_t off = krow * 128 + (ku0 + i) * 16;
        kvsw[i] = off ^ ((off >> 3) & 0x70);
    }

    // fragment addressing (fp16, proven GEMM mapping; 128B rows)
    uint32_t aq_rel, aq_xr;
    {
        int r = wid * 16 + (lane & 7) + ((lane >> 3) & 1) * 8;
        aq_rel = r * 128;
        aq_xr  = (r & 7) << 4;
    }
    const uint32_t a_kb = ((lane >> 4) & 1) * 16;
    uint32_t b_rel[4], b_xr[4];
    #pragma unroll
    for (int j = 0; j < 4; j++) {
        int r = j * 16 + (lane & 7) + ((lane >> 4) & 1) * 8;
        b_rel[j] = r * 128;
        b_xr[j]  = (r & 7) << 4;
    }
    const uint32_t b_kb = ((lane >> 3) & 1) * 16;

    auto load_KV = [&](int stage, int kt) {
        const uint32_t sK = sbase + stage * 16384;
        const uint32_t sV = sK + 8192;
        const __half* kr = Kg  + (size_t)(kt * 64 + krow) * QLD + ku0 * 8;
        const __half* vr = VTg + (size_t)krow * SEQ + kt * 64 + ku0 * 8;
        #pragma unroll
        for (int i = 0; i < 2; i++) CP_ASYNC16(sK + kvsw[i], kr + i * 8);
        #pragma unroll
        for (int i = 0; i < 2; i++) CP_ASYNC16(sV + kvsw[i], vr + i * 8);
    };

    // prologue: Q + tile 0
    {
        const __half* qr = Qg + (size_t)(q0 + qrow) * QLD + qu0 * 8;
        #pragma unroll
        for (int i = 0; i < 4; i++) CP_ASYNC16(qreg + qsw[i], qr + i * 8);
        load_KV(0, 0);
        CP_COMMIT();
        CP_WAIT(0);
        __syncthreads();
    }

    // Q fragments: 4 k16-steps over 64 dims
    uint32_t qf[4][4];
    #pragma unroll
    for (int ks = 0; ks < 4; ks++) {
        uint32_t addr = qreg + ((aq_rel + a_kb + ks * 32) ^ aq_xr);
        LDMATRIX_X4(qf[ks][0], qf[ks][1], qf[ks][2], qf[ks][3], addr);
    }
    __syncthreads();

    const int NT = SEQ / 64;
    load_KV(1, 1);
    CP_COMMIT();

    float o[8][4];
    #pragma unroll
    for (int t = 0; t < 8; t++)
        #pragma unroll
        for (int r = 0; r < 4; r++) o[t][r] = 0.f;
    float m0 = -1e30f, m1 = -1e30f, l0 = 0.f, l1 = 0.f;

    for (int kt = 0; kt < NT; kt++) {
        if (kt < NT - 1) { CP_WAIT(1); } else { CP_WAIT(0); }
        __syncthreads();
        const uint32_t sK = sbase + (kt & 1) * 16384;
        const uint32_t sV = sK + 8192;

        // ---- S = Q @ K^T (fp16) ----
        float s[8][4];
        #pragma unroll
        for (int t = 0; t < 8; t++)
            #pragma unroll
            for (int r = 0; r < 4; r++) s[t][r] = 0.f;

        #pragma unroll
        for (int ks = 0; ks < 4; ks++) {
            uint32_t bf[8][2];
            #pragma unroll
            for (int j = 0; j < 4; j++) {
                uint32_t r0, r1, r2, r3;
                uint32_t addr = sK + ((b_rel[j] + b_kb + ks * 32) ^ b_xr[j]);
                LDMATRIX_X4(r0, r1, r2, r3, addr);
                bf[2*j+0][0] = r0; bf[2*j+0][1] = r1;
                bf[2*j+1][0] = r2; bf[2*j+1][1] = r3;
            }
            const uint32_t* aq = qf[ks];
            #pragma unroll
            for (int t = 0; t < 8; t++)
                MMA_F16(s[t][0], s[t][1], s[t][2], s[t][3],
                        aq[0], aq[1], aq[2], aq[3], bf[t][0], bf[t][1]);
        }

        // ---- online softmax ----
        float tmax0 = -1e30f, tmax1 = -1e30f;
        #pragma unroll
        for (int t = 0; t < 8; t++) {
            s[t][0] *= 0.125f; s[t][1] *= 0.125f; s[t][2] *= 0.125f; s[t][3] *= 0.125f;
            tmax0 = fmaxf(tmax0, fmaxf(s[t][0], s[t][1]));
            tmax1 = fmaxf(tmax1, fmaxf(s[t][2], s[t][3]));
        }
        tmax0 = fmaxf(tmax0, __shfl_xor_sync(0xffffffffu, tmax0, 1));
        tmax0 = fmaxf(tmax0, __shfl_xor_sync(0xffffffffu, tmax0, 2));
        tmax1 = fmaxf(tmax1, __shfl_xor_sync(0xffffffffu, tmax1, 1));
        tmax1 = fmaxf(tmax1, __shfl_xor_sync(0xffffffffu, tmax1, 2));

        const float mnew0 = fmaxf(m0, tmax0);
        const float mnew1 = fmaxf(m1, tmax1);
        const float corr0 = __expf(m0 - mnew0);
        const float corr1 = __expf(m1 - mnew1);

        float rs0 = 0.f, rs1 = 0.f;
        #pragma unroll
        for (int t = 0; t < 8; t++) {
            s[t][0] = __expf(s[t][0] - mnew0);
            s[t][1] = __expf(s[t][1] - mnew0);
            s[t][2] = __expf(s[t][2] - mnew1);
            s[t][3] = __expf(s[t][3] - mnew1);
            rs0 += s[t][0] + s[t][1];
            rs1 += s[t][2] + s[t][3];
        }
        rs0 += __shfl_xor_sync(0xffffffffu, rs0, 1);
        rs0 += __shfl_xor_sync(0xffffffffu, rs0, 2);
        rs1 += __shfl_xor_sync(0xffffffffu, rs1, 1);
        rs1 += __shfl_xor_sync(0xffffffffu, rs1, 2);

        l0 = l0 * corr0 + rs0;
        l1 = l1 * corr1 + rs1;
        #pragma unroll
        for (int t = 0; t < 8; t++) {
            o[t][0] *= corr0; o[t][1] *= corr0;
            o[t][2] *= corr1; o[t][3] *= corr1;
        }
        m0 = mnew0; m1 = mnew1;

        // ---- ctx += P @ V (fp16; A built straight from S accumulators) ----
        #pragma unroll
        for (int ks = 0; ks < 4; ks++) {
            uint32_t a0 = packh2(s[2*ks+0][0], s[2*ks+0][1]);
            uint32_t a1 = packh2(s[2*ks+0][2], s[2*ks+0][3]);
            uint32_t a2 = packh2(s[2*ks+1][0], s[2*ks+1][1]);
            uint32_t a3 = packh2(s[2*ks+1][2], s[2*ks+1][3]);

            uint32_t bf[8][2];
            #pragma unroll
            for (int j = 0; j < 4; j++) {
                uint32_t r0, r1, r2, r3;
                uint32_t addr = sV + ((b_rel[j] + b_kb + ks * 32) ^ b_xr[j]);
                LDMATRIX_X4(r0, r1, r2, r3, addr);
                bf[2*j+0][0] = r0; bf[2*j+0][1] = r1;
                bf[2*j+1][0] = r2; bf[2*j+1][1] = r3;
            }
            #pragma unroll
            for (int t = 0; t < 8; t++)
                MMA_F16(o[t][0], o[t][1], o[t][2], o[t][3],
                        a0, a1, a2, a3, bf[t][0], bf[t][1]);
        }

        __syncthreads();
        const int pf = kt + 2;
        if (pf < NT) { load_KV(pf & 1, pf); CP_COMMIT(); }
    }

    // ---- write ctx as half ----
    const float inv0 = 1.0f / l0;
    const float inv1 = 1.0f / l1;
    const int qa = q0 + wid * 16 + gid;
    __half* orow0 = O + (size_t)(b * SEQ + qa)     * DMODEL + h * HD;
    __half* orow1 = O + (size_t)(b * SEQ + qa + 8) * DMODEL + h * HD;
    #pragma unroll
    for (int t = 0; t < 8; t++) {
        const int col = t * 8 + 2 * tg;
        *(__half2*)(orow0 + col) = __floats2half2_rn(o[t][0] * inv0, o[t][1] * inv0);
        *(__half2*)(orow1 + col) = __floats2half2_rn(o[t][2] * inv1, o[t][3] * inv1);
    }
}

// ---------------------------------------------------------------------------
// Transpose helpers
// ---------------------------------------------------------------------------
__global__ __launch_bounds__(256)
void transpose_k(const float* __restrict__ in, __half* __restrict__ out, int K, int N)
{
    __shared__ float tile[32][33];
    const int k0 = blockIdx.y * 32, n0 = blockIdx.x * 32;
    const int tx = threadIdx.x, ty = threadIdx.y;
    #pragma unroll
    for (int i = ty; i < 32; i += 8)
        tile[i][tx] = in[(size_t)(k0 + i) * N + n0 + tx];
    __syncthreads();
    #pragma unroll
    for (int i = ty; i < 32; i += 8)
        out[(size_t)(n0 + i) * K + k0 + tx] = __float2half_rn(tile[tx][i]);
}

// V slice of fused half qkv -> g_vth[bh][64][2048] half
__global__ __launch_bounds__(256)
void transpose_vt(const __half* __restrict__ qkv, __half* __restrict__ vt)
{
    __shared__ __half tile[32][34];
    const int s0 = blockIdx.x * 32;
    const int d0 = blockIdx.y * 32;
    const int bh = blockIdx.z;
    const int b = bh >> 4, h = bh & 15;
    const int tx = threadIdx.x, ty = threadIdx.y;
    const __half* in = qkv + (size_t)b * SEQ * QLD + 2 * DMODEL + h * HD;
    __half* out = vt + (size_t)bh * HD * SEQ;
    #pragma unroll
    for (int i = ty; i < 32; i += 8)
        tile[i][tx] = in[(size_t)(s0 + i) * QLD + d0 + tx];
    __syncthreads();
    #pragma unroll
    for (int i = ty; i < 32; i += 8)
        out[(size_t)(d0 + i) * SEQ + s0 + tx] = tile[tx][i];
}

__global__ void concat_bias(const float* a, const float* b, const float* c, float* out)
{
    int i = blockIdx.x * 256 + threadIdx.x;
    if (i < DMODEL)            out[i] = a[i];
    else if (i < 2 * DMODEL)   out[i] = b[i - DMODEL];
    else if (i < 3 * DMODEL)   out[i] = c[i - 2 * DMODEL];
}

// Half copy: out[i] = half(in[i]).
__global__ __launch_bounds__(256)
void half_copy(const float* __restrict__ in, __half* __restrict__ out, int n4)
{
    int i = blockIdx.x * 256 + threadIdx.x;
    if (i < n4) {
        float4 v = ((const float4*)in)[i];
        __half2* o = (__half2*)out + i * 2;
        o[0] = __floats2half2_rn(v.x, v.y);
        o[1] = __floats2half2_rn(v.z, v.w);
    }
}

// ---------------------------------------------------------------------------
// Fused residual add + LayerNorm. Optionally writes a half copy for fp16 GEMM A.
// ---------------------------------------------------------------------------
__global__ __launch_bounds__(256)
void add_ln(const float* __restrict__ A, const float* __restrict__ Bv,
            const float* __restrict__ g, const float* __restrict__ be,
            float* __restrict__ out, __half* __restrict__ out_h)
{
    const int row = blockIdx.x;
    const int tid = threadIdx.x;

    const float4 a4 = ((const float4*)(A  + (size_t)row * DMODEL))[tid];
    const float4 b4 = ((const float4*)(Bv + (size_t)row * DMODEL))[tid];
    float4 v;
    v.x = a4.x + b4.x; v.y = a4.y + b4.y; v.z = a4.z + b4.z; v.w = a4.w + b4.w;

    float s  = v.x + v.y + v.z + v.w;
    float ss = v.x*v.x + v.y*v.y + v.z*v.z + v.w*v.w;

    #pragma unroll
    for (int ofs = 16; ofs > 0; ofs >>= 1) {
        s  += __shfl_xor_sync(0xFFFFFFFFu, s,  ofs);
        ss += __shfl_xor_sync(0xFFFFFFFFu, ss, ofs);
    }

    __shared__ float shs[8], shss[8];
    const int w = tid >> 5;
    if ((tid & 31) == 0) { shs[w] = s; shss[w] = ss; }
    __syncthreads();
    if (tid < 32) {
        float s2  = (tid < 8) ? shs[tid]  : 0.f;
        float ss2 = (tid < 8) ? shss[tid] : 0.f;
        #pragma unroll
        for (int ofs = 4; ofs > 0; ofs >>= 1) {
            s2  += __shfl_xor_sync(0xFFFFFFFFu, s2,  ofs);
            ss2 += __shfl_xor_sync(0xFFFFFFFFu, ss2, ofs);
        }
        if (tid == 0) { shs[0] = s2; shss[0] = ss2; }
    }
    __syncthreads();

    const float mu  = shs[0]  * (1.f / DMODEL);
    const float var = shss[0] * (1.f / DMODEL) - mu * mu;
    const float inv = rsqrtf(var + 1e-5f);

    const float4 gv = ((const float4*)g)[tid];
    const float4 bb = ((const float4*)be)[tid];
    float4 o;
    o.x = (v.x - mu) * inv * gv.x + bb.x;
    o.y = (v.y - mu) * inv * gv.y + bb.y;
    o.z = (v.z - mu) * inv * gv.z + bb.z;
    o.w = (v.w - mu) * inv * gv.w + bb.w;
    ((float4*)(out + (size_t)row * DMODEL))[tid] = o;
    if (out_h) {
        __half2* oh = (__half2*)(out_h + (size_t)row * DMODEL) + tid * 2;
        oh[0] = __floats2half2_rn(o.x, o.y);
        oh[1] = __floats2half2_rn(o.z, o.w);
    }
}

// ---------------------------------------------------------------------------
// Launch
// ---------------------------------------------------------------------------
extern "C" void kernel_launch(void* const* d_in, const int* in_sizes, int n_in,
                              void* d_out, int out_size)
{
    const float* src  = (const float*)d_in[0];
    const float* Wq   = (const float*)d_in[1];
    const float* bq   = (const float*)d_in[2];
    const float* Wk   = (const float*)d_in[3];
    const float* bk   = (const float*)d_in[4];
    const float* Wv   = (const float*)d_in[5];
    const float* bv   = (const float*)d_in[6];
    const float* Wo   = (const float*)d_in[7];
    const float* bo   = (const float*)d_in[8];
    const float* W1   = (const float*)d_in[9];
    const float* b1   = (const float*)d_in[10];
    const float* W2   = (const float*)d_in[11];
    const float* b2   = (const float*)d_in[12];
    const float* ln1g = (const float*)d_in[13];
    const float* ln1b = (const float*)d_in[14];
    const float* ln2g = (const float*)d_in[15];
    const float* ln2b = (const float*)d_in[16];
    float* out = (float*)d_out;

    float  *pbqkv, *ptmp, *px;
    __half *pqkvh, *pvth, *psrcr, *pxr, *pwqkvT, *pwoT, *pw1T, *pw2T, *pctx, *pff;
    cudaGetSymbolAddress((void**)&pqkvh,  g_qkvh);
    cudaGetSymbolAddress((void**)&pvth,   g_vth);
    cudaGetSymbolAddress((void**)&psrcr,  g_srcr);
    cudaGetSymbolAddress((void**)&pxr,    g_xr);
    cudaGetSymbolAddress((void**)&pwqkvT, g_wqkvT);
    cudaGetSymbolAddress((void**)&pwoT,   g_woT);
    cudaGetSymbolAddress((void**)&pw1T,   g_w1T);
    cudaGetSymbolAddress((void**)&pw2T,   g_w2T);
    cudaGetSymbolAddress((void**)&pbqkv,  g_bqkv);
    cudaGetSymbolAddress((void**)&pctx,   g_ctx);
    cudaGetSymbolAddress((void**)&ptmp,   g_tmp);
    cudaGetSymbolAddress((void**)&px,     g_x);
    cudaGetSymbolAddress((void**)&pff,    g_ff);

    cudaFuncSetAttribute((const void*)gemm_mma<false,0>, cudaFuncAttributeMaxDynamicSharedMemorySize, SMEM_DYN);
    cudaFuncSetAttribute((const void*)gemm_mma<false,2>, cudaFuncAttributeMaxDynamicSharedMemorySize, SMEM_DYN);
    cudaFuncSetAttribute((const void*)gemm_mma<true,2>,  cudaFuncAttributeMaxDynamicSharedMemorySize, SMEM_DYN);
    cudaFuncSetAttribute((const void*)flash_mma, cudaFuncAttributeMaxDynamicSharedMemorySize, ATT_SMEM);

    // Pre-converted inputs + weight transposes (to K-major [N,K], half)
    {
        dim3 blk(32, 8);
        half_copy<<<(NTOK * DMODEL / 4 + 255) / 256, 256>>>(src, psrcr, NTOK * DMODEL / 4);
        transpose_k<<<dim3(32, 32),  blk>>>(Wq, pwqkvT,                       DMODEL, DMODEL);
        transpose_k<<<dim3(32, 32),  blk>>>(Wk, pwqkvT + DMODEL * DMODEL,     DMODEL, DMODEL);
        transpose_k<<<dim3(32, 32),  blk>>>(Wv, pwqkvT + 2 * DMODEL * DMODEL, DMODEL, DMODEL);
        transpose_k<<<dim3(32, 32),  blk>>>(Wo, pwoT,  DMODEL, DMODEL);
        transpose_k<<<dim3(128, 32), blk>>>(W1, pw1T,  DMODEL, DFF);
        transpose_k<<<dim3(32, 128), blk>>>(W2, pw2T,  DFF,    DMODEL);
        concat_bias<<<12, 256>>>(bq, bk, bv, pbqkv);
    }

    // Fused QKV projection (half in, half out: feeds fp16 flash)
    gemm_mma<false, 2><<<dim3(3 * DMODEL / 128, NTOK / 128), 256, SMEM_DYN>>>(
        psrcr, pwqkvT, pbqkv, pqkvh, NTOK, 3 * DMODEL, DMODEL);

    // V^T (half) for attention PV operand
    transpose_vt<<<dim3(SEQ / 32, HD / 32, 32), dim3(32, 8)>>>(pqkvh, pvth);

    // fp16 flash attention (128 queries/block; half ctx out)
    flash_mma<<<dim3(SEQ / 128, 2 * NHEAD), 256, ATT_SMEM>>>(pqkvh, pvth, pctx);

    // Output projection (half A, fp32 out) + LN1 (writes half copy for FFN1)
    gemm_mma<false, 0><<<dim3(DMODEL / 128, NTOK / 128), 256, SMEM_DYN>>>(
        pctx, pwoT, bo, ptmp, NTOK, DMODEL, DMODEL);
    add_ln<<<NTOK, 256>>>(src, ptmp, ln1g, ln1b, px, pxr);

    // FFN
    gemm_mma<true, 2><<<dim3(DFF / 128, NTOK / 128), 256, SMEM_DYN>>>(
        pxr, pw1T, b1, pff, NTOK, DFF, DMODEL);
    gemm_mma<false, 0><<<dim3(DMODEL / 128, NTOK / 128), 256, SMEM_DYN>>>(
        pff, pw2T, b2, ptmp, NTOK, DMODEL, DFF);
    add_ln<<<NTOK, 256>>>(px, ptmp, ln2g, ln2b, out, (__half*)nullptr);
}

// round 13
// speedup vs baseline: 2.5090x; 1.0320x over previous
#include <cuda_runtime.h>
#include <cuda_fp16.h>
#include <math.h>
#include <stdint.h>

// Problem constants
#define NTOK   4096      // B*S = 2*2048
#define DMODEL 1024
#define DFF    4096
#define NHEAD  16
#define HD     64
#define SEQ    2048
#define QLD    (3 * DMODEL)   // fused qkv row stride

// ---------------------------------------------------------------------------
// Scratch (static device globals; no runtime allocation allowed)
// ---------------------------------------------------------------------------
__device__ __align__(16) __half g_qkvh[NTOK * 3 * DMODEL];    // fused q|k|v half
__device__ __align__(16) __half g_vth [32 * HD * SEQ];        // V^T per (b,h) half
__device__ __align__(16) __half g_srcr[NTOK * DMODEL];        // half src (QKV A)
__device__ __align__(16) __half g_xr  [NTOK * DMODEL];        // half LN1 out (FFN1 A)
__device__ __align__(16) __half g_wqkvT[3 * DMODEL * DMODEL]; // [3072,1024] K-major half
__device__ __align__(16) __half g_woT [DMODEL * DMODEL];
__device__ __align__(16) __half g_w1T [DFF * DMODEL];
__device__ __align__(16) __half g_w2T [DMODEL * DFF];
__device__ __align__(16) float  g_bqkv[3 * DMODEL];
__device__ __align__(16) __half g_ctx [NTOK * DMODEL];        // half flash output (O-proj A)
__device__ __align__(16) float  g_tmp [NTOK * DMODEL];
__device__ __align__(16) float  g_x   [NTOK * DMODEL];
__device__ __align__(16) __half g_ff  [NTOK * DFF];           // half FFN1 output (FFN2 A)

// ---------------------------------------------------------------------------
// PTX helpers
// ---------------------------------------------------------------------------
__device__ __forceinline__ uint32_t smem_u32(const void* p) {
    uint32_t a;
    asm("{ .reg .u64 t; cvta.to.shared.u64 t, %1; cvt.u32.u64 %0, t; }" : "=r"(a) : "l"(p));
    return a;
}
#define CP_ASYNC16(dst, src) \
    asm volatile("cp.async.cg.shared.global [%0], [%1], 16;" :: "r"(dst), "l"(src))
#define CP_COMMIT() asm volatile("cp.async.commit_group;" ::: "memory")
#define CP_WAIT(n)  asm volatile("cp.async.wait_group %0;" :: "n"(n) : "memory")

#define LDMATRIX_X4(r0, r1, r2, r3, addr) \
    asm volatile("ldmatrix.sync.aligned.m8n8.x4.shared.b16 {%0,%1,%2,%3}, [%4];" \
                 : "=r"(r0), "=r"(r1), "=r"(r2), "=r"(r3) : "r"(addr))

#define MMA_F16(c0, c1, c2, c3, a0, a1, a2, a3, b0, b1) \
    asm volatile("mma.sync.aligned.m16n8k16.row.col.f32.f16.f16.f32 " \
                 "{%0,%1,%2,%3}, {%4,%5,%6,%7}, {%8,%9}, {%0,%1,%2,%3};" \
                 : "+f"(c0), "+f"(c1), "+f"(c2), "+f"(c3) \
                 : "r"(a0), "r"(a1), "r"(a2), "r"(a3), "r"(b0), "r"(b1))

__device__ __forceinline__ uint32_t packh2(float x, float y) {
    __half2 h = __floats2half2_rn(x, y);
    return *(uint32_t*)&h;
}

// ---------------------------------------------------------------------------
// fp16 tensor-core GEMM:  C = A @ BT^T + bias.  A,BT half (K-major).
// 256x128 block tile, K-chunk 64 halves, 512 threads (16 warps, 4x4 grid,
// warp tile 64x32 — unchanged), 3-stage cp.async, one barrier per iteration.
// OUTM: 0 = fp32 out, 2 = half out.  Requires M%256==0, N%128==0, K%64==0.
// ---------------------------------------------------------------------------
#define STAGES 3
#define A_ST_BYTES (256 * 128)               // 32KB
#define B_ST_BYTES (128 * 128)               // 16KB
#define STAGE_BYTES (A_ST_BYTES + B_ST_BYTES)
#define SMEM_DYN (STAGES * STAGE_BYTES)      // 144KB -> 1 block/SM, 16 warps

template <bool RELU, int OUTM>
__global__ __launch_bounds__(512, 1)
void gemm_mma(const __half* __restrict__ A, const __half* __restrict__ BT,
              const float* __restrict__ bias, void* __restrict__ Cv,
              int M, int N, int K)
{
    extern __shared__ char smem[];
    const uint32_t sbase = smem_u32(smem);
    const int tid  = threadIdx.x;
    const int wid  = tid >> 5;
    const int lane = tid & 31;
    const int warp_m = wid & 3;        // 0..3 (64 rows each -> 256)
    const int warp_n = wid >> 2;       // 0..3 (32 cols each -> 128)
    const int gid = lane >> 2;
    const int tg  = lane & 3;

    const int bm = blockIdx.y * 256;
    const int bn = blockIdx.x * 128;
    const int KT = K >> 6;

    // A loads: 256 rows x 128B; thread -> row tid>>1, 4 of 8 16B units
    const int arow = tid >> 1;
    const int au0  = (tid & 1) * 4;
    const __half* Ag = A + (size_t)(bm + arow) * K + au0 * 8;
    uint32_t aswz[4];
    #pragma unroll
    for (int i = 0; i < 4; i++) {
        uint32_t off = arow * 128 + (au0 + i) * 16;
        aswz[i] = off ^ ((off >> 3) & 0x70);
    }
    // B loads: 128 rows x 128B; thread -> row tid>>2, 2 of 8 units
    const int brow = tid >> 2;
    const int bu0  = (tid & 3) * 2;
    const __half* Bg = BT + (size_t)(bn + brow) * K + bu0 * 8;
    uint32_t bswz[2];
    #pragma unroll
    for (int i = 0; i < 2; i++) {
        uint32_t off = brow * 128 + (bu0 + i) * 16;
        bswz[i] = off ^ ((off >> 3) & 0x70);
    }

    // fragment addressing (proven 64x32 warp-tile mapping)
    uint32_t a_rel[4], a_xr[4];
    #pragma unroll
    for (int i = 0; i < 4; i++) {
        int r = warp_m * 64 + i * 16 + (lane & 7) + ((lane >> 3) & 1) * 8;
        a_rel[i] = r * 128;
        a_xr[i]  = (r & 7) << 4;
    }
    const uint32_t a_kb = ((lane >> 4) & 1) * 16;
    uint32_t b_rel[2], b_xr[2];
    #pragma unroll
    for (int j = 0; j < 2; j++) {
        int r = warp_n * 32 + j * 16 + (lane & 7) + ((lane >> 4) & 1) * 8;
        b_rel[j] = r * 128;
        b_xr[j]  = (r & 7) << 4;
    }
    const uint32_t b_kb = ((lane >> 3) & 1) * 16;

    float acc[4][4][4];
    #pragma unroll
    for (int i = 0; i < 4; i++)
        #pragma unroll
        for (int t = 0; t < 4; t++)
            #pragma unroll
            for (int r = 0; r < 4; r++) acc[i][t][r] = 0.f;

    auto load_tile = [&](int s, int kt) {
        const uint32_t sA = sbase + s * STAGE_BYTES;
        const uint32_t sB = sA + A_ST_BYTES;
        const __half* ar = Ag + kt * 64;
        const __half* br = Bg + kt * 64;
        #pragma unroll
        for (int i = 0; i < 4; i++) CP_ASYNC16(sA + aswz[i], ar + i * 8);
        #pragma unroll
        for (int i = 0; i < 2; i++) CP_ASYNC16(sB + bswz[i], br + i * 8);
    };

    #pragma unroll
    for (int s = 0; s < STAGES - 1; s++) { load_tile(s, s); CP_COMMIT(); }

    int cur = 0, pfs = STAGES - 1;
    for (int kt = 0; kt < KT; kt++) {
        CP_WAIT(STAGES - 2);
        __syncthreads();

        const int pf = kt + STAGES - 1;
        if (pf < KT) load_tile(pfs, pf);
        CP_COMMIT();

        const uint32_t sA = sbase + cur * STAGE_BYTES;
        const uint32_t sB = sA + A_ST_BYTES;

        #pragma unroll
        for (int ks = 0; ks < 4; ks++) {
            const uint32_t kso = ks * 32;
            uint32_t af[4][4];
            #pragma unroll
            for (int i = 0; i < 4; i++) {
                uint32_t addr = sA + ((a_rel[i] + a_kb + kso) ^ a_xr[i]);
                LDMATRIX_X4(af[i][0], af[i][1], af[i][2], af[i][3], addr);
            }
            uint32_t bf[4][2];
            #pragma unroll
            for (int j = 0; j < 2; j++) {
                uint32_t r0, r1, r2, r3;
                uint32_t addr = sB + ((b_rel[j] + b_kb + kso) ^ b_xr[j]);
                LDMATRIX_X4(r0, r1, r2, r3, addr);
                bf[2*j+0][0] = r0; bf[2*j+0][1] = r1;
                bf[2*j+1][0] = r2; bf[2*j+1][1] = r3;
            }
            #pragma unroll
            for (int i = 0; i < 4; i++)
                #pragma unroll
                for (int t = 0; t < 4; t++)
                    MMA_F16(acc[i][t][0], acc[i][t][1], acc[i][t][2], acc[i][t][3],
                            af[i][0], af[i][1], af[i][2], af[i][3],
                            bf[t][0], bf[t][1]);
        }
        cur++; if (cur == STAGES) cur = 0;
        pfs++; if (pfs == STAGES) pfs = 0;
    }

    #pragma unroll
    for (int i = 0; i < 4; i++) {
        const int row0 = bm + warp_m * 64 + i * 16 + gid;
        #pragma unroll
        for (int t = 0; t < 4; t++) {
            const int col = bn + warp_n * 32 + t * 8 + 2 * tg;
            const float2 bv = *(const float2*)(bias + col);
            float2 v0, v1;
            v0.x = acc[i][t][0] + bv.x; v0.y = acc[i][t][1] + bv.y;
            v1.x = acc[i][t][2] + bv.x; v1.y = acc[i][t][3] + bv.y;
            if (RELU) {
                v0.x = fmaxf(v0.x, 0.f); v0.y = fmaxf(v0.y, 0.f);
                v1.x = fmaxf(v1.x, 0.f); v1.y = fmaxf(v1.y, 0.f);
            }
            if (OUTM == 2) {
                __half* Ch = (__half*)Cv;
                *(__half2*)(Ch + (size_t)row0 * N + col)       = __floats2half2_rn(v0.x, v0.y);
                *(__half2*)(Ch + (size_t)(row0 + 8) * N + col) = __floats2half2_rn(v1.x, v1.y);
            } else {
                float* Cf = (float*)Cv;
                *(float2*)(Cf + (size_t)row0 * N + col)       = v0;
                *(float2*)(Cf + (size_t)(row0 + 8) * N + col) = v1;
            }
        }
    }
}

// ---------------------------------------------------------------------------
// fp16 tensor-core flash attention (R12-proven). 128 queries x 1 head, 8 warps.
// ---------------------------------------------------------------------------
#define ATT_SMEM 49152   // 2 stages x (8KB K + 8KB VT) + 16KB Q

__global__ __launch_bounds__(256, 2)
void flash_mma(const __half* __restrict__ QKV, const __half* __restrict__ VT,
               __half* __restrict__ O)
{
    extern __shared__ char smem[];
    const uint32_t sbase = smem_u32(smem);
    const int tid  = threadIdx.x;
    const int wid  = tid >> 5;
    const int lane = tid & 31;
    const int gid  = lane >> 2;
    const int tg   = lane & 3;

    const int bh = blockIdx.y;
    const int b  = bh >> 4;
    const int h  = bh & 15;
    const int q0 = blockIdx.x * 128;

    const __half* Qg  = QKV + (size_t)b * SEQ * QLD + h * HD;
    const __half* Kg  = Qg + DMODEL;
    const __half* VTg = VT + (size_t)bh * HD * SEQ;

    const uint32_t qreg = sbase + 32768;

    const int qrow = tid >> 1;
    const int qu0  = (tid & 1) * 4;
    uint32_t qsw[4];
    #pragma unroll
    for (int i = 0; i < 4; i++) {
        uint32_t off = qrow * 128 + (qu0 + i) * 16;
        qsw[i] = off ^ ((off >> 3) & 0x70);
    }
    const int krow = tid >> 2;
    const int ku0  = (tid & 3) * 2;
    uint32_t kvsw[2];
    #pragma unroll
    for (int i = 0; i < 2; i++) {
        uint32_t off = krow * 128 + (ku0 + i) * 16;
        kvsw[i] = off ^ ((off >> 3) & 0x70);
    }

    uint32_t aq_rel, aq_xr;
    {
        int r = wid * 16 + (lane & 7) + ((lane >> 3) & 1) * 8;
        aq_rel = r * 128;
        aq_xr  = (r & 7) << 4;
    }
    const uint32_t a_kb = ((lane >> 4) & 1) * 16;
    uint32_t b_rel[4], b_xr[4];
    #pragma unroll
    for (int j = 0; j < 4; j++) {
        int r = j * 16 + (lane & 7) + ((lane >> 4) & 1) * 8;
        b_rel[j] = r * 128;
        b_xr[j]  = (r & 7) << 4;
    }
    const uint32_t b_kb = ((lane >> 3) & 1) * 16;

    auto load_KV = [&](int stage, int kt) {
        const uint32_t sK = sbase + stage * 16384;
        const uint32_t sV = sK + 8192;
        const __half* kr = Kg  + (size_t)(kt * 64 + krow) * QLD + ku0 * 8;
        const __half* vr = VTg + (size_t)krow * SEQ + kt * 64 + ku0 * 8;
        #pragma unroll
        for (int i = 0; i < 2; i++) CP_ASYNC16(sK + kvsw[i], kr + i * 8);
        #pragma unroll
        for (int i = 0; i < 2; i++) CP_ASYNC16(sV + kvsw[i], vr + i * 8);
    };

    {
        const __half* qr = Qg + (size_t)(q0 + qrow) * QLD + qu0 * 8;
        #pragma unroll
        for (int i = 0; i < 4; i++) CP_ASYNC16(qreg + qsw[i], qr + i * 8);
        load_KV(0, 0);
        CP_COMMIT();
        CP_WAIT(0);
        __syncthreads();
    }

    uint32_t qf[4][4];
    #pragma unroll
    for (int ks = 0; ks < 4; ks++) {
        uint32_t addr = qreg + ((aq_rel + a_kb + ks * 32) ^ aq_xr);
        LDMATRIX_X4(qf[ks][0], qf[ks][1], qf[ks][2], qf[ks][3], addr);
    }
    __syncthreads();

    const int NT = SEQ / 64;
    load_KV(1, 1);
    CP_COMMIT();

    float o[8][4];
    #pragma unroll
    for (int t = 0; t < 8; t++)
        #pragma unroll
        for (int r = 0; r < 4; r++) o[t][r] = 0.f;
    float m0 = -1e30f, m1 = -1e30f, l0 = 0.f, l1 = 0.f;

    for (int kt = 0; kt < NT; kt++) {
        if (kt < NT - 1) { CP_WAIT(1); } else { CP_WAIT(0); }
        __syncthreads();
        const uint32_t sK = sbase + (kt & 1) * 16384;
        const uint32_t sV = sK + 8192;

        float s[8][4];
        #pragma unroll
        for (int t = 0; t < 8; t++)
            #pragma unroll
            for (int r = 0; r < 4; r++) s[t][r] = 0.f;

        #pragma unroll
        for (int ks = 0; ks < 4; ks++) {
            uint32_t bf[8][2];
            #pragma unroll
            for (int j = 0; j < 4; j++) {
                uint32_t r0, r1, r2, r3;
                uint32_t addr = sK + ((b_rel[j] + b_kb + ks * 32) ^ b_xr[j]);
                LDMATRIX_X4(r0, r1, r2, r3, addr);
                bf[2*j+0][0] = r0; bf[2*j+0][1] = r1;
                bf[2*j+1][0] = r2; bf[2*j+1][1] = r3;
            }
            const uint32_t* aq = qf[ks];
            #pragma unroll
            for (int t = 0; t < 8; t++)
                MMA_F16(s[t][0], s[t][1], s[t][2], s[t][3],
                        aq[0], aq[1], aq[2], aq[3], bf[t][0], bf[t][1]);
        }

        float tmax0 = -1e30f, tmax1 = -1e30f;
        #pragma unroll
        for (int t = 0; t < 8; t++) {
            s[t][0] *= 0.125f; s[t][1] *= 0.125f; s[t][2] *= 0.125f; s[t][3] *= 0.125f;
            tmax0 = fmaxf(tmax0, fmaxf(s[t][0], s[t][1]));
            tmax1 = fmaxf(tmax1, fmaxf(s[t][2], s[t][3]));
        }
        tmax0 = fmaxf(tmax0, __shfl_xor_sync(0xffffffffu, tmax0, 1));
        tmax0 = fmaxf(tmax0, __shfl_xor_sync(0xffffffffu, tmax0, 2));
        tmax1 = fmaxf(tmax1, __shfl_xor_sync(0xffffffffu, tmax1, 1));
        tmax1 = fmaxf(tmax1, __shfl_xor_sync(0xffffffffu, tmax1, 2));

        const float mnew0 = fmaxf(m0, tmax0);
        const float mnew1 = fmaxf(m1, tmax1);
        const float corr0 = __expf(m0 - mnew0);
        const float corr1 = __expf(m1 - mnew1);

        float rs0 = 0.f, rs1 = 0.f;
        #pragma unroll
        for (int t = 0; t < 8; t++) {
            s[t][0] = __expf(s[t][0] - mnew0);
            s[t][1] = __expf(s[t][1] - mnew0);
            s[t][2] = __expf(s[t][2] - mnew1);
            s[t][3] = __expf(s[t][3] - mnew1);
            rs0 += s[t][0] + s[t][1];
            rs1 += s[t][2] + s[t][3];
        }
        rs0 += __shfl_xor_sync(0xffffffffu, rs0, 1);
        rs0 += __shfl_xor_sync(0xffffffffu, rs0, 2);
        rs1 += __shfl_xor_sync(0xffffffffu, rs1, 1);
        rs1 += __shfl_xor_sync(0xffffffffu, rs1, 2);

        l0 = l0 * corr0 + rs0;
        l1 = l1 * corr1 + rs1;
        #pragma unroll
        for (int t = 0; t < 8; t++) {
            o[t][0] *= corr0; o[t][1] *= corr0;
            o[t][2] *= corr1; o[t][3] *= corr1;
        }
        m0 = mnew0; m1 = mnew1;

        #pragma unroll
        for (int ks = 0; ks < 4; ks++) {
            uint32_t a0 = packh2(s[2*ks+0][0], s[2*ks+0][1]);
            uint32_t a1 = packh2(s[2*ks+0][2], s[2*ks+0][3]);
            uint32_t a2 = packh2(s[2*ks+1][0], s[2*ks+1][1]);
            uint32_t a3 = packh2(s[2*ks+1][2], s[2*ks+1][3]);

            uint32_t bf[8][2];
            #pragma unroll
            for (int j = 0; j < 4; j++) {
                uint32_t r0, r1, r2, r3;
                uint32_t addr = sV + ((b_rel[j] + b_kb + ks * 32) ^ b_xr[j]);
                LDMATRIX_X4(r0, r1, r2, r3, addr);
                bf[2*j+0][0] = r0; bf[2*j+0][1] = r1;
                bf[2*j+1][0] = r2; bf[2*j+1][1] = r3;
            }
            #pragma unroll
            for (int t = 0; t < 8; t++)
                MMA_F16(o[t][0], o[t][1], o[t][2], o[t][3],
                        a0, a1, a2, a3, bf[t][0], bf[t][1]);
        }

        __syncthreads();
        const int pf = kt + 2;
        if (pf < NT) { load_KV(pf & 1, pf); CP_COMMIT(); }
    }

    const float inv0 = 1.0f / l0;
    const float inv1 = 1.0f / l1;
    const int qa = q0 + wid * 16 + gid;
    __half* orow0 = O + (size_t)(b * SEQ + qa)     * DMODEL + h * HD;
    __half* orow1 = O + (size_t)(b * SEQ + qa + 8) * DMODEL + h * HD;
    #pragma unroll
    for (int t = 0; t < 8; t++) {
        const int col = t * 8 + 2 * tg;
        *(__half2*)(orow0 + col) = __floats2half2_rn(o[t][0] * inv0, o[t][1] * inv0);
        *(__half2*)(orow1 + col) = __floats2half2_rn(o[t][2] * inv1, o[t][3] * inv1);
    }
}

// ---------------------------------------------------------------------------
// Transpose helpers
// ---------------------------------------------------------------------------
__global__ __launch_bounds__(256)
void transpose_k(const float* __restrict__ in, __half* __restrict__ out, int K, int N)
{
    __shared__ float tile[32][33];
    const int k0 = blockIdx.y * 32, n0 = blockIdx.x * 32;
    const int tx = threadIdx.x, ty = threadIdx.y;
    #pragma unroll
    for (int i = ty; i < 32; i += 8)
        tile[i][tx] = in[(size_t)(k0 + i) * N + n0 + tx];
    __syncthreads();
    #pragma unroll
    for (int i = ty; i < 32; i += 8)
        out[(size_t)(n0 + i) * K + k0 + tx] = __float2half_rn(tile[tx][i]);
}

// V slice of fused half qkv -> g_vth[bh][64][2048] half
__global__ __launch_bounds__(256)
void transpose_vt(const __half* __restrict__ qkv, __half* __restrict__ vt)
{
    __shared__ __half tile[32][34];
    const int s0 = blockIdx.x * 32;
    const int d0 = blockIdx.y * 32;
    const int bh = blockIdx.z;
    const int b = bh >> 4, h = bh & 15;
    const int tx = threadIdx.x, ty = threadIdx.y;
    const __half* in = qkv + (size_t)b * SEQ * QLD + 2 * DMODEL + h * HD;
    __half* out = vt + (size_t)bh * HD * SEQ;
    #pragma unroll
    for (int i = ty; i < 32; i += 8)
        tile[i][tx] = in[(size_t)(s0 + i) * QLD + d0 + tx];
    __syncthreads();
    #pragma unroll
    for (int i = ty; i < 32; i += 8)
        out[(size_t)(d0 + i) * SEQ + s0 + tx] = tile[tx][i];
}

__global__ void concat_bias(const float* a, const float* b, const float* c, float* out)
{
    int i = blockIdx.x * 256 + threadIdx.x;
    if (i < DMODEL)            out[i] = a[i];
    else if (i < 2 * DMODEL)   out[i] = b[i - DMODEL];
    else if (i < 3 * DMODEL)   out[i] = c[i - 2 * DMODEL];
}

// Half copy: out[i] = half(in[i]).
__global__ __launch_bounds__(256)
void half_copy(const float* __restrict__ in, __half* __restrict__ out, int n4)
{
    int i = blockIdx.x * 256 + threadIdx.x;
    if (i < n4) {
        float4 v = ((const float4*)in)[i];
        __half2* o = (__half2*)out + i * 2;
        o[0] = __floats2half2_rn(v.x, v.y);
        o[1] = __floats2half2_rn(v.z, v.w);
    }
}

// ---------------------------------------------------------------------------
// Fused residual add + LayerNorm. Optionally writes a half copy for fp16 GEMM A.
// ---------------------------------------------------------------------------
__global__ __launch_bounds__(256)
void add_ln(const float* __restrict__ A, const float* __restrict__ Bv,
            const float* __restrict__ g, const float* __restrict__ be,
            float* __restrict__ out, __half* __restrict__ out_h)
{
    const int row = blockIdx.x;
    const int tid = threadIdx.x;

    const float4 a4 = ((const float4*)(A  + (size_t)row * DMODEL))[tid];
    const float4 b4 = ((const float4*)(Bv + (size_t)row * DMODEL))[tid];
    float4 v;
    v.x = a4.x + b4.x; v.y = a4.y + b4.y; v.z = a4.z + b4.z; v.w = a4.w + b4.w;

    float s  = v.x + v.y + v.z + v.w;
    float ss = v.x*v.x + v.y*v.y + v.z*v.z + v.w*v.w;

    #pragma unroll
    for (int ofs = 16; ofs > 0; ofs >>= 1) {
        s  += __shfl_xor_sync(0xFFFFFFFFu, s,  ofs);
        ss += __shfl_xor_sync(0xFFFFFFFFu, ss, ofs);
    }

    __shared__ float shs[8], shss[8];
    const int w = tid >> 5;
    if ((tid & 31) == 0) { shs[w] = s; shss[w] = ss; }
    __syncthreads();
    if (tid < 32) {
        float s2  = (tid < 8) ? shs[tid]  : 0.f;
        float ss2 = (tid < 8) ? shss[tid] : 0.f;
        #pragma unroll
        for (int ofs = 4; ofs > 0; ofs >>= 1) {
            s2  += __shfl_xor_sync(0xFFFFFFFFu, s2,  ofs);
            ss2 += __shfl_xor_sync(0xFFFFFFFFu, ss2, ofs);
        }
        if (tid == 0) { shs[0] = s2; shss[0] = ss2; }
    }
    __syncthreads();

    const float mu  = shs[0]  * (1.f / DMODEL);
    const float var = shss[0] * (1.f / DMODEL) - mu * mu;
    const float inv = rsqrtf(var + 1e-5f);

    const float4 gv = ((const float4*)g)[tid];
    const float4 bb = ((const float4*)be)[tid];
    float4 o;
    o.x = (v.x - mu) * inv * gv.x + bb.x;
    o.y = (v.y - mu) * inv * gv.y + bb.y;
    o.z = (v.z - mu) * inv * gv.z + bb.z;
    o.w = (v.w - mu) * inv * gv.w + bb.w;
    ((float4*)(out + (size_t)row * DMODEL))[tid] = o;
    if (out_h) {
        __half2* oh = (__half2*)(out_h + (size_t)row * DMODEL) + tid * 2;
        oh[0] = __floats2half2_rn(o.x, o.y);
        oh[1] = __floats2half2_rn(o.z, o.w);
    }
}

// ---------------------------------------------------------------------------
// Launch
// ---------------------------------------------------------------------------
extern "C" void kernel_launch(void* const* d_in, const int* in_sizes, int n_in,
                              void* d_out, int out_size)
{
    const float* src  = (const float*)d_in[0];
    const float* Wq   = (const float*)d_in[1];
    const float* bq   = (const float*)d_in[2];
    const float* Wk   = (const float*)d_in[3];
    const float* bk   = (const float*)d_in[4];
    const float* Wv   = (const float*)d_in[5];
    const float* bv   = (const float*)d_in[6];
    const float* Wo   = (const float*)d_in[7];
    const float* bo   = (const float*)d_in[8];
    const float* W1   = (const float*)d_in[9];
    const float* b1   = (const float*)d_in[10];
    const float* W2   = (const float*)d_in[11];
    const float* b2   = (const float*)d_in[12];
    const float* ln1g = (const float*)d_in[13];
    const float* ln1b = (const float*)d_in[14];
    const float* ln2g = (const float*)d_in[15];
    const float* ln2b = (const float*)d_in[16];
    float* out = (float*)d_out;

    float  *pbqkv, *ptmp, *px;
    __half *pqkvh, *pvth, *psrcr, *pxr, *pwqkvT, *pwoT, *pw1T, *pw2T, *pctx, *pff;
    cudaGetSymbolAddress((void**)&pqkvh,  g_qkvh);
    cudaGetSymbolAddress((void**)&pvth,   g_vth);
    cudaGetSymbolAddress((void**)&psrcr,  g_srcr);
    cudaGetSymbolAddress((void**)&pxr,    g_xr);
    cudaGetSymbolAddress((void**)&pwqkvT, g_wqkvT);
    cudaGetSymbolAddress((void**)&pwoT,   g_woT);
    cudaGetSymbolAddress((void**)&pw1T,   g_w1T);
    cudaGetSymbolAddress((void**)&pw2T,   g_w2T);
    cudaGetSymbolAddress((void**)&pbqkv,  g_bqkv);
    cudaGetSymbolAddress((void**)&pctx,   g_ctx);
    cudaGetSymbolAddress((void**)&ptmp,   g_tmp);
    cudaGetSymbolAddress((void**)&px,     g_x);
    cudaGetSymbolAddress((void**)&pff,    g_ff);

    cudaFuncSetAttribute((const void*)gemm_mma<false,0>, cudaFuncAttributeMaxDynamicSharedMemorySize, SMEM_DYN);
    cudaFuncSetAttribute((const void*)gemm_mma<false,2>, cudaFuncAttributeMaxDynamicSharedMemorySize, SMEM_DYN);
    cudaFuncSetAttribute((const void*)gemm_mma<true,2>,  cudaFuncAttributeMaxDynamicSharedMemorySize, SMEM_DYN);
    cudaFuncSetAttribute((const void*)flash_mma, cudaFuncAttributeMaxDynamicSharedMemorySize, ATT_SMEM);

    // Pre-converted inputs + weight transposes (to K-major [N,K], half)
    {
        dim3 blk(32, 8);
        half_copy<<<(NTOK * DMODEL / 4 + 255) / 256, 256>>>(src, psrcr, NTOK * DMODEL / 4);
        transpose_k<<<dim3(32, 32),  blk>>>(Wq, pwqkvT,                       DMODEL, DMODEL);
        transpose_k<<<dim3(32, 32),  blk>>>(Wk, pwqkvT + DMODEL * DMODEL,     DMODEL, DMODEL);
        transpose_k<<<dim3(32, 32),  blk>>>(Wv, pwqkvT + 2 * DMODEL * DMODEL, DMODEL, DMODEL);
        transpose_k<<<dim3(32, 32),  blk>>>(Wo, pwoT,  DMODEL, DMODEL);
        transpose_k<<<dim3(128, 32), blk>>>(W1, pw1T,  DMODEL, DFF);
        transpose_k<<<dim3(32, 128), blk>>>(W2, pw2T,  DFF,    DMODEL);
        concat_bias<<<12, 256>>>(bq, bk, bv, pbqkv);
    }

    // Fused QKV projection (half in, half out: feeds fp16 flash)
    gemm_mma<false, 2><<<dim3(3 * DMODEL / 128, NTOK / 256), 512, SMEM_DYN>>>(
        psrcr, pwqkvT, pbqkv, pqkvh, NTOK, 3 * DMODEL, DMODEL);

    // V^T (half) for attention PV operand
    transpose_vt<<<dim3(SEQ / 32, HD / 32, 32), dim3(32, 8)>>>(pqkvh, pvth);

    // fp16 flash attention (128 queries/block; half ctx out)
    flash_mma<<<dim3(SEQ / 128, 2 * NHEAD), 256, ATT_SMEM>>>(pqkvh, pvth, pctx);

    // Output projection (half A, fp32 out) + LN1 (writes half copy for FFN1)
    gemm_mma<false, 0><<<dim3(DMODEL / 128, NTOK / 256), 512, SMEM_DYN>>>(
        pctx, pwoT, bo, ptmp, NTOK, DMODEL, DMODEL);
    add_ln<<<NTOK, 256>>>(src, ptmp, ln1g, ln1b, px, pxr);

    // FFN
    gemm_mma<true, 2><<<dim3(DFF / 128, NTOK / 256), 512, SMEM_DYN>>>(
        pxr, pw1T, b1, pff, NTOK, DFF, DMODEL);
    gemm_mma<false, 0><<<dim3(DMODEL / 128, NTOK / 256), 512, SMEM_DYN>>>(
        pff, pw2T, b2, ptmp, NTOK, DMODEL, DFF);
    add_ln<<<NTOK, 256>>>(px, ptmp, ln2g, ln2b, out, (__half*)nullptr);
}

// round 14
// speedup vs baseline: 2.5759x; 1.0267x over previous
#include <cuda_runtime.h>
#include <cuda_fp16.h>
#include <math.h>
#include <stdint.h>

// Problem constants
#define NTOK   4096      // B*S = 2*2048
#define DMODEL 1024
#define DFF    4096
#define NHEAD  16
#define HD     64
#define SEQ    2048
#define QLD    (3 * DMODEL)   // fused qkv row stride

// ---------------------------------------------------------------------------
// Scratch (static device globals; no runtime allocation allowed)
// ---------------------------------------------------------------------------
__device__ __align__(16) __half g_qkvh[NTOK * 3 * DMODEL];    // fused q|k|v half
__device__ __align__(16) __half g_srcr[NTOK * DMODEL];        // half src (QKV A)
__device__ __align__(16) __half g_xr  [NTOK * DMODEL];        // half LN1 out (FFN1 A)
__device__ __align__(16) __half g_wqkvT[3 * DMODEL * DMODEL]; // [3072,1024] K-major half
__device__ __align__(16) __half g_woT [DMODEL * DMODEL];
__device__ __align__(16) __half g_w1T [DFF * DMODEL];
__device__ __align__(16) __half g_w2T [DMODEL * DFF];
__device__ __align__(16) float  g_bqkv[3 * DMODEL];
__device__ __align__(16) __half g_ctx [NTOK * DMODEL];        // half flash output (O-proj A)
__device__ __align__(16) float  g_tmp [NTOK * DMODEL];
__device__ __align__(16) float  g_x   [NTOK * DMODEL];
__device__ __align__(16) __half g_ff  [NTOK * DFF];           // half FFN1 output (FFN2 A)

// ---------------------------------------------------------------------------
// PTX helpers
// ---------------------------------------------------------------------------
__device__ __forceinline__ uint32_t smem_u32(const void* p) {
    uint32_t a;
    asm("{ .reg .u64 t; cvta.to.shared.u64 t, %1; cvt.u32.u64 %0, t; }" : "=r"(a) : "l"(p));
    return a;
}
#define CP_ASYNC16(dst, src) \
    asm volatile("cp.async.cg.shared.global [%0], [%1], 16;" :: "r"(dst), "l"(src))
#define CP_COMMIT() asm volatile("cp.async.commit_group;" ::: "memory")
#define CP_WAIT(n)  asm volatile("cp.async.wait_group %0;" :: "n"(n) : "memory")

#define LDMATRIX_X4(r0, r1, r2, r3, addr) \
    asm volatile("ldmatrix.sync.aligned.m8n8.x4.shared.b16 {%0,%1,%2,%3}, [%4];" \
                 : "=r"(r0), "=r"(r1), "=r"(r2), "=r"(r3) : "r"(addr))

#define LDMATRIX_X4_TRANS(r0, r1, r2, r3, addr) \
    asm volatile("ldmatrix.sync.aligned.m8n8.x4.trans.shared.b16 {%0,%1,%2,%3}, [%4];" \
                 : "=r"(r0), "=r"(r1), "=r"(r2), "=r"(r3) : "r"(addr))

#define MMA_F16(c0, c1, c2, c3, a0, a1, a2, a3, b0, b1) \
    asm volatile("mma.sync.aligned.m16n8k16.row.col.f32.f16.f16.f32 " \
                 "{%0,%1,%2,%3}, {%4,%5,%6,%7}, {%8,%9}, {%0,%1,%2,%3};" \
                 : "+f"(c0), "+f"(c1), "+f"(c2), "+f"(c3) \
                 : "r"(a0), "r"(a1), "r"(a2), "r"(a3), "r"(b0), "r"(b1))

__device__ __forceinline__ uint32_t packh2(float x, float y) {
    __half2 h = __floats2half2_rn(x, y);
    return *(uint32_t*)&h;
}

// ---------------------------------------------------------------------------
// fp16 tensor-core GEMM (R13-proven):  C = A @ BT^T + bias.  A,BT half.
// 256x128 block tile, K-chunk 64, 512 threads (16 warps, warp tile 64x32),
// 3-stage cp.async, one barrier per iteration. OUTM: 0 = fp32, 2 = half.
// ---------------------------------------------------------------------------
#define STAGES 3
#define A_ST_BYTES (256 * 128)
#define B_ST_BYTES (128 * 128)
#define STAGE_BYTES (A_ST_BYTES + B_ST_BYTES)
#define SMEM_DYN (STAGES * STAGE_BYTES)      // 144KB

template <bool RELU, int OUTM>
__global__ __launch_bounds__(512, 1)
void gemm_mma(const __half* __restrict__ A, const __half* __restrict__ BT,
              const float* __restrict__ bias, void* __restrict__ Cv,
              int M, int N, int K)
{
    extern __shared__ char smem[];
    const uint32_t sbase = smem_u32(smem);
    const int tid  = threadIdx.x;
    const int wid  = tid >> 5;
    const int lane = tid & 31;
    const int warp_m = wid & 3;
    const int warp_n = wid >> 2;
    const int gid = lane >> 2;
    const int tg  = lane & 3;

    const int bm = blockIdx.y * 256;
    const int bn = blockIdx.x * 128;
    const int KT = K >> 6;

    const int arow = tid >> 1;
    const int au0  = (tid & 1) * 4;
    const __half* Ag = A + (size_t)(bm + arow) * K + au0 * 8;
    uint32_t aswz[4];
    #pragma unroll
    for (int i = 0; i < 4; i++) {
        uint32_t off = arow * 128 + (au0 + i) * 16;
        aswz[i] = off ^ ((off >> 3) & 0x70);
    }
    const int brow = tid >> 2;
    const int bu0  = (tid & 3) * 2;
    const __half* Bg = BT + (size_t)(bn + brow) * K + bu0 * 8;
    uint32_t bswz[2];
    #pragma unroll
    for (int i = 0; i < 2; i++) {
        uint32_t off = brow * 128 + (bu0 + i) * 16;
        bswz[i] = off ^ ((off >> 3) & 0x70);
    }

    uint32_t a_rel[4], a_xr[4];
    #pragma unroll
    for (int i = 0; i < 4; i++) {
        int r = warp_m * 64 + i * 16 + (lane & 7) + ((lane >> 3) & 1) * 8;
        a_rel[i] = r * 128;
        a_xr[i]  = (r & 7) << 4;
    }
    const uint32_t a_kb = ((lane >> 4) & 1) * 16;
    uint32_t b_rel[2], b_xr[2];
    #pragma unroll
    for (int j = 0; j < 2; j++) {
        int r = warp_n * 32 + j * 16 + (lane & 7) + ((lane >> 4) & 1) * 8;
        b_rel[j] = r * 128;
        b_xr[j]  = (r & 7) << 4;
    }
    const uint32_t b_kb = ((lane >> 3) & 1) * 16;

    float acc[4][4][4];
    #pragma unroll
    for (int i = 0; i < 4; i++)
        #pragma unroll
        for (int t = 0; t < 4; t++)
            #pragma unroll
            for (int r = 0; r < 4; r++) acc[i][t][r] = 0.f;

    auto load_tile = [&](int s, int kt) {
        const uint32_t sA = sbase + s * STAGE_BYTES;
        const uint32_t sB = sA + A_ST_BYTES;
        const __half* ar = Ag + kt * 64;
        const __half* br = Bg + kt * 64;
        #pragma unroll
        for (int i = 0; i < 4; i++) CP_ASYNC16(sA + aswz[i], ar + i * 8);
        #pragma unroll
        for (int i = 0; i < 2; i++) CP_ASYNC16(sB + bswz[i], br + i * 8);
    };

    #pragma unroll
    for (int s = 0; s < STAGES - 1; s++) { load_tile(s, s); CP_COMMIT(); }

    int cur = 0, pfs = STAGES - 1;
    for (int kt = 0; kt < KT; kt++) {
        CP_WAIT(STAGES - 2);
        __syncthreads();

        const int pf = kt + STAGES - 1;
        if (pf < KT) load_tile(pfs, pf);
        CP_COMMIT();

        const uint32_t sA = sbase + cur * STAGE_BYTES;
        const uint32_t sB = sA + A_ST_BYTES;

        #pragma unroll
        for (int ks = 0; ks < 4; ks++) {
            const uint32_t kso = ks * 32;
            uint32_t af[4][4];
            #pragma unroll
            for (int i = 0; i < 4; i++) {
                uint32_t addr = sA + ((a_rel[i] + a_kb + kso) ^ a_xr[i]);
                LDMATRIX_X4(af[i][0], af[i][1], af[i][2], af[i][3], addr);
            }
            uint32_t bf[4][2];
            #pragma unroll
            for (int j = 0; j < 2; j++) {
                uint32_t r0, r1, r2, r3;
                uint32_t addr = sB + ((b_rel[j] + b_kb + kso) ^ b_xr[j]);
                LDMATRIX_X4(r0, r1, r2, r3, addr);
                bf[2*j+0][0] = r0; bf[2*j+0][1] = r1;
                bf[2*j+1][0] = r2; bf[2*j+1][1] = r3;
            }
            #pragma unroll
            for (int i = 0; i < 4; i++)
                #pragma unroll
                for (int t = 0; t < 4; t++)
                    MMA_F16(acc[i][t][0], acc[i][t][1], acc[i][t][2], acc[i][t][3],
                            af[i][0], af[i][1], af[i][2], af[i][3],
                            bf[t][0], bf[t][1]);
        }
        cur++; if (cur == STAGES) cur = 0;
        pfs++; if (pfs == STAGES) pfs = 0;
    }

    #pragma unroll
    for (int i = 0; i < 4; i++) {
        const int row0 = bm + warp_m * 64 + i * 16 + gid;
        #pragma unroll
        for (int t = 0; t < 4; t++) {
            const int col = bn + warp_n * 32 + t * 8 + 2 * tg;
            const float2 bv = *(const float2*)(bias + col);
            float2 v0, v1;
            v0.x = acc[i][t][0] + bv.x; v0.y = acc[i][t][1] + bv.y;
            v1.x = acc[i][t][2] + bv.x; v1.y = acc[i][t][3] + bv.y;
            if (RELU) {
                v0.x = fmaxf(v0.x, 0.f); v0.y = fmaxf(v0.y, 0.f);
                v1.x = fmaxf(v1.x, 0.f); v1.y = fmaxf(v1.y, 0.f);
            }
            if (OUTM == 2) {
                __half* Ch = (__half*)Cv;
                *(__half2*)(Ch + (size_t)row0 * N + col)       = __floats2half2_rn(v0.x, v0.y);
                *(__half2*)(Ch + (size_t)(row0 + 8) * N + col) = __floats2half2_rn(v1.x, v1.y);
            } else {
                float* Cf = (float*)Cv;
                *(float2*)(Cf + (size_t)row0 * N + col)       = v0;
                *(float2*)(Cf + (size_t)(row0 + 8) * N + col) = v1;
            }
        }
    }
}

// ---------------------------------------------------------------------------
// fp16 tensor-core flash attention. 128 queries x 1 head, 8 warps.
// K AND V both loaded row-major from fused qkv; PV B-fragments via
// ldmatrix.x4.trans (no V^T pre-transpose kernel needed).
// ---------------------------------------------------------------------------
#define ATT_SMEM 49152   // 2 stages x (8KB K + 8KB V) + 16KB Q

__global__ __launch_bounds__(256, 2)
void flash_mma(const __half* __restrict__ QKV, __half* __restrict__ O)
{
    extern __shared__ char smem[];
    const uint32_t sbase = smem_u32(smem);
    const int tid  = threadIdx.x;
    const int wid  = tid >> 5;
    const int lane = tid & 31;
    const int gid  = lane >> 2;
    const int tg   = lane & 3;

    const int bh = blockIdx.y;
    const int b  = bh >> 4;
    const int h  = bh & 15;
    const int q0 = blockIdx.x * 128;

    const __half* Qg = QKV + (size_t)b * SEQ * QLD + h * HD;
    const __half* Kg = Qg + DMODEL;
    const __half* Vg = Qg + 2 * DMODEL;

    const uint32_t qreg = sbase + 32768;

    const int qrow = tid >> 1;
    const int qu0  = (tid & 1) * 4;
    uint32_t qsw[4];
    #pragma unroll
    for (int i = 0; i < 4; i++) {
        uint32_t off = qrow * 128 + (qu0 + i) * 16;
        qsw[i] = off ^ ((off >> 3) & 0x70);
    }
    const int krow = tid >> 2;
    const int ku0  = (tid & 3) * 2;
    uint32_t kvsw[2];
    #pragma unroll
    for (int i = 0; i < 2; i++) {
        uint32_t off = krow * 128 + (ku0 + i) * 16;
        kvsw[i] = off ^ ((off >> 3) & 0x70);
    }

    uint32_t aq_rel, aq_xr;
    {
        int r = wid * 16 + (lane & 7) + ((lane >> 3) & 1) * 8;
        aq_rel = r * 128;
        aq_xr  = (r & 7) << 4;
    }
    const uint32_t a_kb = ((lane >> 4) & 1) * 16;
    // K (non-trans) fragment addressing
    uint32_t b_rel[4], b_xr[4];
    #pragma unroll
    for (int j = 0; j < 4; j++) {
        int r = j * 16 + (lane & 7) + ((lane >> 4) & 1) * 8;
        b_rel[j] = r * 128;
        b_xr[j]  = (r & 7) << 4;
    }
    const uint32_t b_kb = ((lane >> 3) & 1) * 16;
    // V (trans) fragment addressing: source rows = keys, cols = dims.
    // lane-groups: 0-7 (k lo, d lo) -> r0; 8-15 (k hi, d lo) -> r1;
    //              16-23 (k lo, d hi) -> r2; 24-31 (k hi, d hi) -> r3.
    uint32_t v_rel[4];
    #pragma unroll
    for (int j = 0; j < 4; j++) {
        int kr = ((lane >> 3) & 1) * 8 + (lane & 7);      // source key row
        int dc = j * 16 + ((lane >> 4) & 1) * 8;          // dim column (halves)
        v_rel[j] = kr * 128 + dc * 2;
    }

    auto load_KV = [&](int stage, int kt) {
        const uint32_t sK = sbase + stage * 16384;
        const uint32_t sV = sK + 8192;
        const __half* kr = Kg + (size_t)(kt * 64 + krow) * QLD + ku0 * 8;
        const __half* vr = Vg + (size_t)(kt * 64 + krow) * QLD + ku0 * 8;
        #pragma unroll
        for (int i = 0; i < 2; i++) CP_ASYNC16(sK + kvsw[i], kr + i * 8);
        #pragma unroll
        for (int i = 0; i < 2; i++) CP_ASYNC16(sV + kvsw[i], vr + i * 8);
    };

    {
        const __half* qr = Qg + (size_t)(q0 + qrow) * QLD + qu0 * 8;
        #pragma unroll
        for (int i = 0; i < 4; i++) CP_ASYNC16(qreg + qsw[i], qr + i * 8);
        load_KV(0, 0);
        CP_COMMIT();
        CP_WAIT(0);
        __syncthreads();
    }

    uint32_t qf[4][4];
    #pragma unroll
    for (int ks = 0; ks < 4; ks++) {
        uint32_t addr = qreg + ((aq_rel + a_kb + ks * 32) ^ aq_xr);
        LDMATRIX_X4(qf[ks][0], qf[ks][1], qf[ks][2], qf[ks][3], addr);
    }
    __syncthreads();

    const int NT = SEQ / 64;
    load_KV(1, 1);
    CP_COMMIT();

    float o[8][4];
    #pragma unroll
    for (int t = 0; t < 8; t++)
        #pragma unroll
        for (int r = 0; r < 4; r++) o[t][r] = 0.f;
    float m0 = -1e30f, m1 = -1e30f, l0 = 0.f, l1 = 0.f;

    for (int kt = 0; kt < NT; kt++) {
        if (kt < NT - 1) { CP_WAIT(1); } else { CP_WAIT(0); }
        __syncthreads();
        const uint32_t sK = sbase + (kt & 1) * 16384;
        const uint32_t sV = sK + 8192;

        float s[8][4];
        #pragma unroll
        for (int t = 0; t < 8; t++)
            #pragma unroll
            for (int r = 0; r < 4; r++) s[t][r] = 0.f;

        #pragma unroll
        for (int ks = 0; ks < 4; ks++) {
            uint32_t bf[8][2];
            #pragma unroll
            for (int j = 0; j < 4; j++) {
                uint32_t r0, r1, r2, r3;
                uint32_t addr = sK + ((b_rel[j] + b_kb + ks * 32) ^ b_xr[j]);
                LDMATRIX_X4(r0, r1, r2, r3, addr);
                bf[2*j+0][0] = r0; bf[2*j+0][1] = r1;
                bf[2*j+1][0] = r2; bf[2*j+1][1] = r3;
            }
            const uint32_t* aq = qf[ks];
            #pragma unroll
            for (int t = 0; t < 8; t++)
                MMA_F16(s[t][0], s[t][1], s[t][2], s[t][3],
                        aq[0], aq[1], aq[2], aq[3], bf[t][0], bf[t][1]);
        }

        float tmax0 = -1e30f, tmax1 = -1e30f;
        #pragma unroll
        for (int t = 0; t < 8; t++) {
            s[t][0] *= 0.125f; s[t][1] *= 0.125f; s[t][2] *= 0.125f; s[t][3] *= 0.125f;
            tmax0 = fmaxf(tmax0, fmaxf(s[t][0], s[t][1]));
            tmax1 = fmaxf(tmax1, fmaxf(s[t][2], s[t][3]));
        }
        tmax0 = fmaxf(tmax0, __shfl_xor_sync(0xffffffffu, tmax0, 1));
        tmax0 = fmaxf(tmax0, __shfl_xor_sync(0xffffffffu, tmax0, 2));
        tmax1 = fmaxf(tmax1, __shfl_xor_sync(0xffffffffu, tmax1, 1));
        tmax1 = fmaxf(tmax1, __shfl_xor_sync(0xffffffffu, tmax1, 2));

        const float mnew0 = fmaxf(m0, tmax0);
        const float mnew1 = fmaxf(m1, tmax1);
        const float corr0 = __expf(m0 - mnew0);
        const float corr1 = __expf(m1 - mnew1);

        float rs0 = 0.f, rs1 = 0.f;
        #pragma unroll
        for (int t = 0; t < 8; t++) {
            s[t][0] = __expf(s[t][0] - mnew0);
            s[t][1] = __expf(s[t][1] - mnew0);
            s[t][2] = __expf(s[t][2] - mnew1);
            s[t][3] = __expf(s[t][3] - mnew1);
            rs0 += s[t][0] + s[t][1];
            rs1 += s[t][2] + s[t][3];
        }
        rs0 += __shfl_xor_sync(0xffffffffu, rs0, 1);
        rs0 += __shfl_xor_sync(0xffffffffu, rs0, 2);
        rs1 += __shfl_xor_sync(0xffffffffu, rs1, 1);
        rs1 += __shfl_xor_sync(0xffffffffu, rs1, 2);

        l0 = l0 * corr0 + rs0;
        l1 = l1 * corr1 + rs1;
        #pragma unroll
        for (int t = 0; t < 8; t++) {
            o[t][0] *= corr0; o[t][1] *= corr0;
            o[t][2] *= corr1; o[t][3] *= corr1;
        }
        m0 = mnew0; m1 = mnew1;

        // ---- ctx += P @ V (V via trans ldmatrix from row-major tile) ----
        #pragma unroll
        for (int ks = 0; ks < 4; ks++) {
            uint32_t a0 = packh2(s[2*ks+0][0], s[2*ks+0][1]);
            uint32_t a1 = packh2(s[2*ks+0][2], s[2*ks+0][3]);
            uint32_t a2 = packh2(s[2*ks+1][0], s[2*ks+1][1]);
            uint32_t a3 = packh2(s[2*ks+1][2], s[2*ks+1][3]);

            uint32_t bf[8][2];
            #pragma unroll
            for (int j = 0; j < 4; j++) {
                uint32_t r0, r1, r2, r3;
                uint32_t off = v_rel[j] + ks * 2048;   // +16 key rows per ks
                uint32_t addr = sV + (off ^ ((off >> 3) & 0x70));
                LDMATRIX_X4_TRANS(r0, r1, r2, r3, addr);
                bf[2*j+0][0] = r0; bf[2*j+0][1] = r1;
                bf[2*j+1][0] = r2; bf[2*j+1][1] = r3;
            }
            #pragma unroll
            for (int t = 0; t < 8; t++)
                MMA_F16(o[t][0], o[t][1], o[t][2], o[t][3],
                        a0, a1, a2, a3, bf[t][0], bf[t][1]);
        }

        __syncthreads();
        const int pf = kt + 2;
        if (pf < NT) { load_KV(pf & 1, pf); CP_COMMIT(); }
    }

    const float inv0 = 1.0f / l0;
    const float inv1 = 1.0f / l1;
    const int qa = q0 + wid * 16 + gid;
    __half* orow0 = O + (size_t)(b * SEQ + qa)     * DMODEL + h * HD;
    __half* orow1 = O + (size_t)(b * SEQ + qa + 8) * DMODEL + h * HD;
    #pragma unroll
    for (int t = 0; t < 8; t++) {
        const int col = t * 8 + 2 * tg;
        *(__half2*)(orow0 + col) = __floats2half2_rn(o[t][0] * inv0, o[t][1] * inv0);
        *(__half2*)(orow1 + col) = __floats2half2_rn(o[t][2] * inv1, o[t][3] * inv1);
    }
}

// ---------------------------------------------------------------------------
// Transpose helpers
// ---------------------------------------------------------------------------
// Batched square transpose: z in {0,1,2} -> wqkvT slices; z=3 -> woT.
__global__ __launch_bounds__(256)
void transpose_k4(const float* __restrict__ w0, const float* __restrict__ w1,
                  const float* __restrict__ w2, const float* __restrict__ w3,
                  __half* __restrict__ oqkv, __half* __restrict__ oo)
{
    __shared__ float tile[32][33];
    const int z = blockIdx.z;
    const float* in = (z == 0) ? w0 : (z == 1) ? w1 : (z == 2) ? w2 : w3;
    __half* out = (z < 3) ? (oqkv + (size_t)z * DMODEL * DMODEL) : oo;
    const int k0 = blockIdx.y * 32, n0 = blockIdx.x * 32;
    const int tx = threadIdx.x, ty = threadIdx.y;
    #pragma unroll
    for (int i = ty; i < 32; i += 8)
        tile[i][tx] = in[(size_t)(k0 + i) * DMODEL + n0 + tx];
    __syncthreads();
    #pragma unroll
    for (int i = ty; i < 32; i += 8)
        out[(size_t)(n0 + i) * DMODEL + k0 + tx] = __float2half_rn(tile[tx][i]);
}

__global__ __launch_bounds__(256)
void transpose_k(const float* __restrict__ in, __half* __restrict__ out, int K, int N)
{
    __shared__ float tile[32][33];
    const int k0 = blockIdx.y * 32, n0 = blockIdx.x * 32;
    const int tx = threadIdx.x, ty = threadIdx.y;
    #pragma unroll
    for (int i = ty; i < 32; i += 8)
        tile[i][tx] = in[(size_t)(k0 + i) * N + n0 + tx];
    __syncthreads();
    #pragma unroll
    for (int i = ty; i < 32; i += 8)
        out[(size_t)(n0 + i) * K + k0 + tx] = __float2half_rn(tile[tx][i]);
}

__global__ void concat_bias(const float* a, const float* b, const float* c, float* out)
{
    int i = blockIdx.x * 256 + threadIdx.x;
    if (i < DMODEL)            out[i] = a[i];
    else if (i < 2 * DMODEL)   out[i] = b[i - DMODEL];
    else if (i < 3 * DMODEL)   out[i] = c[i - 2 * DMODEL];
}

// Half copy: out[i] = half(in[i]).
__global__ __launch_bounds__(256)
void half_copy(const float* __restrict__ in, __half* __restrict__ out, int n4)
{
    int i = blockIdx.x * 256 + threadIdx.x;
    if (i < n4) {
        float4 v = ((const float4*)in)[i];
        __half2* o = (__half2*)out + i * 2;
        o[0] = __floats2half2_rn(v.x, v.y);
        o[1] = __floats2half2_rn(v.z, v.w);
    }
}

// ---------------------------------------------------------------------------
// Fused residual add + LayerNorm. Optionally writes a half copy for fp16 GEMM A.
// ---------------------------------------------------------------------------
__global__ __launch_bounds__(256)
void add_ln(const float* __restrict__ A, const float* __restrict__ Bv,
            const float* __restrict__ g, const float* __restrict__ be,
            float* __restrict__ out, __half* __restrict__ out_h)
{
    const int row = blockIdx.x;
    const int tid = threadIdx.x;

    const float4 a4 = ((const float4*)(A  + (size_t)row * DMODEL))[tid];
    const float4 b4 = ((const float4*)(Bv + (size_t)row * DMODEL))[tid];
    float4 v;
    v.x = a4.x + b4.x; v.y = a4.y + b4.y; v.z = a4.z + b4.z; v.w = a4.w + b4.w;

    float s  = v.x + v.y + v.z + v.w;
    float ss = v.x*v.x + v.y*v.y + v.z*v.z + v.w*v.w;

    #pragma unroll
    for (int ofs = 16; ofs > 0; ofs >>= 1) {
        s  += __shfl_xor_sync(0xFFFFFFFFu, s,  ofs);
        ss += __shfl_xor_sync(0xFFFFFFFFu, ss, ofs);
    }

    __shared__ float shs[8], shss[8];
    const int w = tid >> 5;
    if ((tid & 31) == 0) { shs[w] = s; shss[w] = ss; }
    __syncthreads();
    if (tid < 32) {
        float s2  = (tid < 8) ? shs[tid]  : 0.f;
        float ss2 = (tid < 8) ? shss[tid] : 0.f;
        #pragma unroll
        for (int ofs = 4; ofs > 0; ofs >>= 1) {
            s2  += __shfl_xor_sync(0xFFFFFFFFu, s2,  ofs);
            ss2 += __shfl_xor_sync(0xFFFFFFFFu, ss2, ofs);
        }
        if (tid == 0) { shs[0] = s2; shss[0] = ss2; }
    }
    __syncthreads();

    const float mu  = shs[0]  * (1.f / DMODEL);
    const float var = shss[0] * (1.f / DMODEL) - mu * mu;
    const float inv = rsqrtf(var + 1e-5f);

    const float4 gv = ((const float4*)g)[tid];
    const float4 bb = ((const float4*)be)[tid];
    float4 o;
    o.x = (v.x - mu) * inv * gv.x + bb.x;
    o.y = (v.y - mu) * inv * gv.y + bb.y;
    o.z = (v.z - mu) * inv * gv.z + bb.z;
    o.w = (v.w - mu) * inv * gv.w + bb.w;
    ((float4*)(out + (size_t)row * DMODEL))[tid] = o;
    if (out_h) {
        __half2* oh = (__half2*)(out_h + (size_t)row * DMODEL) + tid * 2;
        oh[0] = __floats2half2_rn(o.x, o.y);
        oh[1] = __floats2half2_rn(o.z, o.w);
    }
}

// ---------------------------------------------------------------------------
// Launch
// ---------------------------------------------------------------------------
extern "C" void kernel_launch(void* const* d_in, const int* in_sizes, int n_in,
                              void* d_out, int out_size)
{
    const float* src  = (const float*)d_in[0];
    const float* Wq   = (const float*)d_in[1];
    const float* bq   = (const float*)d_in[2];
    const float* Wk   = (const float*)d_in[3];
    const float* bk   = (const float*)d_in[4];
    const float* Wv   = (const float*)d_in[5];
    const float* bv   = (const float*)d_in[6];
    const float* Wo   = (const float*)d_in[7];
    const float* bo   = (const float*)d_in[8];
    const float* W1   = (const float*)d_in[9];
    const float* b1   = (const float*)d_in[10];
    const float* W2   = (const float*)d_in[11];
    const float* b2   = (const float*)d_in[12];
    const float* ln1g = (const float*)d_in[13];
    const float* ln1b = (const float*)d_in[14];
    const float* ln2g = (const float*)d_in[15];
    const float* ln2b = (const float*)d_in[16];
    float* out = (float*)d_out;

    float  *pbqkv, *ptmp, *px;
    __half *pqkvh, *psrcr, *pxr, *pwqkvT, *pwoT, *pw1T, *pw2T, *pctx, *pff;
    cudaGetSymbolAddress((void**)&pqkvh,  g_qkvh);
    cudaGetSymbolAddress((void**)&psrcr,  g_srcr);
    cudaGetSymbolAddress((void**)&pxr,    g_xr);
    cudaGetSymbolAddress((void**)&pwqkvT, g_wqkvT);
    cudaGetSymbolAddress((void**)&pwoT,   g_woT);
    cudaGetSymbolAddress((void**)&pw1T,   g_w1T);
    cudaGetSymbolAddress((void**)&pw2T,   g_w2T);
    cudaGetSymbolAddress((void**)&pbqkv,  g_bqkv);
    cudaGetSymbolAddress((void**)&pctx,   g_ctx);
    cudaGetSymbolAddress((void**)&ptmp,   g_tmp);
    cudaGetSymbolAddress((void**)&px,     g_x);
    cudaGetSymbolAddress((void**)&pff,    g_ff);

    cudaFuncSetAttribute((const void*)gemm_mma<false,0>, cudaFuncAttributeMaxDynamicSharedMemorySize, SMEM_DYN);
    cudaFuncSetAttribute((const void*)gemm_mma<false,2>, cudaFuncAttributeMaxDynamicSharedMemorySize, SMEM_DYN);
    cudaFuncSetAttribute((const void*)gemm_mma<true,2>,  cudaFuncAttributeMaxDynamicSharedMemorySize, SMEM_DYN);
    cudaFuncSetAttribute((const void*)flash_mma, cudaFuncAttributeMaxDynamicSharedMemorySize, ATT_SMEM);

    // Pre-converted inputs + weight transposes (to K-major [N,K], half)
    {
        dim3 blk(32, 8);
        half_copy<<<(NTOK * DMODEL / 4 + 255) / 256, 256>>>(src, psrcr, NTOK * DMODEL / 4);
        transpose_k4<<<dim3(32, 32, 4), blk>>>(Wq, Wk, Wv, Wo, pwqkvT, pwoT);
        transpose_k<<<dim3(128, 32), blk>>>(W1, pw1T, DMODEL, DFF);
        transpose_k<<<dim3(32, 128), blk>>>(W2, pw2T, DFF, DMODEL);
        concat_bias<<<12, 256>>>(bq, bk, bv, pbqkv);
    }

    // Fused QKV projection (half in, half out: feeds fp16 flash)
    gemm_mma<false, 2><<<dim3(3 * DMODEL / 128, NTOK / 256), 512, SMEM_DYN>>>(
        psrcr, pwqkvT, pbqkv, pqkvh, NTOK, 3 * DMODEL, DMODEL);

    // fp16 flash attention (128 queries/block; V via trans ldmatrix; half ctx out)
    flash_mma<<<dim3(SEQ / 128, 2 * NHEAD), 256, ATT_SMEM>>>(pqkvh, pctx);

    // Output projection (half A, fp32 out) + LN1 (writes half copy for FFN1)
    gemm_mma<false, 0><<<dim3(DMODEL / 128, NTOK / 256), 512, SMEM_DYN>>>(
        pctx, pwoT, bo, ptmp, NTOK, DMODEL, DMODEL);
    add_ln<<<NTOK, 256>>>(src, ptmp, ln1g, ln1b, px, pxr);

    // FFN
    gemm_mma<true, 2><<<dim3(DFF / 128, NTOK / 256), 512, SMEM_DYN>>>(
        pxr, pw1T, b1, pff, NTOK, DFF, DMODEL);
    gemm_mma<false, 0><<<dim3(DMODEL / 128, NTOK / 256), 512, SMEM_DYN>>>(
        pff, pw2T, b2, ptmp, NTOK, DMODEL, DFF);
    add_ln<<<NTOK, 256>>>(px, ptmp, ln2g, ln2b, out, (__half*)nullptr);
}

// round 15
// speedup vs baseline: 2.6450x; 1.0268x over previous
#include <cuda_runtime.h>
#include <cuda_fp16.h>
#include <math.h>
#include <stdint.h>

// Problem constants
#define NTOK   4096      // B*S = 2*2048
#define DMODEL 1024
#define DFF    4096
#define NHEAD  16
#define HD     64
#define SEQ    2048
#define QLD    (3 * DMODEL)   // fused qkv row stride

// ---------------------------------------------------------------------------
// Scratch (static device globals; no runtime allocation allowed)
// ---------------------------------------------------------------------------
__device__ __align__(16) __half g_qkvh[NTOK * 3 * DMODEL];    // fused q|k|v half
__device__ __align__(16) __half g_srcr[NTOK * DMODEL];        // half src (QKV A)
__device__ __align__(16) __half g_xr  [NTOK * DMODEL];        // half LN1 out (FFN1 A)
__device__ __align__(16) __half g_wqkvT[3 * DMODEL * DMODEL]; // [3072,1024] K-major half
__device__ __align__(16) __half g_woT [DMODEL * DMODEL];
__device__ __align__(16) __half g_w1T [DFF * DMODEL];
__device__ __align__(16) __half g_w2T [DMODEL * DFF];
__device__ __align__(16) float  g_bqkv[3 * DMODEL];
__device__ __align__(16) __half g_ctx [NTOK * DMODEL];        // half flash output (O-proj A)
__device__ __align__(16) float  g_tmp [NTOK * DMODEL];
__device__ __align__(16) float  g_x   [NTOK * DMODEL];
__device__ __align__(16) __half g_ff  [NTOK * DFF];           // half FFN1 output (FFN2 A)

// ---------------------------------------------------------------------------
// PTX helpers
// ---------------------------------------------------------------------------
__device__ __forceinline__ uint32_t smem_u32(const void* p) {
    uint32_t a;
    asm("{ .reg .u64 t; cvta.to.shared.u64 t, %1; cvt.u32.u64 %0, t; }" : "=r"(a) : "l"(p));
    return a;
}
#define CP_ASYNC16(dst, src) \
    asm volatile("cp.async.cg.shared.global [%0], [%1], 16;" :: "r"(dst), "l"(src))
#define CP_COMMIT() asm volatile("cp.async.commit_group;" ::: "memory")
#define CP_WAIT(n)  asm volatile("cp.async.wait_group %0;" :: "n"(n) : "memory")

#define LDMATRIX_X4(r0, r1, r2, r3, addr) \
    asm volatile("ldmatrix.sync.aligned.m8n8.x4.shared.b16 {%0,%1,%2,%3}, [%4];" \
                 : "=r"(r0), "=r"(r1), "=r"(r2), "=r"(r3) : "r"(addr))

#define LDMATRIX_X4_TRANS(r0, r1, r2, r3, addr) \
    asm volatile("ldmatrix.sync.aligned.m8n8.x4.trans.shared.b16 {%0,%1,%2,%3}, [%4];" \
                 : "=r"(r0), "=r"(r1), "=r"(r2), "=r"(r3) : "r"(addr))

#define MMA_F16(c0, c1, c2, c3, a0, a1, a2, a3, b0, b1) \
    asm volatile("mma.sync.aligned.m16n8k16.row.col.f32.f16.f16.f32 " \
                 "{%0,%1,%2,%3}, {%4,%5,%6,%7}, {%8,%9}, {%0,%1,%2,%3};" \
                 : "+f"(c0), "+f"(c1), "+f"(c2), "+f"(c3) \
                 : "r"(a0), "r"(a1), "r"(a2), "r"(a3), "r"(b0), "r"(b1))

__device__ __forceinline__ uint32_t packh2(float x, float y) {
    __half2 h = __floats2half2_rn(x, y);
    return *(uint32_t*)&h;
}

// ---------------------------------------------------------------------------
// fp16 tensor-core GEMM (R13-proven):  C = A @ BT^T + bias.  A,BT half.
// 256x128 block tile, K-chunk 64, 512 threads (16 warps, warp tile 64x32),
// 3-stage cp.async, one barrier per iteration. OUTM: 0 = fp32, 2 = half.
// ---------------------------------------------------------------------------
#define STAGES 3
#define A_ST_BYTES (256 * 128)
#define B_ST_BYTES (128 * 128)
#define STAGE_BYTES (A_ST_BYTES + B_ST_BYTES)
#define SMEM_DYN (STAGES * STAGE_BYTES)      // 144KB

template <bool RELU, int OUTM>
__global__ __launch_bounds__(512, 1)
void gemm_mma(const __half* __restrict__ A, const __half* __restrict__ BT,
              const float* __restrict__ bias, void* __restrict__ Cv,
              int M, int N, int K)
{
    extern __shared__ char smem[];
    const uint32_t sbase = smem_u32(smem);
    const int tid  = threadIdx.x;
    const int wid  = tid >> 5;
    const int lane = tid & 31;
    const int warp_m = wid & 3;
    const int warp_n = wid >> 2;
    const int gid = lane >> 2;
    const int tg  = lane & 3;

    const int bm = blockIdx.y * 256;
    const int bn = blockIdx.x * 128;
    const int KT = K >> 6;

    const int arow = tid >> 1;
    const int au0  = (tid & 1) * 4;
    const __half* Ag = A + (size_t)(bm + arow) * K + au0 * 8;
    uint32_t aswz[4];
    #pragma unroll
    for (int i = 0; i < 4; i++) {
        uint32_t off = arow * 128 + (au0 + i) * 16;
        aswz[i] = off ^ ((off >> 3) & 0x70);
    }
    const int brow = tid >> 2;
    const int bu0  = (tid & 3) * 2;
    const __half* Bg = BT + (size_t)(bn + brow) * K + bu0 * 8;
    uint32_t bswz[2];
    #pragma unroll
    for (int i = 0; i < 2; i++) {
        uint32_t off = brow * 128 + (bu0 + i) * 16;
        bswz[i] = off ^ ((off >> 3) & 0x70);
    }

    uint32_t a_rel[4], a_xr[4];
    #pragma unroll
    for (int i = 0; i < 4; i++) {
        int r = warp_m * 64 + i * 16 + (lane & 7) + ((lane >> 3) & 1) * 8;
        a_rel[i] = r * 128;
        a_xr[i]  = (r & 7) << 4;
    }
    const uint32_t a_kb = ((lane >> 4) & 1) * 16;
    uint32_t b_rel[2], b_xr[2];
    #pragma unroll
    for (int j = 0; j < 2; j++) {
        int r = warp_n * 32 + j * 16 + (lane & 7) + ((lane >> 4) & 1) * 8;
        b_rel[j] = r * 128;
        b_xr[j]  = (r & 7) << 4;
    }
    const uint32_t b_kb = ((lane >> 3) & 1) * 16;

    float acc[4][4][4];
    #pragma unroll
    for (int i = 0; i < 4; i++)
        #pragma unroll
        for (int t = 0; t < 4; t++)
            #pragma unroll
            for (int r = 0; r < 4; r++) acc[i][t][r] = 0.f;

    auto load_tile = [&](int s, int kt) {
        const uint32_t sA = sbase + s * STAGE_BYTES;
        const uint32_t sB = sA + A_ST_BYTES;
        const __half* ar = Ag + kt * 64;
        const __half* br = Bg + kt * 64;
        #pragma unroll
        for (int i = 0; i < 4; i++) CP_ASYNC16(sA + aswz[i], ar + i * 8);
        #pragma unroll
        for (int i = 0; i < 2; i++) CP_ASYNC16(sB + bswz[i], br + i * 8);
    };

    #pragma unroll
    for (int s = 0; s < STAGES - 1; s++) { load_tile(s, s); CP_COMMIT(); }

    int cur = 0, pfs = STAGES - 1;
    for (int kt = 0; kt < KT; kt++) {
        CP_WAIT(STAGES - 2);
        __syncthreads();

        const int pf = kt + STAGES - 1;
        if (pf < KT) load_tile(pfs, pf);
        CP_COMMIT();

        const uint32_t sA = sbase + cur * STAGE_BYTES;
        const uint32_t sB = sA + A_ST_BYTES;

        #pragma unroll
        for (int ks = 0; ks < 4; ks++) {
            const uint32_t kso = ks * 32;
            uint32_t af[4][4];
            #pragma unroll
            for (int i = 0; i < 4; i++) {
                uint32_t addr = sA + ((a_rel[i] + a_kb + kso) ^ a_xr[i]);
                LDMATRIX_X4(af[i][0], af[i][1], af[i][2], af[i][3], addr);
            }
            uint32_t bf[4][2];
            #pragma unroll
            for (int j = 0; j < 2; j++) {
                uint32_t r0, r1, r2, r3;
                uint32_t addr = sB + ((b_rel[j] + b_kb + kso) ^ b_xr[j]);
                LDMATRIX_X4(r0, r1, r2, r3, addr);
                bf[2*j+0][0] = r0; bf[2*j+0][1] = r1;
                bf[2*j+1][0] = r2; bf[2*j+1][1] = r3;
            }
            #pragma unroll
            for (int i = 0; i < 4; i++)
                #pragma unroll
                for (int t = 0; t < 4; t++)
                    MMA_F16(acc[i][t][0], acc[i][t][1], acc[i][t][2], acc[i][t][3],
                            af[i][0], af[i][1], af[i][2], af[i][3],
                            bf[t][0], bf[t][1]);
        }
        cur++; if (cur == STAGES) cur = 0;
        pfs++; if (pfs == STAGES) pfs = 0;
    }

    #pragma unroll
    for (int i = 0; i < 4; i++) {
        const int row0 = bm + warp_m * 64 + i * 16 + gid;
        #pragma unroll
        for (int t = 0; t < 4; t++) {
            const int col = bn + warp_n * 32 + t * 8 + 2 * tg;
            const float2 bv = *(const float2*)(bias + col);
            float2 v0, v1;
            v0.x = acc[i][t][0] + bv.x; v0.y = acc[i][t][1] + bv.y;
            v1.x = acc[i][t][2] + bv.x; v1.y = acc[i][t][3] + bv.y;
            if (RELU) {
                v0.x = fmaxf(v0.x, 0.f); v0.y = fmaxf(v0.y, 0.f);
                v1.x = fmaxf(v1.x, 0.f); v1.y = fmaxf(v1.y, 0.f);
            }
            if (OUTM == 2) {
                __half* Ch = (__half*)Cv;
                *(__half2*)(Ch + (size_t)row0 * N + col)       = __floats2half2_rn(v0.x, v0.y);
                *(__half2*)(Ch + (size_t)(row0 + 8) * N + col) = __floats2half2_rn(v1.x, v1.y);
            } else {
                float* Cf = (float*)Cv;
                *(float2*)(Cf + (size_t)row0 * N + col)       = v0;
                *(float2*)(Cf + (size_t)(row0 + 8) * N + col) = v1;
            }
        }
    }
}

// ---------------------------------------------------------------------------
// fp16 tensor-core flash attention (R14-proven). 128 queries x 1 head, 8 warps.
// K AND V loaded row-major from fused qkv; PV B-fragments via ldmatrix.trans.
// ---------------------------------------------------------------------------
#define ATT_SMEM 49152   // 2 stages x (8KB K + 8KB V) + 16KB Q

__global__ __launch_bounds__(256, 2)
void flash_mma(const __half* __restrict__ QKV, __half* __restrict__ O)
{
    extern __shared__ char smem[];
    const uint32_t sbase = smem_u32(smem);
    const int tid  = threadIdx.x;
    const int wid  = tid >> 5;
    const int lane = tid & 31;
    const int gid  = lane >> 2;
    const int tg   = lane & 3;

    const int bh = blockIdx.y;
    const int b  = bh >> 4;
    const int h  = bh & 15;
    const int q0 = blockIdx.x * 128;

    const __half* Qg = QKV + (size_t)b * SEQ * QLD + h * HD;
    const __half* Kg = Qg + DMODEL;
    const __half* Vg = Qg + 2 * DMODEL;

    const uint32_t qreg = sbase + 32768;

    const int qrow = tid >> 1;
    const int qu0  = (tid & 1) * 4;
    uint32_t qsw[4];
    #pragma unroll
    for (int i = 0; i < 4; i++) {
        uint32_t off = qrow * 128 + (qu0 + i) * 16;
        qsw[i] = off ^ ((off >> 3) & 0x70);
    }
    const int krow = tid >> 2;
    const int ku0  = (tid & 3) * 2;
    uint32_t kvsw[2];
    #pragma unroll
    for (int i = 0; i < 2; i++) {
        uint32_t off = krow * 128 + (ku0 + i) * 16;
        kvsw[i] = off ^ ((off >> 3) & 0x70);
    }

    uint32_t aq_rel, aq_xr;
    {
        int r = wid * 16 + (lane & 7) + ((lane >> 3) & 1) * 8;
        aq_rel = r * 128;
        aq_xr  = (r & 7) << 4;
    }
    const uint32_t a_kb = ((lane >> 4) & 1) * 16;
    uint32_t b_rel[4], b_xr[4];
    #pragma unroll
    for (int j = 0; j < 4; j++) {
        int r = j * 16 + (lane & 7) + ((lane >> 4) & 1) * 8;
        b_rel[j] = r * 128;
        b_xr[j]  = (r & 7) << 4;
    }
    const uint32_t b_kb = ((lane >> 3) & 1) * 16;
    uint32_t v_rel[4];
    #pragma unroll
    for (int j = 0; j < 4; j++) {
        int kr = ((lane >> 3) & 1) * 8 + (lane & 7);
        int dc = j * 16 + ((lane >> 4) & 1) * 8;
        v_rel[j] = kr * 128 + dc * 2;
    }

    auto load_KV = [&](int stage, int kt) {
        const uint32_t sK = sbase + stage * 16384;
        const uint32_t sV = sK + 8192;
        const __half* kr = Kg + (size_t)(kt * 64 + krow) * QLD + ku0 * 8;
        const __half* vr = Vg + (size_t)(kt * 64 + krow) * QLD + ku0 * 8;
        #pragma unroll
        for (int i = 0; i < 2; i++) CP_ASYNC16(sK + kvsw[i], kr + i * 8);
        #pragma unroll
        for (int i = 0; i < 2; i++) CP_ASYNC16(sV + kvsw[i], vr + i * 8);
    };

    {
        const __half* qr = Qg + (size_t)(q0 + qrow) * QLD + qu0 * 8;
        #pragma unroll
        for (int i = 0; i < 4; i++) CP_ASYNC16(qreg + qsw[i], qr + i * 8);
        load_KV(0, 0);
        CP_COMMIT();
        CP_WAIT(0);
        __syncthreads();
    }

    uint32_t qf[4][4];
    #pragma unroll
    for (int ks = 0; ks < 4; ks++) {
        uint32_t addr = qreg + ((aq_rel + a_kb + ks * 32) ^ aq_xr);
        LDMATRIX_X4(qf[ks][0], qf[ks][1], qf[ks][2], qf[ks][3], addr);
    }
    __syncthreads();

    const int NT = SEQ / 64;
    load_KV(1, 1);
    CP_COMMIT();

    float o[8][4];
    #pragma unroll
    for (int t = 0; t < 8; t++)
        #pragma unroll
        for (int r = 0; r < 4; r++) o[t][r] = 0.f;
    float m0 = -1e30f, m1 = -1e30f, l0 = 0.f, l1 = 0.f;

    for (int kt = 0; kt < NT; kt++) {
        if (kt < NT - 1) { CP_WAIT(1); } else { CP_WAIT(0); }
        __syncthreads();
        const uint32_t sK = sbase + (kt & 1) * 16384;
        const uint32_t sV = sK + 8192;

        float s[8][4];
        #pragma unroll
        for (int t = 0; t < 8; t++)
            #pragma unroll
            for (int r = 0; r < 4; r++) s[t][r] = 0.f;

        #pragma unroll
        for (int ks = 0; ks < 4; ks++) {
            uint32_t bf[8][2];
            #pragma unroll
            for (int j = 0; j < 4; j++) {
                uint32_t r0, r1, r2, r3;
                uint32_t addr = sK + ((b_rel[j] + b_kb + ks * 32) ^ b_xr[j]);
                LDMATRIX_X4(r0, r1, r2, r3, addr);
                bf[2*j+0][0] = r0; bf[2*j+0][1] = r1;
                bf[2*j+1][0] = r2; bf[2*j+1][1] = r3;
            }
            const uint32_t* aq = qf[ks];
            #pragma unroll
            for (int t = 0; t < 8; t++)
                MMA_F16(s[t][0], s[t][1], s[t][2], s[t][3],
                        aq[0], aq[1], aq[2], aq[3], bf[t][0], bf[t][1]);
        }

        float tmax0 = -1e30f, tmax1 = -1e30f;
        #pragma unroll
        for (int t = 0; t < 8; t++) {
            s[t][0] *= 0.125f; s[t][1] *= 0.125f; s[t][2] *= 0.125f; s[t][3] *= 0.125f;
            tmax0 = fmaxf(tmax0, fmaxf(s[t][0], s[t][1]));
            tmax1 = fmaxf(tmax1, fmaxf(s[t][2], s[t][3]));
        }
        tmax0 = fmaxf(tmax0, __shfl_xor_sync(0xffffffffu, tmax0, 1));
        tmax0 = fmaxf(tmax0, __shfl_xor_sync(0xffffffffu, tmax0, 2));
        tmax1 = fmaxf(tmax1, __shfl_xor_sync(0xffffffffu, tmax1, 1));
        tmax1 = fmaxf(tmax1, __shfl_xor_sync(0xffffffffu, tmax1, 2));

        const float mnew0 = fmaxf(m0, tmax0);
        const float mnew1 = fmaxf(m1, tmax1);
        const float corr0 = __expf(m0 - mnew0);
        const float corr1 = __expf(m1 - mnew1);

        float rs0 = 0.f, rs1 = 0.f;
        #pragma unroll
        for (int t = 0; t < 8; t++) {
            s[t][0] = __expf(s[t][0] - mnew0);
            s[t][1] = __expf(s[t][1] - mnew0);
            s[t][2] = __expf(s[t][2] - mnew1);
            s[t][3] = __expf(s[t][3] - mnew1);
            rs0 += s[t][0] + s[t][1];
            rs1 += s[t][2] + s[t][3];
        }
        rs0 += __shfl_xor_sync(0xffffffffu, rs0, 1);
        rs0 += __shfl_xor_sync(0xffffffffu, rs0, 2);
        rs1 += __shfl_xor_sync(0xffffffffu, rs1, 1);
        rs1 += __shfl_xor_sync(0xffffffffu, rs1, 2);

        l0 = l0 * corr0 + rs0;
        l1 = l1 * corr1 + rs1;
        #pragma unroll
        for (int t = 0; t < 8; t++) {
            o[t][0] *= corr0; o[t][1] *= corr0;
            o[t][2] *= corr1; o[t][3] *= corr1;
        }
        m0 = mnew0; m1 = mnew1;

        #pragma unroll
        for (int ks = 0; ks < 4; ks++) {
            uint32_t a0 = packh2(s[2*ks+0][0], s[2*ks+0][1]);
            uint32_t a1 = packh2(s[2*ks+0][2], s[2*ks+0][3]);
            uint32_t a2 = packh2(s[2*ks+1][0], s[2*ks+1][1]);
            uint32_t a3 = packh2(s[2*ks+1][2], s[2*ks+1][3]);

            uint32_t bf[8][2];
            #pragma unroll
            for (int j = 0; j < 4; j++) {
                uint32_t r0, r1, r2, r3;
                uint32_t off = v_rel[j] + ks * 2048;
                uint32_t addr = sV + (off ^ ((off >> 3) & 0x70));
                LDMATRIX_X4_TRANS(r0, r1, r2, r3, addr);
                bf[2*j+0][0] = r0; bf[2*j+0][1] = r1;
                bf[2*j+1][0] = r2; bf[2*j+1][1] = r3;
            }
            #pragma unroll
            for (int t = 0; t < 8; t++)
                MMA_F16(o[t][0], o[t][1], o[t][2], o[t][3],
                        a0, a1, a2, a3, bf[t][0], bf[t][1]);
        }

        __syncthreads();
        const int pf = kt + 2;
        if (pf < NT) { load_KV(pf & 1, pf); CP_COMMIT(); }
    }

    const float inv0 = 1.0f / l0;
    const float inv1 = 1.0f / l1;
    const int qa = q0 + wid * 16 + gid;
    __half* orow0 = O + (size_t)(b * SEQ + qa)     * DMODEL + h * HD;
    __half* orow1 = O + (size_t)(b * SEQ + qa + 8) * DMODEL + h * HD;
    #pragma unroll
    for (int t = 0; t < 8; t++) {
        const int col = t * 8 + 2 * tg;
        *(__half2*)(orow0 + col) = __floats2half2_rn(o[t][0] * inv0, o[t][1] * inv0);
        *(__half2*)(orow1 + col) = __floats2half2_rn(o[t][2] * inv1, o[t][3] * inv1);
    }
}

// ---------------------------------------------------------------------------
// Fused weight transpose: all 6 weights in ONE launch. 64x64 tiles,
// float4 loads, 2x16B half stores per thread (fully coalesced).
// ---------------------------------------------------------------------------
__device__ __forceinline__ void tr64(const float* __restrict__ in,
                                     __half* __restrict__ out,
                                     int K, int N, int kt, int nt)
{
    __shared__ float tile[64][65];
    const int t  = threadIdx.x;
    const int r  = t >> 2;            // 0..63
    const int c0 = (t & 3) * 16;      // float col base

    const float* ip = in + (size_t)(kt * 64 + r) * N + nt * 64 + c0;
    #pragma unroll
    for (int i = 0; i < 4; i++) {
        float4 v = *(const float4*)(ip + i * 4);
        tile[r][c0 + 4*i + 0] = v.x;
        tile[r][c0 + 4*i + 1] = v.y;
        tile[r][c0 + 4*i + 2] = v.z;
        tile[r][c0 + 4*i + 3] = v.w;
    }
    __syncthreads();

    __align__(16) __half2 hb[8];
    #pragma unroll
    for (int j = 0; j < 8; j++)
        hb[j] = __floats2half2_rn(tile[c0 + 2*j][r], tile[c0 + 2*j + 1][r]);

    __half* op = out + (size_t)(nt * 64 + r) * K + kt * 64 + c0;
    *(uint4*)(op)     = ((uint4*)hb)[0];
    *(uint4*)(op + 8) = ((uint4*)hb)[1];
}

__global__ __launch_bounds__(256)
void transpose_all(const float* __restrict__ Wq, const float* __restrict__ Wk,
                   const float* __restrict__ Wv, const float* __restrict__ Wo,
                   const float* __restrict__ W1, const float* __restrict__ W2,
                   __half* __restrict__ wqkvT, __half* __restrict__ woT,
                   __half* __restrict__ w1T,   __half* __restrict__ w2T)
{
    const int id = blockIdx.x;
    if (id < 1024) {                       // Wq/Wk/Wv/Wo: 1024x1024, 16x16 tiles each
        const int w = id >> 8, rr = id & 255;
        const float* in = (w == 0) ? Wq : (w == 1) ? Wk : (w == 2) ? Wv : Wo;
        __half* out = (w < 3) ? (wqkvT + (size_t)w * DMODEL * DMODEL) : woT;
        tr64(in, out, DMODEL, DMODEL, rr >> 4, rr & 15);
    } else if (id < 2048) {                // W1: [1024,4096] -> w1T [4096,1024]
        const int rr = id - 1024;          // 16 k-tiles x 64 n-tiles
        tr64(W1, w1T, DMODEL, DFF, rr >> 6, rr & 63);
    } else {                               // W2: [4096,1024] -> w2T [1024,4096]
        const int rr = id - 2048;          // 64 k-tiles x 16 n-tiles
        tr64(W2, w2T, DFF, DMODEL, rr >> 4, rr & 15);
    }
}

__global__ void concat_bias(const float* a, const float* b, const float* c, float* out)
{
    int i = blockIdx.x * 256 + threadIdx.x;
    if (i < DMODEL)            out[i] = a[i];
    else if (i < 2 * DMODEL)   out[i] = b[i - DMODEL];
    else if (i < 3 * DMODEL)   out[i] = c[i - 2 * DMODEL];
}

// Half copy: out[i] = half(in[i]).
__global__ __launch_bounds__(256)
void half_copy(const float* __restrict__ in, __half* __restrict__ out, int n4)
{
    int i = blockIdx.x * 256 + threadIdx.x;
    if (i < n4) {
        float4 v = ((const float4*)in)[i];
        __half2* o = (__half2*)out + i * 2;
        o[0] = __floats2half2_rn(v.x, v.y);
        o[1] = __floats2half2_rn(v.z, v.w);
    }
}

// ---------------------------------------------------------------------------
// Fused residual add + LayerNorm. Optionally writes a half copy for fp16 GEMM A.
// ---------------------------------------------------------------------------
__global__ __launch_bounds__(256)
void add_ln(const float* __restrict__ A, const float* __restrict__ Bv,
            const float* __restrict__ g, const float* __restrict__ be,
            float* __restrict__ out, __half* __restrict__ out_h)
{
    const int row = blockIdx.x;
    const int tid = threadIdx.x;

    const float4 a4 = ((const float4*)(A  + (size_t)row * DMODEL))[tid];
    const float4 b4 = ((const float4*)(Bv + (size_t)row * DMODEL))[tid];
    float4 v;
    v.x = a4.x + b4.x; v.y = a4.y + b4.y; v.z = a4.z + b4.z; v.w = a4.w + b4.w;

    float s  = v.x + v.y + v.z + v.w;
    float ss = v.x*v.x + v.y*v.y + v.z*v.z + v.w*v.w;

    #pragma unroll
    for (int ofs = 16; ofs > 0; ofs >>= 1) {
        s  += __shfl_xor_sync(0xFFFFFFFFu, s,  ofs);
        ss += __shfl_xor_sync(0xFFFFFFFFu, ss, ofs);
    }

    __shared__ float shs[8], shss[8];
    const int w = tid >> 5;
    if ((tid & 31) == 0) { shs[w] = s; shss[w] = ss; }
    __syncthreads();
    if (tid < 32) {
        float s2  = (tid < 8) ? shs[tid]  : 0.f;
        float ss2 = (tid < 8) ? shss[tid] : 0.f;
        #pragma unroll
        for (int ofs = 4; ofs > 0; ofs >>= 1) {
            s2  += __shfl_xor_sync(0xFFFFFFFFu, s2,  ofs);
            ss2 += __shfl_xor_sync(0xFFFFFFFFu, ss2, ofs);
        }
        if (tid == 0) { shs[0] = s2; shss[0] = ss2; }
    }
    __syncthreads();

    const float mu  = shs[0]  * (1.f / DMODEL);
    const float var = shss[0] * (1.f / DMODEL) - mu * mu;
    const float inv = rsqrtf(var + 1e-5f);

    const float4 gv = ((const float4*)g)[tid];
    const float4 bb = ((const float4*)be)[tid];
    float4 o;
    o.x = (v.x - mu) * inv * gv.x + bb.x;
    o.y = (v.y - mu) * inv * gv.y + bb.y;
    o.z = (v.z - mu) * inv * gv.z + bb.z;
    o.w = (v.w - mu) * inv * gv.w + bb.w;
    ((float4*)(out + (size_t)row * DMODEL))[tid] = o;
    if (out_h) {
        __half2* oh = (__half2*)(out_h + (size_t)row * DMODEL) + tid * 2;
        oh[0] = __floats2half2_rn(o.x, o.y);
        oh[1] = __floats2half2_rn(o.z, o.w);
    }
}

// ---------------------------------------------------------------------------
// Launch
// ---------------------------------------------------------------------------
extern "C" void kernel_launch(void* const* d_in, const int* in_sizes, int n_in,
                              void* d_out, int out_size)
{
    const float* src  = (const float*)d_in[0];
    const float* Wq   = (const float*)d_in[1];
    const float* bq   = (const float*)d_in[2];
    const float* Wk   = (const float*)d_in[3];
    const float* bk   = (const float*)d_in[4];
    const float* Wv   = (const float*)d_in[5];
    const float* bv   = (const float*)d_in[6];
    const float* Wo   = (const float*)d_in[7];
    const float* bo   = (const float*)d_in[8];
    const float* W1   = (const float*)d_in[9];
    const float* b1   = (const float*)d_in[10];
    const float* W2   = (const float*)d_in[11];
    const float* b2   = (const float*)d_in[12];
    const float* ln1g = (const float*)d_in[13];
    const float* ln1b = (const float*)d_in[14];
    const float* ln2g = (const float*)d_in[15];
    const float* ln2b = (const float*)d_in[16];
    float* out = (float*)d_out;

    float  *pbqkv, *ptmp, *px;
    __half *pqkvh, *psrcr, *pxr, *pwqkvT, *pwoT, *pw1T, *pw2T, *pctx, *pff;
    cudaGetSymbolAddress((void**)&pqkvh,  g_qkvh);
    cudaGetSymbolAddress((void**)&psrcr,  g_srcr);
    cudaGetSymbolAddress((void**)&pxr,    g_xr);
    cudaGetSymbolAddress((void**)&pwqkvT, g_wqkvT);
    cudaGetSymbolAddress((void**)&pwoT,   g_woT);
    cudaGetSymbolAddress((void**)&pw1T,   g_w1T);
    cudaGetSymbolAddress((void**)&pw2T,   g_w2T);
    cudaGetSymbolAddress((void**)&pbqkv,  g_bqkv);
    cudaGetSymbolAddress((void**)&pctx,   g_ctx);
    cudaGetSymbolAddress((void**)&ptmp,   g_tmp);
    cudaGetSymbolAddress((void**)&px,     g_x);
    cudaGetSymbolAddress((void**)&pff,    g_ff);

    cudaFuncSetAttribute((const void*)gemm_mma<false,0>, cudaFuncAttributeMaxDynamicSharedMemorySize, SMEM_DYN);
    cudaFuncSetAttribute((const void*)gemm_mma<false,2>, cudaFuncAttributeMaxDynamicSharedMemorySize, SMEM_DYN);
    cudaFuncSetAttribute((const void*)gemm_mma<true,2>,  cudaFuncAttributeMaxDynamicSharedMemorySize, SMEM_DYN);
    cudaFuncSetAttribute((const void*)flash_mma, cudaFuncAttributeMaxDynamicSharedMemorySize, ATT_SMEM);

    // Pre-converted inputs + all weight transposes in one launch
    half_copy<<<(NTOK * DMODEL / 4 + 255) / 256, 256>>>(src, psrcr, NTOK * DMODEL / 4);
    transpose_all<<<3072, 256>>>(Wq, Wk, Wv, Wo, W1, W2, pwqkvT, pwoT, pw1T, pw2T);
    concat_bias<<<12, 256>>>(bq, bk, bv, pbqkv);

    // Fused QKV projection (half in, half out: feeds fp16 flash)
    gemm_mma<false, 2><<<dim3(3 * DMODEL / 128, NTOK / 256), 512, SMEM_DYN>>>(
        psrcr, pwqkvT, pbqkv, pqkvh, NTOK, 3 * DMODEL, DMODEL);

    // fp16 flash attention (128 queries/block; V via trans ldmatrix; half ctx out)
    flash_mma<<<dim3(SEQ / 128, 2 * NHEAD), 256, ATT_SMEM>>>(pqkvh, pctx);

    // Output projection (half A, fp32 out) + LN1 (writes half copy for FFN1)
    gemm_mma<false, 0><<<dim3(DMODEL / 128, NTOK / 256), 512, SMEM_DYN>>>(
        pctx, pwoT, bo, ptmp, NTOK, DMODEL, DMODEL);
    add_ln<<<NTOK, 256>>>(src, ptmp, ln1g, ln1b, px, pxr);

    // FFN
    gemm_mma<true, 2><<<dim3(DFF / 128, NTOK / 256), 512, SMEM_DYN>>>(
        pxr, pw1T, b1, pff, NTOK, DFF, DMODEL);
    gemm_mma<false, 0><<<dim3(DMODEL / 128, NTOK / 256), 512, SMEM_DYN>>>(
        pff, pw2T, b2, ptmp, NTOK, DMODEL, DFF);
    add_ln<<<NTOK, 256>>>(px, ptmp, ln2g, ln2b, out, (__half*)nullptr);
}

// round 16
// speedup vs baseline: 2.7025x; 1.0218x over previous
#include <cuda_runtime.h>
#include <cuda_fp16.h>
#include <math.h>
#include <stdint.h>

// Problem constants
#define NTOK   4096      // B*S = 2*2048
#define DMODEL 1024
#define DFF    4096
#define NHEAD  16
#define HD     64
#define SEQ    2048
#define QLD    (3 * DMODEL)   // fused qkv row stride

// ---------------------------------------------------------------------------
// Scratch (static device globals; no runtime allocation allowed)
// ---------------------------------------------------------------------------
__device__ __align__(16) __half g_qkvh[NTOK * 3 * DMODEL];    // fused q|k|v half
__device__ __align__(16) __half g_srcr[NTOK * DMODEL];        // half src (QKV A)
__device__ __align__(16) __half g_xr  [NTOK * DMODEL];        // half LN1 out (FFN1 A)
__device__ __align__(16) __half g_wqkvT[3 * DMODEL * DMODEL]; // [3072,1024] K-major half
__device__ __align__(16) __half g_woT [DMODEL * DMODEL];
__device__ __align__(16) __half g_w1T [DFF * DMODEL];
__device__ __align__(16) __half g_w2T [DMODEL * DFF];
__device__ __align__(16) float  g_bqkv[3 * DMODEL];
__device__ __align__(16) __half g_ctx [NTOK * DMODEL];        // half flash output (O-proj A)
__device__ __align__(16) float  g_tmp [NTOK * DMODEL];
__device__ __align__(16) float  g_x   [NTOK * DMODEL];
__device__ __align__(16) __half g_ff  [NTOK * DFF];           // half FFN1 output (FFN2 A)

// ---------------------------------------------------------------------------
// PTX helpers
// ---------------------------------------------------------------------------
__device__ __forceinline__ uint32_t smem_u32(const void* p) {
    uint32_t a;
    asm("{ .reg .u64 t; cvta.to.shared.u64 t, %1; cvt.u32.u64 %0, t; }" : "=r"(a) : "l"(p));
    return a;
}
#define CP_ASYNC16(dst, src) \
    asm volatile("cp.async.cg.shared.global [%0], [%1], 16;" :: "r"(dst), "l"(src))
#define CP_COMMIT() asm volatile("cp.async.commit_group;" ::: "memory")
#define CP_WAIT(n)  asm volatile("cp.async.wait_group %0;" :: "n"(n) : "memory")

#define LDMATRIX_X4(r0, r1, r2, r3, addr) \
    asm volatile("ldmatrix.sync.aligned.m8n8.x4.shared.b16 {%0,%1,%2,%3}, [%4];" \
                 : "=r"(r0), "=r"(r1), "=r"(r2), "=r"(r3) : "r"(addr))

#define LDMATRIX_X4_TRANS(r0, r1, r2, r3, addr) \
    asm volatile("ldmatrix.sync.aligned.m8n8.x4.trans.shared.b16 {%0,%1,%2,%3}, [%4];" \
                 : "=r"(r0), "=r"(r1), "=r"(r2), "=r"(r3) : "r"(addr))

#define MMA_F16(c0, c1, c2, c3, a0, a1, a2, a3, b0, b1) \
    asm volatile("mma.sync.aligned.m16n8k16.row.col.f32.f16.f16.f32 " \
                 "{%0,%1,%2,%3}, {%4,%5,%6,%7}, {%8,%9}, {%0,%1,%2,%3};" \
                 : "+f"(c0), "+f"(c1), "+f"(c2), "+f"(c3) \
                 : "r"(a0), "r"(a1), "r"(a2), "r"(a3), "r"(b0), "r"(b1))

__device__ __forceinline__ uint32_t packh2(float x, float y) {
    __half2 h = __floats2half2_rn(x, y);
    return *(uint32_t*)&h;
}

// ---------------------------------------------------------------------------
// fp16 tensor-core GEMM:  C = A @ BT^T + bias.  A,BT half.
// 256x128 block tile, K-chunk 64, 512 threads (16 warps, warp tile 64x32),
// 3-stage cp.async, one barrier per iteration. A-fragments software-pipelined
// (2-deep ring) so LDSM overlaps MMA. OUTM: 0 = fp32, 2 = half.
// ---------------------------------------------------------------------------
#define STAGES 3
#define A_ST_BYTES (256 * 128)
#define B_ST_BYTES (128 * 128)
#define STAGE_BYTES (A_ST_BYTES + B_ST_BYTES)
#define SMEM_DYN (STAGES * STAGE_BYTES)      // 144KB

template <bool RELU, int OUTM>
__global__ __launch_bounds__(512, 1)
void gemm_mma(const __half* __restrict__ A, const __half* __restrict__ BT,
              const float* __restrict__ bias, void* __restrict__ Cv,
              int M, int N, int K)
{
    extern __shared__ char smem[];
    const uint32_t sbase = smem_u32(smem);
    const int tid  = threadIdx.x;
    const int wid  = tid >> 5;
    const int lane = tid & 31;
    const int warp_m = wid & 3;
    const int warp_n = wid >> 2;
    const int gid = lane >> 2;
    const int tg  = lane & 3;

    const int bm = blockIdx.y * 256;
    const int bn = blockIdx.x * 128;
    const int KT = K >> 6;

    const int arow = tid >> 1;
    const int au0  = (tid & 1) * 4;
    const __half* Ag = A + (size_t)(bm + arow) * K + au0 * 8;
    uint32_t aswz[4];
    #pragma unroll
    for (int i = 0; i < 4; i++) {
        uint32_t off = arow * 128 + (au0 + i) * 16;
        aswz[i] = off ^ ((off >> 3) & 0x70);
    }
    const int brow = tid >> 2;
    const int bu0  = (tid & 3) * 2;
    const __half* Bg = BT + (size_t)(bn + brow) * K + bu0 * 8;
    uint32_t bswz[2];
    #pragma unroll
    for (int i = 0; i < 2; i++) {
        uint32_t off = brow * 128 + (bu0 + i) * 16;
        bswz[i] = off ^ ((off >> 3) & 0x70);
    }

    uint32_t a_rel[4], a_xr[4];
    #pragma unroll
    for (int i = 0; i < 4; i++) {
        int r = warp_m * 64 + i * 16 + (lane & 7) + ((lane >> 3) & 1) * 8;
        a_rel[i] = r * 128;
        a_xr[i]  = (r & 7) << 4;
    }
    const uint32_t a_kb = ((lane >> 4) & 1) * 16;
    uint32_t b_rel[2], b_xr[2];
    #pragma unroll
    for (int j = 0; j < 2; j++) {
        int r = warp_n * 32 + j * 16 + (lane & 7) + ((lane >> 4) & 1) * 8;
        b_rel[j] = r * 128;
        b_xr[j]  = (r & 7) << 4;
    }
    const uint32_t b_kb = ((lane >> 3) & 1) * 16;

    float acc[4][4][4];
    #pragma unroll
    for (int i = 0; i < 4; i++)
        #pragma unroll
        for (int t = 0; t < 4; t++)
            #pragma unroll
            for (int r = 0; r < 4; r++) acc[i][t][r] = 0.f;

    auto load_tile = [&](int s, int kt) {
        const uint32_t sA = sbase + s * STAGE_BYTES;
        const uint32_t sB = sA + A_ST_BYTES;
        const __half* ar = Ag + kt * 64;
        const __half* br = Bg + kt * 64;
        #pragma unroll
        for (int i = 0; i < 4; i++) CP_ASYNC16(sA + aswz[i], ar + i * 8);
        #pragma unroll
        for (int i = 0; i < 2; i++) CP_ASYNC16(sB + bswz[i], br + i * 8);
    };

    #pragma unroll
    for (int s = 0; s < STAGES - 1; s++) { load_tile(s, s); CP_COMMIT(); }

    int cur = 0, pfs = STAGES - 1;
    for (int kt = 0; kt < KT; kt++) {
        CP_WAIT(STAGES - 2);
        __syncthreads();

        const int pf = kt + STAGES - 1;
        if (pf < KT) load_tile(pfs, pf);
        CP_COMMIT();

        const uint32_t sA = sbase + cur * STAGE_BYTES;
        const uint32_t sB = sA + A_ST_BYTES;

        #pragma unroll
        for (int ks = 0; ks < 4; ks++) {
            const uint32_t kso = ks * 32;
            // B fragments first
            uint32_t bf[4][2];
            #pragma unroll
            for (int j = 0; j < 2; j++) {
                uint32_t r0, r1, r2, r3;
                uint32_t addr = sB + ((b_rel[j] + b_kb + kso) ^ b_xr[j]);
                LDMATRIX_X4(r0, r1, r2, r3, addr);
                bf[2*j+0][0] = r0; bf[2*j+0][1] = r1;
                bf[2*j+1][0] = r2; bf[2*j+1][1] = r3;
            }
            // A fragments: 2-deep ring, LDSM for i+1 overlaps MMA for i
            uint32_t af[2][4];
            {
                uint32_t addr = sA + ((a_rel[0] + a_kb + kso) ^ a_xr[0]);
                LDMATRIX_X4(af[0][0], af[0][1], af[0][2], af[0][3], addr);
            }
            #pragma unroll
            for (int i = 0; i < 4; i++) {
                if (i < 3) {
                    uint32_t addr = sA + ((a_rel[i+1] + a_kb + kso) ^ a_xr[i+1]);
                    LDMATRIX_X4(af[(i+1)&1][0], af[(i+1)&1][1],
                                af[(i+1)&1][2], af[(i+1)&1][3], addr);
                }
                const uint32_t* a = af[i & 1];
                #pragma unroll
                for (int t = 0; t < 4; t++)
                    MMA_F16(acc[i][t][0], acc[i][t][1], acc[i][t][2], acc[i][t][3],
                            a[0], a[1], a[2], a[3], bf[t][0], bf[t][1]);
            }
        }
        cur++; if (cur == STAGES) cur = 0;
        pfs++; if (pfs == STAGES) pfs = 0;
    }

    #pragma unroll
    for (int i = 0; i < 4; i++) {
        const int row0 = bm + warp_m * 64 + i * 16 + gid;
        #pragma unroll
        for (int t = 0; t < 4; t++) {
            const int col = bn + warp_n * 32 + t * 8 + 2 * tg;
            const float2 bv = *(const float2*)(bias + col);
            float2 v0, v1;
            v0.x = acc[i][t][0] + bv.x; v0.y = acc[i][t][1] + bv.y;
            v1.x = acc[i][t][2] + bv.x; v1.y = acc[i][t][3] + bv.y;
            if (RELU) {
                v0.x = fmaxf(v0.x, 0.f); v0.y = fmaxf(v0.y, 0.f);
                v1.x = fmaxf(v1.x, 0.f); v1.y = fmaxf(v1.y, 0.f);
            }
            if (OUTM == 2) {
                __half* Ch = (__half*)Cv;
                *(__half2*)(Ch + (size_t)row0 * N + col)       = __floats2half2_rn(v0.x, v0.y);
                *(__half2*)(Ch + (size_t)(row0 + 8) * N + col) = __floats2half2_rn(v1.x, v1.y);
            } else {
                float* Cf = (float*)Cv;
                *(float2*)(Cf + (size_t)row0 * N + col)       = v0;
                *(float2*)(Cf + (size_t)(row0 + 8) * N + col) = v1;
            }
        }
    }
}

// ---------------------------------------------------------------------------
// fp16 tensor-core flash attention (R14-proven). 128 queries x 1 head, 8 warps.
// ---------------------------------------------------------------------------
#define ATT_SMEM 49152   // 2 stages x (8KB K + 8KB V) + 16KB Q

__global__ __launch_bounds__(256, 2)
void flash_mma(const __half* __restrict__ QKV, __half* __restrict__ O)
{
    extern __shared__ char smem[];
    const uint32_t sbase = smem_u32(smem);
    const int tid  = threadIdx.x;
    const int wid  = tid >> 5;
    const int lane = tid & 31;
    const int gid  = lane >> 2;
    const int tg   = lane & 3;

    const int bh = blockIdx.y;
    const int b  = bh >> 4;
    const int h  = bh & 15;
    const int q0 = blockIdx.x * 128;

    const __half* Qg = QKV + (size_t)b * SEQ * QLD + h * HD;
    const __half* Kg = Qg + DMODEL;
    const __half* Vg = Qg + 2 * DMODEL;

    const uint32_t qreg = sbase + 32768;

    const int qrow = tid >> 1;
    const int qu0  = (tid & 1) * 4;
    uint32_t qsw[4];
    #pragma unroll
    for (int i = 0; i < 4; i++) {
        uint32_t off = qrow * 128 + (qu0 + i) * 16;
        qsw[i] = off ^ ((off >> 3) & 0x70);
    }
    const int krow = tid >> 2;
    const int ku0  = (tid & 3) * 2;
    uint32_t kvsw[2];
    #pragma unroll
    for (int i = 0; i < 2; i++) {
        uint32_t off = krow * 128 + (ku0 + i) * 16;
        kvsw[i] = off ^ ((off >> 3) & 0x70);
    }

    uint32_t aq_rel, aq_xr;
    {
        int r = wid * 16 + (lane & 7) + ((lane >> 3) & 1) * 8;
        aq_rel = r * 128;
        aq_xr  = (r & 7) << 4;
    }
    const uint32_t a_kb = ((lane >> 4) & 1) * 16;
    uint32_t b_rel[4], b_xr[4];
    #pragma unroll
    for (int j = 0; j < 4; j++) {
        int r = j * 16 + (lane & 7) + ((lane >> 4) & 1) * 8;
        b_rel[j] = r * 128;
        b_xr[j]  = (r & 7) << 4;
    }
    const uint32_t b_kb = ((lane >> 3) & 1) * 16;
    uint32_t v_rel[4];
    #pragma unroll
    for (int j = 0; j < 4; j++) {
        int kr = ((lane >> 3) & 1) * 8 + (lane & 7);
        int dc = j * 16 + ((lane >> 4) & 1) * 8;
        v_rel[j] = kr * 128 + dc * 2;
    }

    auto load_KV = [&](int stage, int kt) {
        const uint32_t sK = sbase + stage * 16384;
        const uint32_t sV = sK + 8192;
        const __half* kr = Kg + (size_t)(kt * 64 + krow) * QLD + ku0 * 8;
        const __half* vr = Vg + (size_t)(kt * 64 + krow) * QLD + ku0 * 8;
        #pragma unroll
        for (int i = 0; i < 2; i++) CP_ASYNC16(sK + kvsw[i], kr + i * 8);
        #pragma unroll
        for (int i = 0; i < 2; i++) CP_ASYNC16(sV + kvsw[i], vr + i * 8);
    };

    {
        const __half* qr = Qg + (size_t)(q0 + qrow) * QLD + qu0 * 8;
        #pragma unroll
        for (int i = 0; i < 4; i++) CP_ASYNC16(qreg + qsw[i], qr + i * 8);
        load_KV(0, 0);
        CP_COMMIT();
        CP_WAIT(0);
        __syncthreads();
    }

    uint32_t qf[4][4];
    #pragma unroll
    for (int ks = 0; ks < 4; ks++) {
        uint32_t addr = qreg + ((aq_rel + a_kb + ks * 32) ^ aq_xr);
        LDMATRIX_X4(qf[ks][0], qf[ks][1], qf[ks][2], qf[ks][3], addr);
    }
    __syncthreads();

    const int NT = SEQ / 64;
    load_KV(1, 1);
    CP_COMMIT();

    float o[8][4];
    #pragma unroll
    for (int t = 0; t < 8; t++)
        #pragma unroll
        for (int r = 0; r < 4; r++) o[t][r] = 0.f;
    float m0 = -1e30f, m1 = -1e30f, l0 = 0.f, l1 = 0.f;

    for (int kt = 0; kt < NT; kt++) {
        if (kt < NT - 1) { CP_WAIT(1); } else { CP_WAIT(0); }
        __syncthreads();
        const uint32_t sK = sbase + (kt & 1) * 16384;
        const uint32_t sV = sK + 8192;

        float s[8][4];
        #pragma unroll
        for (int t = 0; t < 8; t++)
            #pragma unroll
            for (int r = 0; r < 4; r++) s[t][r] = 0.f;

        #pragma unroll
        for (int ks = 0; ks < 4; ks++) {
            uint32_t bf[8][2];
            #pragma unroll
            for (int j = 0; j < 4; j++) {
                uint32_t r0, r1, r2, r3;
                uint32_t addr = sK + ((b_rel[j] + b_kb + ks * 32) ^ b_xr[j]);
                LDMATRIX_X4(r0, r1, r2, r3, addr);
                bf[2*j+0][0] = r0; bf[2*j+0][1] = r1;
                bf[2*j+1][0] = r2; bf[2*j+1][1] = r3;
            }
            const uint32_t* aq = qf[ks];
            #pragma unroll
            for (int t = 0; t < 8; t++)
                MMA_F16(s[t][0], s[t][1], s[t][2], s[t][3],
                        aq[0], aq[1], aq[2], aq[3], bf[t][0], bf[t][1]);
        }

        float tmax0 = -1e30f, tmax1 = -1e30f;
        #pragma unroll
        for (int t = 0; t < 8; t++) {
            s[t][0] *= 0.125f; s[t][1] *= 0.125f; s[t][2] *= 0.125f; s[t][3] *= 0.125f;
            tmax0 = fmaxf(tmax0, fmaxf(s[t][0], s[t][1]));
            tmax1 = fmaxf(tmax1, fmaxf(s[t][2], s[t][3]));
        }
        tmax0 = fmaxf(tmax0, __shfl_xor_sync(0xffffffffu, tmax0, 1));
        tmax0 = fmaxf(tmax0, __shfl_xor_sync(0xffffffffu, tmax0, 2));
        tmax1 = fmaxf(tmax1, __shfl_xor_sync(0xffffffffu, tmax1, 1));
        tmax1 = fmaxf(tmax1, __shfl_xor_sync(0xffffffffu, tmax1, 2));

        const float mnew0 = fmaxf(m0, tmax0);
        const float mnew1 = fmaxf(m1, tmax1);
        const float corr0 = __expf(m0 - mnew0);
        const float corr1 = __expf(m1 - mnew1);

        float rs0 = 0.f, rs1 = 0.f;
        #pragma unroll
        for (int t = 0; t < 8; t++) {
            s[t][0] = __expf(s[t][0] - mnew0);
            s[t][1] = __expf(s[t][1] - mnew0);
            s[t][2] = __expf(s[t][2] - mnew1);
            s[t][3] = __expf(s[t][3] - mnew1);
            rs0 += s[t][0] + s[t][1];
            rs1 += s[t][2] + s[t][3];
        }
        rs0 += __shfl_xor_sync(0xffffffffu, rs0, 1);
        rs0 += __shfl_xor_sync(0xffffffffu, rs0, 2);
        rs1 += __shfl_xor_sync(0xffffffffu, rs1, 1);
        rs1 += __shfl_xor_sync(0xffffffffu, rs1, 2);

        l0 = l0 * corr0 + rs0;
        l1 = l1 * corr1 + rs1;
        #pragma unroll
        for (int t = 0; t < 8; t++) {
            o[t][0] *= corr0; o[t][1] *= corr0;
            o[t][2] *= corr1; o[t][3] *= corr1;
        }
        m0 = mnew0; m1 = mnew1;

        #pragma unroll
        for (int ks = 0; ks < 4; ks++) {
            uint32_t a0 = packh2(s[2*ks+0][0], s[2*ks+0][1]);
            uint32_t a1 = packh2(s[2*ks+0][2], s[2*ks+0][3]);
            uint32_t a2 = packh2(s[2*ks+1][0], s[2*ks+1][1]);
            uint32_t a3 = packh2(s[2*ks+1][2], s[2*ks+1][3]);

            uint32_t bf[8][2];
            #pragma unroll
            for (int j = 0; j < 4; j++) {
                uint32_t r0, r1, r2, r3;
                uint32_t off = v_rel[j] + ks * 2048;
                uint32_t addr = sV + (off ^ ((off >> 3) & 0x70));
                LDMATRIX_X4_TRANS(r0, r1, r2, r3, addr);
                bf[2*j+0][0] = r0; bf[2*j+0][1] = r1;
                bf[2*j+1][0] = r2; bf[2*j+1][1] = r3;
            }
            #pragma unroll
            for (int t = 0; t < 8; t++)
                MMA_F16(o[t][0], o[t][1], o[t][2], o[t][3],
                        a0, a1, a2, a3, bf[t][0], bf[t][1]);
        }

        __syncthreads();
        const int pf = kt + 2;
        if (pf < NT) { load_KV(pf & 1, pf); CP_COMMIT(); }
    }

    const float inv0 = 1.0f / l0;
    const float inv1 = 1.0f / l1;
    const int qa = q0 + wid * 16 + gid;
    __half* orow0 = O + (size_t)(b * SEQ + qa)     * DMODEL + h * HD;
    __half* orow1 = O + (size_t)(b * SEQ + qa + 8) * DMODEL + h * HD;
    #pragma unroll
    for (int t = 0; t < 8; t++) {
        const int col = t * 8 + 2 * tg;
        *(__half2*)(orow0 + col) = __floats2half2_rn(o[t][0] * inv0, o[t][1] * inv0);
        *(__half2*)(orow1 + col) = __floats2half2_rn(o[t][2] * inv1, o[t][3] * inv1);
    }
}

// ---------------------------------------------------------------------------
// Fused preprocessing: weight transposes + src half-copy + bias concat, ONE launch.
// ---------------------------------------------------------------------------
__device__ __forceinline__ void tr64(const float* __restrict__ in,
                                     __half* __restrict__ out,
                                     int K, int N, int kt, int nt)
{
    __shared__ float tile[64][65];
    const int t  = threadIdx.x;
    const int r  = t >> 2;
    const int c0 = (t & 3) * 16;

    const float* ip = in + (size_t)(kt * 64 + r) * N + nt * 64 + c0;
    #pragma unroll
    for (int i = 0; i < 4; i++) {
        float4 v = *(const float4*)(ip + i * 4);
        tile[r][c0 + 4*i + 0] = v.x;
        tile[r][c0 + 4*i + 1] = v.y;
        tile[r][c0 + 4*i + 2] = v.z;
        tile[r][c0 + 4*i + 3] = v.w;
    }
    __syncthreads();

    __align__(16) __half2 hb[8];
    #pragma unroll
    for (int j = 0; j < 8; j++)
        hb[j] = __floats2half2_rn(tile[c0 + 2*j][r], tile[c0 + 2*j + 1][r]);

    __half* op = out + (size_t)(nt * 64 + r) * K + kt * 64 + c0;
    *(uint4*)(op)     = ((uint4*)hb)[0];
    *(uint4*)(op + 8) = ((uint4*)hb)[1];
}

__global__ __launch_bounds__(256)
void prep_all(const float* __restrict__ src,
              const float* __restrict__ Wq, const float* __restrict__ Wk,
              const float* __restrict__ Wv, const float* __restrict__ Wo,
              const float* __restrict__ W1, const float* __restrict__ W2,
              const float* __restrict__ bq, const float* __restrict__ bk,
              const float* __restrict__ bv,
              __half* __restrict__ srcr,
              __half* __restrict__ wqkvT, __half* __restrict__ woT,
              __half* __restrict__ w1T,   __half* __restrict__ w2T,
              float* __restrict__ bqkv)
{
    const int id = blockIdx.x;
    if (id < 1024) {                       // Wq/Wk/Wv/Wo: 16x16 tiles each
        const int w = id >> 8, rr = id & 255;
        const float* in = (w == 0) ? Wq : (w == 1) ? Wk : (w == 2) ? Wv : Wo;
        __half* out = (w < 3) ? (wqkvT + (size_t)w * DMODEL * DMODEL) : woT;
        tr64(in, out, DMODEL, DMODEL, rr >> 4, rr & 15);
    } else if (id < 2048) {                // W1: [1024,4096] -> w1T [4096,1024]
        const int rr = id - 1024;
        tr64(W1, w1T, DMODEL, DFF, rr >> 6, rr & 63);
    } else if (id < 3072) {                // W2: [4096,1024] -> w2T [1024,4096]
        const int rr = id - 2048;
        tr64(W2, w2T, DFF, DMODEL, rr >> 4, rr & 15);
    } else if (id < 3072 + 4096) {         // src half copy (1M float4)
        int i = (id - 3072) * 256 + threadIdx.x;
        float4 v = ((const float4*)src)[i];
        __half2* o = (__half2*)srcr + i * 2;
        o[0] = __floats2half2_rn(v.x, v.y);
        o[1] = __floats2half2_rn(v.z, v.w);
    } else {                               // concat qkv bias (12 blocks)
        int i = (id - 3072 - 4096) * 256 + threadIdx.x;
        if (i < DMODEL)            bqkv[i] = bq[i];
        else if (i < 2 * DMODEL)   bqkv[i] = bk[i - DMODEL];
        else if (i < 3 * DMODEL)   bqkv[i] = bv[i - 2 * DMODEL];
    }
}

// ---------------------------------------------------------------------------
// Fused residual add + LayerNorm. Optionally writes a half copy for fp16 GEMM A.
// ---------------------------------------------------------------------------
__global__ __launch_bounds__(256)
void add_ln(const float* __restrict__ A, const float* __restrict__ Bv,
            const float* __restrict__ g, const float* __restrict__ be,
            float* __restrict__ out, __half* __restrict__ out_h)
{
    const int row = blockIdx.x;
    const int tid = threadIdx.x;

    const float4 a4 = ((const float4*)(A  + (size_t)row * DMODEL))[tid];
    const float4 b4 = ((const float4*)(Bv + (size_t)row * DMODEL))[tid];
    float4 v;
    v.x = a4.x + b4.x; v.y = a4.y + b4.y; v.z = a4.z + b4.z; v.w = a4.w + b4.w;

    float s  = v.x + v.y + v.z + v.w;
    float ss = v.x*v.x + v.y*v.y + v.z*v.z + v.w*v.w;

    #pragma unroll
    for (int ofs = 16; ofs > 0; ofs >>= 1) {
        s  += __shfl_xor_sync(0xFFFFFFFFu, s,  ofs);
        ss += __shfl_xor_sync(0xFFFFFFFFu, ss, ofs);
    }

    __shared__ float shs[8], shss[8];
    const int w = tid >> 5;
    if ((tid & 31) == 0) { shs[w] = s; shss[w] = ss; }
    __syncthreads();
    if (tid < 32) {
        float s2  = (tid < 8) ? shs[tid]  : 0.f;
        float ss2 = (tid < 8) ? shss[tid] : 0.f;
        #pragma unroll
        for (int ofs = 4; ofs > 0; ofs >>= 1) {
            s2  += __shfl_xor_sync(0xFFFFFFFFu, s2,  ofs);
            ss2 += __shfl_xor_sync(0xFFFFFFFFu, ss2, ofs);
        }
        if (tid == 0) { shs[0] = s2; shss[0] = ss2; }
    }
    __syncthreads();

    const float mu  = shs[0]  * (1.f / DMODEL);
    const float var = shss[0] * (1.f / DMODEL) - mu * mu;
    const float inv = rsqrtf(var + 1e-5f);

    const float4 gv = ((const float4*)g)[tid];
    const float4 bb = ((const float4*)be)[tid];
    float4 o;
    o.x = (v.x - mu) * inv * gv.x + bb.x;
    o.y = (v.y - mu) * inv * gv.y + bb.y;
    o.z = (v.z - mu) * inv * gv.z + bb.z;
    o.w = (v.w - mu) * inv * gv.w + bb.w;
    ((float4*)(out + (size_t)row * DMODEL))[tid] = o;
    if (out_h) {
        __half2* oh = (__half2*)(out_h + (size_t)row * DMODEL) + tid * 2;
        oh[0] = __floats2half2_rn(o.x, o.y);
        oh[1] = __floats2half2_rn(o.z, o.w);
    }
}

// ---------------------------------------------------------------------------
// Launch
// ---------------------------------------------------------------------------
extern "C" void kernel_launch(void* const* d_in, const int* in_sizes, int n_in,
                              void* d_out, int out_size)
{
    const float* src  = (const float*)d_in[0];
    const float* Wq   = (const float*)d_in[1];
    const float* bq   = (const float*)d_in[2];
    const float* Wk   = (const float*)d_in[3];
    const float* bk   = (const float*)d_in[4];
    const float* Wv   = (const float*)d_in[5];
    const float* bv   = (const float*)d_in[6];
    const float* Wo   = (const float*)d_in[7];
    const float* bo   = (const float*)d_in[8];
    const float* W1   = (const float*)d_in[9];
    const float* b1   = (const float*)d_in[10];
    const float* W2   = (const float*)d_in[11];
    const float* b2   = (const float*)d_in[12];
    const float* ln1g = (const float*)d_in[13];
    const float* ln1b = (const float*)d_in[14];
    const float* ln2g = (const float*)d_in[15];
    const float* ln2b = (const float*)d_in[16];
    float* out = (float*)d_out;

    float  *pbqkv, *ptmp, *px;
    __half *pqkvh, *psrcr, *pxr, *pwqkvT, *pwoT, *pw1T, *pw2T, *pctx, *pff;
    cudaGetSymbolAddress((void**)&pqkvh,  g_qkvh);
    cudaGetSymbolAddress((void**)&psrcr,  g_srcr);
    cudaGetSymbolAddress((void**)&pxr,    g_xr);
    cudaGetSymbolAddress((void**)&pwqkvT, g_wqkvT);
    cudaGetSymbolAddress((void**)&pwoT,   g_woT);
    cudaGetSymbolAddress((void**)&pw1T,   g_w1T);
    cudaGetSymbolAddress((void**)&pw2T,   g_w2T);
    cudaGetSymbolAddress((void**)&pbqkv,  g_bqkv);
    cudaGetSymbolAddress((void**)&pctx,   g_ctx);
    cudaGetSymbolAddress((void**)&ptmp,   g_tmp);
    cudaGetSymbolAddress((void**)&px,     g_x);
    cudaGetSymbolAddress((void**)&pff,    g_ff);

    cudaFuncSetAttribute((const void*)gemm_mma<false,0>, cudaFuncAttributeMaxDynamicSharedMemorySize, SMEM_DYN);
    cudaFuncSetAttribute((const void*)gemm_mma<false,2>, cudaFuncAttributeMaxDynamicSharedMemorySize, SMEM_DYN);
    cudaFuncSetAttribute((const void*)gemm_mma<true,2>,  cudaFuncAttributeMaxDynamicSharedMemorySize, SMEM_DYN);
    cudaFuncSetAttribute((const void*)flash_mma, cudaFuncAttributeMaxDynamicSharedMemorySize, ATT_SMEM);

    // All preprocessing in one launch
    prep_all<<<3072 + 4096 + 12, 256>>>(src, Wq, Wk, Wv, Wo, W1, W2, bq, bk, bv,
                                        psrcr, pwqkvT, pwoT, pw1T, pw2T, pbqkv);

    // Fused QKV projection (half in, half out: feeds fp16 flash)
    gemm_mma<false, 2><<<dim3(3 * DMODEL / 128, NTOK / 256), 512, SMEM_DYN>>>(
        psrcr, pwqkvT, pbqkv, pqkvh, NTOK, 3 * DMODEL, DMODEL);

    // fp16 flash attention (128 queries/block; V via trans ldmatrix; half ctx out)
    flash_mma<<<dim3(SEQ / 128, 2 * NHEAD), 256, ATT_SMEM>>>(pqkvh, pctx);

    // Output projection (half A, fp32 out) + LN1 (writes half copy for FFN1)
    gemm_mma<false, 0><<<dim3(DMODEL / 128, NTOK / 256), 512, SMEM_DYN>>>(
        pctx, pwoT, bo, ptmp, NTOK, DMODEL, DMODEL);
    add_ln<<<NTOK, 256>>>(src, ptmp, ln1g, ln1b, px, pxr);

    // FFN
    gemm_mma<true, 2><<<dim3(DFF / 128, NTOK / 256), 512, SMEM_DYN>>>(
        pxr, pw1T, b1, pff, NTOK, DFF, DMODEL);
    gemm_mma<false, 0><<<dim3(DMODEL / 128, NTOK / 256), 512, SMEM_DYN>>>(
        pff, pw2T, b2, ptmp, NTOK, DMODEL, DFF);
    add_ln<<<NTOK, 256>>>(px, ptmp, ln2g, ln2b, out, (__half*)nullptr);
}